// round 1
// baseline (speedup 1.0000x reference)
#include <cuda_runtime.h>
#include <math.h>

#define TN 9216      // H*W = 96*96
#define NB 2         // batch

// ---------------- scratch (static device allocations; no cudaMalloc allowed) ---
__device__ float g_wkf[512 * 512];
__device__ float g_bkf[512];
__device__ float g_wof[512 * 512];
__device__ float g_bof[512];
__device__ float g_k[NB * 512 * TN];
__device__ float g_val[NB * 256 * TN];
__device__ float g_ctx[NB * 256 * TN];
__device__ float g_ctx2[NB * 512 * TN];
__device__ float g_rowsum[NB * TN];
__device__ float g_att[(size_t)NB * TN * TN];   // 679 MB, unnormalized exp after softmax pass

// ---------------- fold BN into conv weights --------------------------------
// bn(conv(x,w,b)) = (s*w) x + (s*b + beta - mean*s), s = gamma/sqrt(var+eps)
__global__ void fold_bn(const float* __restrict__ w, const float* __restrict__ cb,
                        const float* __restrict__ g, const float* __restrict__ bb,
                        const float* __restrict__ m, const float* __restrict__ v,
                        float* __restrict__ wf, float* __restrict__ bf, int Cin)
{
    int o = blockIdx.x;
    float s = g[o] * rsqrtf(v[o] + 1e-5f);
    for (int c = threadIdx.x; c < Cin; c += blockDim.x)
        wf[o * Cin + c] = w[o * Cin + c] * s;
    if (threadIdx.x == 0)
        bf[o] = cb[o] * s + bb[o] - m[o] * s;
}

// ---------------- shared 8x8 microtile FMA core ----------------------------
// Fragment layout: rows ty*4 + {0..3} and ty*4+64 + {0..3}; cols likewise with tx.
// 16B-aligned LDS.128, conflict-free across a warp.
__device__ __forceinline__ void mma_tile(const float (*As)[128], const float (*Bs)[128],
                                         float acc[8][8], int ty, int tx)
{
#pragma unroll
    for (int kk = 0; kk < 8; kk++) {
        float a[8], b[8];
        *(float4*)&a[0] = *(const float4*)&As[kk][ty * 4];
        *(float4*)&a[4] = *(const float4*)&As[kk][ty * 4 + 64];
        *(float4*)&b[0] = *(const float4*)&Bs[kk][tx * 4];
        *(float4*)&b[4] = *(const float4*)&Bs[kk][tx * 4 + 64];
#pragma unroll
        for (int i = 0; i < 8; i++)
#pragma unroll
            for (int j = 0; j < 8; j++)
                acc[i][j] += a[i] * b[j];
    }
}

// ---------------- C = A[M,K] * B[K,TN] + bias (opt relu), batched over z ----
__global__ __launch_bounds__(256) void gemm_wx(
    const float* __restrict__ A, const float* __restrict__ bias,
    const float* __restrict__ Bm, float* __restrict__ C,
    int M, int K, int do_relu)
{
    const float* Bb = Bm + (size_t)blockIdx.z * K * TN;
    float* Cb = C + (size_t)blockIdx.z * M * TN;
    const int n0 = blockIdx.x * 128, m0 = blockIdx.y * 128;
    const int tid = threadIdx.x;
    const int ty = tid >> 4, tx = tid & 15;
    const int am = tid >> 1, ak = (tid & 1) * 4;     // A: 128 rows x 8 k (transpose-store)
    const int bk = tid >> 5, bn = (tid & 31) * 4;    // B: 8 k x 128 n (direct)
    __shared__ float As[8][128], Bs[8][128];
    float acc[8][8] = {};

    float4 av = *(const float4*)&A[(size_t)(m0 + am) * K + ak];
    float4 bv = *(const float4*)&Bb[(size_t)bk * TN + n0 + bn];
    for (int k0 = 0; k0 < K; k0 += 8) {
        __syncthreads();
        As[ak + 0][am] = av.x; As[ak + 1][am] = av.y;
        As[ak + 2][am] = av.z; As[ak + 3][am] = av.w;
        *(float4*)&Bs[bk][bn] = bv;
        if (k0 + 8 < K) {
            av = *(const float4*)&A[(size_t)(m0 + am) * K + (k0 + 8) + ak];
            bv = *(const float4*)&Bb[(size_t)(k0 + 8 + bk) * TN + n0 + bn];
        }
        __syncthreads();
        mma_tile(As, Bs, acc, ty, tx);
    }
#pragma unroll
    for (int i = 0; i < 8; i++) {
        int m = m0 + ty * 4 + (i & 3) + ((i >> 2) * 64);
        float bsv = bias[m];
        float4 o0, o1;
        o0.x = acc[i][0] + bsv; o0.y = acc[i][1] + bsv;
        o0.z = acc[i][2] + bsv; o0.w = acc[i][3] + bsv;
        o1.x = acc[i][4] + bsv; o1.y = acc[i][5] + bsv;
        o1.z = acc[i][6] + bsv; o1.w = acc[i][7] + bsv;
        if (do_relu) {
            o0.x = fmaxf(o0.x, 0.f); o0.y = fmaxf(o0.y, 0.f);
            o0.z = fmaxf(o0.z, 0.f); o0.w = fmaxf(o0.w, 0.f);
            o1.x = fmaxf(o1.x, 0.f); o1.y = fmaxf(o1.y, 0.f);
            o1.z = fmaxf(o1.z, 0.f); o1.w = fmaxf(o1.w, 0.f);
        }
        *(float4*)&Cb[(size_t)m * TN + n0 + tx * 4] = o0;
        *(float4*)&Cb[(size_t)m * TN + n0 + tx * 4 + 64] = o1;
    }
}

// ---------------- sim = scale * k^T k  (k is [512, TN] K-major) -------------
__global__ __launch_bounds__(256) void gemm_ata(const float* __restrict__ Kf,
                                                float* __restrict__ Att, float scale)
{
    const float* Kb = Kf + (size_t)blockIdx.z * 512 * TN;
    float* Ab = Att + (size_t)blockIdx.z * TN * TN;
    const int j0 = blockIdx.x * 128, i0 = blockIdx.y * 128;
    const int tid = threadIdx.x;
    const int ty = tid >> 4, tx = tid & 15;
    const int lk = tid >> 5, ln = (tid & 31) * 4;    // both operands loaded B-style
    __shared__ float As[8][128], Bs[8][128];
    float acc[8][8] = {};

    float4 av = *(const float4*)&Kb[(size_t)lk * TN + i0 + ln];
    float4 bv = *(const float4*)&Kb[(size_t)lk * TN + j0 + ln];
    for (int k0 = 0; k0 < 512; k0 += 8) {
        __syncthreads();
        *(float4*)&As[lk][ln] = av;
        *(float4*)&Bs[lk][ln] = bv;
        if (k0 + 8 < 512) {
            av = *(const float4*)&Kb[(size_t)(k0 + 8 + lk) * TN + i0 + ln];
            bv = *(const float4*)&Kb[(size_t)(k0 + 8 + lk) * TN + j0 + ln];
        }
        __syncthreads();
        mma_tile(As, Bs, acc, ty, tx);
    }
#pragma unroll
    for (int i = 0; i < 8; i++) {
        int r = i0 + ty * 4 + (i & 3) + ((i >> 2) * 64);
        float4 o0, o1;
        o0.x = acc[i][0] * scale; o0.y = acc[i][1] * scale;
        o0.z = acc[i][2] * scale; o0.w = acc[i][3] * scale;
        o1.x = acc[i][4] * scale; o1.y = acc[i][5] * scale;
        o1.z = acc[i][6] * scale; o1.w = acc[i][7] * scale;
        *(float4*)&Ab[(size_t)r * TN + j0 + tx * 4] = o0;
        *(float4*)&Ab[(size_t)r * TN + j0 + tx * 4 + 64] = o1;
    }
}

// ---------------- per-row: store exp(x - max), rowsum (normalize later) ----
__global__ __launch_bounds__(256) void softmax_rows(float* __restrict__ Att,
                                                    float* __restrict__ rowsum)
{
    float* row = Att + ((size_t)blockIdx.y * TN + blockIdx.x) * TN;
    const int tid = threadIdx.x;
    __shared__ float red[8];

    float mx = -1e30f;
    for (int i = tid * 4; i < TN; i += 1024) {
        float4 v = *(const float4*)&row[i];
        mx = fmaxf(mx, fmaxf(fmaxf(v.x, v.y), fmaxf(v.z, v.w)));
    }
#pragma unroll
    for (int o = 16; o; o >>= 1) mx = fmaxf(mx, __shfl_xor_sync(0xffffffffu, mx, o));
    if ((tid & 31) == 0) red[tid >> 5] = mx;
    __syncthreads();
    mx = fmaxf(fmaxf(fmaxf(red[0], red[1]), fmaxf(red[2], red[3])),
               fmaxf(fmaxf(red[4], red[5]), fmaxf(red[6], red[7])));

    float s = 0.f;
    for (int i = tid * 4; i < TN; i += 1024) {
        float4 v = *(const float4*)&row[i];
        v.x = __expf(v.x - mx); v.y = __expf(v.y - mx);
        v.z = __expf(v.z - mx); v.w = __expf(v.w - mx);
        s += v.x + v.y + v.z + v.w;
        *(float4*)&row[i] = v;
    }
#pragma unroll
    for (int o = 16; o; o >>= 1) s += __shfl_xor_sync(0xffffffffu, s, o);
    __syncthreads();                       // red reuse
    if ((tid & 31) == 0) red[tid >> 5] = s;
    __syncthreads();
    if (tid == 0)
        rowsum[(size_t)blockIdx.y * TN + blockIdx.x] =
            red[0] + red[1] + red[2] + red[3] + red[4] + red[5] + red[6] + red[7];
}

// ---------------- ctx[v,n] = (1/rowsum[n]) * sum_m val[v,m] * att[n,m] ------
__global__ __launch_bounds__(256) void gemm_ctx(
    const float* __restrict__ V, const float* __restrict__ Att,
    const float* __restrict__ rowsum, float* __restrict__ Ctx)
{
    const float* Vb = V + (size_t)blockIdx.z * 256 * TN;
    const float* Ab = Att + (size_t)blockIdx.z * TN * TN;
    const float* rs = rowsum + (size_t)blockIdx.z * TN;
    float* Cb = Ctx + (size_t)blockIdx.z * 256 * TN;
    const int n0 = blockIdx.x * 128, m0 = blockIdx.y * 128;
    const int tid = threadIdx.x;
    const int ty = tid >> 4, tx = tid & 15;
    const int ar = tid >> 1, ak = (tid & 1) * 4;     // both operands K-contiguous rows
    __shared__ float As[8][128], Bs[8][128];
    float acc[8][8] = {};

    float4 av = *(const float4*)&Vb[(size_t)(m0 + ar) * TN + ak];
    float4 bv = *(const float4*)&Ab[(size_t)(n0 + ar) * TN + ak];
    for (int k0 = 0; k0 < TN; k0 += 8) {
        __syncthreads();
        As[ak + 0][ar] = av.x; As[ak + 1][ar] = av.y;
        As[ak + 2][ar] = av.z; As[ak + 3][ar] = av.w;
        Bs[ak + 0][ar] = bv.x; Bs[ak + 1][ar] = bv.y;
        Bs[ak + 2][ar] = bv.z; Bs[ak + 3][ar] = bv.w;
        if (k0 + 8 < TN) {
            av = *(const float4*)&Vb[(size_t)(m0 + ar) * TN + (k0 + 8) + ak];
            bv = *(const float4*)&Ab[(size_t)(n0 + ar) * TN + (k0 + 8) + ak];
        }
        __syncthreads();
        mma_tile(As, Bs, acc, ty, tx);
    }
    float inv0[4], inv1[4];
#pragma unroll
    for (int j = 0; j < 4; j++) {
        inv0[j] = 1.0f / rs[n0 + tx * 4 + j];
        inv1[j] = 1.0f / rs[n0 + tx * 4 + 64 + j];
    }
#pragma unroll
    for (int i = 0; i < 8; i++) {
        int m = m0 + ty * 4 + (i & 3) + ((i >> 2) * 64);
        float4 o0, o1;
        o0.x = acc[i][0] * inv0[0]; o0.y = acc[i][1] * inv0[1];
        o0.z = acc[i][2] * inv0[2]; o0.w = acc[i][3] * inv0[3];
        o1.x = acc[i][4] * inv1[0]; o1.y = acc[i][5] * inv1[1];
        o1.z = acc[i][6] * inv1[2]; o1.w = acc[i][7] * inv1[3];
        *(float4*)&Cb[(size_t)m * TN + n0 + tx * 4] = o0;
        *(float4*)&Cb[(size_t)m * TN + n0 + tx * 4 + 64] = o1;
    }
}

// ---------------- launch --------------------------------------------------
extern "C" void kernel_launch(void* const* d_in, const int* in_sizes, int n_in,
                              void* d_out, int out_size)
{
    const float* x  = (const float*)d_in[0];
    const float* wk = (const float*)d_in[1];
    const float* bk = (const float*)d_in[2];
    const float* g1 = (const float*)d_in[3];
    const float* b1 = (const float*)d_in[4];
    const float* m1 = (const float*)d_in[5];
    const float* v1 = (const float*)d_in[6];
    const float* wv = (const float*)d_in[7];
    const float* bv = (const float*)d_in[8];
    const float* wW = (const float*)d_in[9];
    const float* bW = (const float*)d_in[10];
    const float* wo = (const float*)d_in[11];
    const float* bo = (const float*)d_in[12];
    const float* g2 = (const float*)d_in[13];
    const float* b2 = (const float*)d_in[14];
    const float* m2 = (const float*)d_in[15];
    const float* v2 = (const float*)d_in[16];
    float* out = (float*)d_out;

    float *p_wkf, *p_bkf, *p_wof, *p_bof, *p_k, *p_val, *p_ctx, *p_ctx2, *p_rs, *p_att;
    cudaGetSymbolAddress((void**)&p_wkf, g_wkf);
    cudaGetSymbolAddress((void**)&p_bkf, g_bkf);
    cudaGetSymbolAddress((void**)&p_wof, g_wof);
    cudaGetSymbolAddress((void**)&p_bof, g_bof);
    cudaGetSymbolAddress((void**)&p_k,   g_k);
    cudaGetSymbolAddress((void**)&p_val, g_val);
    cudaGetSymbolAddress((void**)&p_ctx, g_ctx);
    cudaGetSymbolAddress((void**)&p_ctx2, g_ctx2);
    cudaGetSymbolAddress((void**)&p_rs,  g_rowsum);
    cudaGetSymbolAddress((void**)&p_att, g_att);

    // fold BN1 into wk and BN2 into wo
    fold_bn<<<512, 256>>>(wk, bk, g1, b1, m1, v1, p_wkf, p_bkf, 512);
    fold_bn<<<512, 256>>>(wo, bo, g2, b2, m2, v2, p_wof, p_bof, 512);

    // k = relu(bn(Wk x)), val = Wv x
    gemm_wx<<<dim3(72, 4, NB), 256>>>(p_wkf, p_bkf, x, p_k, 512, 512, 1);
    gemm_wx<<<dim3(72, 2, NB), 256>>>(wv, bv, x, p_val, 256, 512, 0);

    // sim = k^T k / sqrt(512); unnormalized softmax; ctx = val att^T / rowsum
    gemm_ata<<<dim3(72, 72, NB), 256>>>(p_k, p_att, 0.0441941738241592f);
    softmax_rows<<<dim3(TN, NB), 256>>>(p_att, p_rs);
    gemm_ctx<<<dim3(72, 2, NB), 256>>>(p_val, p_att, p_rs, p_ctx);

    // ctx2 = wW ctx + bW ;  out = relu(bn(wo ctx2 + bo))
    gemm_wx<<<dim3(72, 4, NB), 256>>>(wW, bW, p_ctx, p_ctx2, 512, 256, 0);
    gemm_wx<<<dim3(72, 4, NB), 256>>>(p_wof, p_bof, p_ctx2, out, 512, 512, 1);
}

// round 3
// speedup vs baseline: 2.2799x; 2.2799x over previous
#include <cuda_runtime.h>
#include <cuda_fp16.h>
#include <math.h>
#include <stdint.h>

#define TN 9216
#define NB 2
typedef unsigned int u32;
typedef unsigned long long u64;

#define F_RELU   1
#define F_BROW   2
#define F_BCOL   4
#define F_ROWDIV 8
#define F_F32    16

// ---------------- scratch (static device arrays; no cudaMalloc allowed) ----
__device__ __half g_xh[(size_t)NB*TN*512],  g_xl[(size_t)NB*TN*512];
__device__ __half g_kh[(size_t)NB*TN*512],  g_kl[(size_t)NB*TN*512];
__device__ __half g_vh[(size_t)NB*256*TN],  g_vl[(size_t)NB*256*TN];
__device__ __half g_ahh[(size_t)NB*TN*TN],  g_all[(size_t)NB*TN*TN];
__device__ __half g_ch[(size_t)NB*TN*256],  g_cl[(size_t)NB*TN*256];
__device__ __half g_c2h[(size_t)NB*TN*512], g_c2l[(size_t)NB*TN*512];
__device__ __half g_wkh[512*512], g_wkl[512*512];
__device__ __half g_wvh[256*512], g_wvl[256*512];
__device__ __half g_wWh[512*256], g_wWl[512*256];
__device__ __half g_woh[512*512], g_wol[512*512];
__device__ float g_bkf[512], g_bof[512];
__device__ float g_rs[NB*TN];

// ---------------- helpers ----------------------------------------------------
static __device__ __forceinline__ u32 smem_u32(const void* p){
    u32 a;
    asm("{ .reg .u64 t; cvta.to.shared.u64 t, %1; cvt.u32.u64 %0, t; }" : "=r"(a) : "l"(p));
    return a;
}
static __device__ __forceinline__ void cpasync16(u32 s, const void* g){
    asm volatile("cp.async.cg.shared.global [%0], [%1], 16;" :: "r"(s), "l"(g) : "memory");
}
#define CP_COMMIT() asm volatile("cp.async.commit_group;" ::: "memory")
#define CP_WAIT0()  asm volatile("cp.async.wait_group 0;" ::: "memory")

static __device__ __forceinline__ void ldsm4(u32& r0, u32& r1, u32& r2, u32& r3, u32 a){
    asm volatile("ldmatrix.sync.aligned.m8n8.x4.shared.b16 {%0,%1,%2,%3}, [%4];"
                 : "=r"(r0), "=r"(r1), "=r"(r2), "=r"(r3) : "r"(a));
}
static __device__ __forceinline__ void mma16816(float* d, const u32* a, const u32* b){
    asm volatile("mma.sync.aligned.m16n8k16.row.col.f32.f16.f16.f32 "
                 "{%0,%1,%2,%3}, {%4,%5,%6,%7}, {%8,%9}, {%0,%1,%2,%3};"
                 : "+f"(d[0]), "+f"(d[1]), "+f"(d[2]), "+f"(d[3])
                 : "r"(a[0]), "r"(a[1]), "r"(a[2]), "r"(a[3]), "r"(b[0]), "r"(b[1]));
}
static __device__ __forceinline__ void split2(float v, __half& h, __half& l){
    h = __float2half_rn(v);
    l = __float2half_rn(v - __half2float(h));
}

// ---------------- generic split-fp16 tensor GEMM -----------------------------
// D[m0..+128][n0..+128] = scale*(sum_k (Ah+Al)[m][k]*(Bh+Bl)[n][k]) + bias, epilogue flags.
// A,B row-major with K contiguous. K-slab 64, SW128 swizzle, cp.async double buffer.
__global__ void __launch_bounds__(256,1) gemm_tc(
    const __half* __restrict__ ah, const __half* __restrict__ al, size_t a_bs, int lda,
    const __half* __restrict__ bh, const __half* __restrict__ bl, size_t b_bs, int ldb,
    int K, int flags, const float* __restrict__ bias, const float* __restrict__ rowsum,
    float scale, __half* oh, __half* ol, float* of, size_t o_bs, int ldo)
{
    extern __shared__ char dsm[];
    const int tid = threadIdx.x, wid = tid>>5, lid = tid&31;
    const int m0 = blockIdx.x*128, n0 = blockIdx.y*128, z = blockIdx.z;
    ah += (size_t)z*a_bs; al += (size_t)z*a_bs;
    bh += (size_t)z*b_bs; bl += (size_t)z*b_bs;
    const int wm = wid>>2, wn = wid&3;            // warp grid 2(m) x 4(n)
    const u32 sb = smem_u32(dsm);

    const int lrow = tid>>3, lc = tid&7;          // gmem->smem load coords
    const __half* gpA[2] = {ah, al};
    const __half* gpB[2] = {bh, bl};

    float acc[4][4][4];
#pragma unroll
    for (int i=0;i<4;i++)
#pragma unroll
        for (int j=0;j<4;j++)
#pragma unroll
            for (int q=0;q<4;q++) acc[i][j][q] = 0.f;

    const int S = K >> 6;

    auto issue = [&](int s){
        const int k0 = s << 6;
        const u32 bufo = (u32)(s & 1) << 16;      // 65536 per stage
#pragma unroll
        for (int arr=0; arr<4; arr++){
            const __half* gp = (arr<2) ? gpA[arr] : gpB[arr-2];
            const int rb = (arr<2) ? m0 : n0;
            const int ld = (arr<2) ? lda : ldb;
            const u32 so = sb + bufo + arr*16384u;
#pragma unroll
            for (int i=0;i<4;i++){
                const int row = lrow + i*32;
                const void* g = gp + (size_t)(rb+row)*ld + k0 + lc*8;
                const u32 sa = so + (u32)(row*128) + (u32)((lc ^ (row&7)) << 4);
                cpasync16(sa, g);
            }
        }
        CP_COMMIT();
    };

    issue(0);
    for (int s=0; s<S; s++){
        CP_WAIT0();
        __syncthreads();
        if (s+1 < S) issue(s+1);
        const u32 bufo = (u32)(s & 1) << 16;
        const u32 bAh = sb+bufo, bAl = sb+bufo+16384u, bBh = sb+bufo+32768u, bBl = sb+bufo+49152u;
        const int prA = (wm*64 + (lid&15)) * 128;
        const int prB0 = (wn*32 +      (lid&7) + ((lid>>4)<<3)) * 128;
        const int prB1 = (wn*32 + 16 + (lid&7) + ((lid>>4)<<3)) * 128;
#pragma unroll
        for (int st=0; st<4; st++){
            u32 Ah[4][4], Al[4][4], Bh[4][2], Bl[4][2];
            const int xa = ((st*2 + (lid>>4))    ^ (lid&7)) << 4;
            const int xb = ((st*2 + ((lid>>3)&1)) ^ (lid&7)) << 4;
#pragma unroll
            for (int i=0;i<4;i++){
                ldsm4(Ah[i][0],Ah[i][1],Ah[i][2],Ah[i][3], bAh + prA + i*2048 + xa);
                ldsm4(Al[i][0],Al[i][1],Al[i][2],Al[i][3], bAl + prA + i*2048 + xa);
            }
            {
                u32 r0,r1,r2,r3;
                ldsm4(r0,r1,r2,r3, bBh + prB0 + xb);
                Bh[0][0]=r0; Bh[0][1]=r1; Bh[1][0]=r2; Bh[1][1]=r3;
                ldsm4(r0,r1,r2,r3, bBh + prB1 + xb);
                Bh[2][0]=r0; Bh[2][1]=r1; Bh[3][0]=r2; Bh[3][1]=r3;
                ldsm4(r0,r1,r2,r3, bBl + prB0 + xb);
                Bl[0][0]=r0; Bl[0][1]=r1; Bl[1][0]=r2; Bl[1][1]=r3;
                ldsm4(r0,r1,r2,r3, bBl + prB1 + xb);
                Bl[2][0]=r0; Bl[2][1]=r1; Bl[3][0]=r2; Bl[3][1]=r3;
            }
#pragma unroll
            for (int i=0;i<4;i++)
#pragma unroll
                for (int j=0;j<4;j++) mma16816(acc[i][j], Ah[i], Bh[j]);
#pragma unroll
            for (int i=0;i<4;i++)
#pragma unroll
                for (int j=0;j<4;j++) mma16816(acc[i][j], Ah[i], Bl[j]);
#pragma unroll
            for (int i=0;i<4;i++)
#pragma unroll
                for (int j=0;j<4;j++) mma16816(acc[i][j], Al[i], Bh[j]);
        }
    }

    // ---------------- epilogue ----------------
    const int tr = lid>>2, tc = (lid&3)*2;
    const int mBase = m0 + wm*64, nBase = n0 + wn*32;
#pragma unroll
    for (int i=0;i<4;i++){
#pragma unroll
        for (int hh=0; hh<2; hh++){
            const int row = mBase + i*16 + tr + hh*8;
            float brow = (flags & F_BROW) ? bias[row] : 0.f;
            float mult = scale;
            if (flags & F_ROWDIV) mult *= 1.0f / rowsum[(size_t)z*TN + row];
            if (flags & F_F32){
                float* op = of + (size_t)z*o_bs + (size_t)row*ldo;
#pragma unroll
                for (int j=0;j<4;j++){
                    const int n = nBase + j*8 + tc;
                    float v0 = acc[i][j][hh*2+0]*mult + brow;
                    float v1 = acc[i][j][hh*2+1]*mult + brow;
                    if (flags & F_BCOL){ v0 += bias[n]; v1 += bias[n+1]; }
                    if (flags & F_RELU){ v0 = fmaxf(v0,0.f); v1 = fmaxf(v1,0.f); }
                    float2 w; w.x = v0; w.y = v1;
                    *(float2*)(op + n) = w;
                }
            } else {
                __half* oph = oh + (size_t)z*o_bs + (size_t)row*ldo;
                __half* opl = ol + (size_t)z*o_bs + (size_t)row*ldo;
#pragma unroll
                for (int j=0;j<4;j++){
                    const int n = nBase + j*8 + tc;
                    float v0 = acc[i][j][hh*2+0]*mult + brow;
                    float v1 = acc[i][j][hh*2+1]*mult + brow;
                    if (flags & F_BCOL){ v0 += bias[n]; v1 += bias[n+1]; }
                    if (flags & F_RELU){ v0 = fmaxf(v0,0.f); v1 = fmaxf(v1,0.f); }
                    __half2 h2, l2;
                    split2(v0, h2.x, l2.x); split2(v1, h2.y, l2.y);
                    *(__half2*)(oph + n) = h2;
                    *(__half2*)(opl + n) = l2;
                }
            }
        }
    }
}

// ---------------- weight prep: optional BN fold + hi/lo split ---------------
__global__ void prep_w(const float* __restrict__ w, const float* __restrict__ cb,
                       const float* __restrict__ g, const float* __restrict__ bb,
                       const float* __restrict__ m, const float* __restrict__ v,
                       __half* __restrict__ wh, __half* __restrict__ wl,
                       float* __restrict__ bf_, int Kw, int has_bn)
{
    int o = blockIdx.x;
    float s = 1.f, off = 0.f;
    if (has_bn){ s = g[o] * rsqrtf(v[o] + 1e-5f); off = bb[o] - m[o]*s; }
    for (int c = threadIdx.x; c < Kw; c += blockDim.x){
        __half h, l; split2(w[o*Kw + c] * s, h, l);
        wh[o*Kw + c] = h; wl[o*Kw + c] = l;
    }
    if (threadIdx.x == 0 && bf_) bf_[o] = cb[o]*s + off;
}

// ---------------- x: [b][c][n] fp32 -> x_t: [b][n][c] fp16 hi/lo ------------
__global__ void conv_x(const float* __restrict__ x, __half* __restrict__ xh, __half* __restrict__ xl)
{
    __shared__ float t[32][33];
    const int z = blockIdx.z;
    const float* xb = x + (size_t)z*512*TN;
    const int n0 = blockIdx.x*32, c0 = blockIdx.y*32;
    const int tx = threadIdx.x, ty = threadIdx.y;
#pragma unroll
    for (int i=0;i<4;i++)
        t[ty + i*8][tx] = xb[(size_t)(c0 + ty + i*8)*TN + n0 + tx];
    __syncthreads();
#pragma unroll
    for (int i=0;i<4;i++){
        int n = n0 + ty + i*8, c = c0 + tx;
        __half h, l; split2(t[tx][ty + i*8], h, l);
        size_t o = ((size_t)z*TN + n)*512 + c;
        xh[o] = h; xl[o] = l;
    }
}

// ---------------- softmax over rows of sim (fp16 hi/lo, in place) -----------
__global__ void __launch_bounds__(256) softmax_rows(__half* __restrict__ ah, __half* __restrict__ al,
                                                    float* __restrict__ rowsum)
{
    const size_t ro = ((size_t)blockIdx.y*TN + blockIdx.x)*TN;
    uint2* ph = (uint2*)(ah + ro);
    uint2* pl = (uint2*)(al + ro);
    const int tid = threadIdx.x;
    __shared__ float red[8];

    float mx = -1e30f;
    for (int i = tid; i < TN/4; i += 256){
        uint2 uh = ph[i], ul = pl[i];
        __half2 h0 = *(__half2*)&uh.x, h1 = *(__half2*)&uh.y;
        __half2 l0 = *(__half2*)&ul.x, l1 = *(__half2*)&ul.y;
        float a = __half2float(h0.x)+__half2float(l0.x);
        float b = __half2float(h0.y)+__half2float(l0.y);
        float c = __half2float(h1.x)+__half2float(l1.x);
        float d = __half2float(h1.y)+__half2float(l1.y);
        mx = fmaxf(mx, fmaxf(fmaxf(a,b), fmaxf(c,d)));
    }
#pragma unroll
    for (int o=16;o;o>>=1) mx = fmaxf(mx, __shfl_xor_sync(0xffffffffu, mx, o));
    if ((tid&31)==0) red[tid>>5] = mx;
    __syncthreads();
    mx = fmaxf(fmaxf(fmaxf(red[0],red[1]),fmaxf(red[2],red[3])),
               fmaxf(fmaxf(red[4],red[5]),fmaxf(red[6],red[7])));
    __syncthreads();

    float s = 0.f;
    for (int i = tid; i < TN/4; i += 256){
        uint2 uh = ph[i], ul = pl[i];
        __half2 h0 = *(__half2*)&uh.x, h1 = *(__half2*)&uh.y;
        __half2 l0 = *(__half2*)&ul.x, l1 = *(__half2*)&ul.y;
        float e0 = __expf(__half2float(h0.x)+__half2float(l0.x) - mx);
        float e1 = __expf(__half2float(h0.y)+__half2float(l0.y) - mx);
        float e2 = __expf(__half2float(h1.x)+__half2float(l1.x) - mx);
        float e3 = __expf(__half2float(h1.y)+__half2float(l1.y) - mx);
        s += e0+e1+e2+e3;
        __half2 oh0, ol0, oh1, ol1;
        split2(e0, oh0.x, ol0.x); split2(e1, oh0.y, ol0.y);
        split2(e2, oh1.x, ol1.x); split2(e3, oh1.y, ol1.y);
        uint2 wh, wl;
        wh.x = *(u32*)&oh0; wh.y = *(u32*)&oh1;
        wl.x = *(u32*)&ol0; wl.y = *(u32*)&ol1;
        ph[i] = wh; pl[i] = wl;
    }
#pragma unroll
    for (int o=16;o;o>>=1) s += __shfl_xor_sync(0xffffffffu, s, o);
    if ((tid&31)==0) red[tid>>5] = s;
    __syncthreads();
    if (tid==0)
        rowsum[(size_t)blockIdx.y*TN + blockIdx.x] =
            red[0]+red[1]+red[2]+red[3]+red[4]+red[5]+red[6]+red[7];
}

// ---------------- launch ----------------------------------------------------
#define DSMEM 131072

extern "C" void kernel_launch(void* const* d_in, const int* in_sizes, int n_in,
                              void* d_out, int out_size)
{
    const float* x  = (const float*)d_in[0];
    const float* wk = (const float*)d_in[1];
    const float* bk = (const float*)d_in[2];
    const float* g1 = (const float*)d_in[3];
    const float* b1 = (const float*)d_in[4];
    const float* m1 = (const float*)d_in[5];
    const float* v1 = (const float*)d_in[6];
    const float* wv = (const float*)d_in[7];
    const float* bv = (const float*)d_in[8];
    const float* wW = (const float*)d_in[9];
    const float* bW = (const float*)d_in[10];
    const float* wo = (const float*)d_in[11];
    const float* bo = (const float*)d_in[12];
    const float* g2 = (const float*)d_in[13];
    const float* b2 = (const float*)d_in[14];
    const float* m2 = (const float*)d_in[15];
    const float* v2 = (const float*)d_in[16];
    float* out = (float*)d_out;

    cudaFuncSetAttribute(gemm_tc, cudaFuncAttributeMaxDynamicSharedMemorySize, DSMEM);

    __half *xh,*xl,*kh,*kl,*vh,*vl,*aH,*aL,*ch,*cl,*c2h,*c2l;
    __half *wkh,*wkl,*wvh,*wvl,*wWh,*wWl,*woh,*wol;
    float *bkf,*bof,*rs;
    cudaGetSymbolAddress((void**)&xh, g_xh);   cudaGetSymbolAddress((void**)&xl, g_xl);
    cudaGetSymbolAddress((void**)&kh, g_kh);   cudaGetSymbolAddress((void**)&kl, g_kl);
    cudaGetSymbolAddress((void**)&vh, g_vh);   cudaGetSymbolAddress((void**)&vl, g_vl);
    cudaGetSymbolAddress((void**)&aH, g_ahh);  cudaGetSymbolAddress((void**)&aL, g_all);
    cudaGetSymbolAddress((void**)&ch, g_ch);   cudaGetSymbolAddress((void**)&cl, g_cl);
    cudaGetSymbolAddress((void**)&c2h, g_c2h); cudaGetSymbolAddress((void**)&c2l, g_c2l);
    cudaGetSymbolAddress((void**)&wkh, g_wkh); cudaGetSymbolAddress((void**)&wkl, g_wkl);
    cudaGetSymbolAddress((void**)&wvh, g_wvh); cudaGetSymbolAddress((void**)&wvl, g_wvl);
    cudaGetSymbolAddress((void**)&wWh, g_wWh); cudaGetSymbolAddress((void**)&wWl, g_wWl);
    cudaGetSymbolAddress((void**)&woh, g_woh); cudaGetSymbolAddress((void**)&wol, g_wol);
    cudaGetSymbolAddress((void**)&bkf, g_bkf); cudaGetSymbolAddress((void**)&bof, g_bof);
    cudaGetSymbolAddress((void**)&rs,  g_rs);

    // weight prep (BN folded into wk, wo)
    prep_w<<<512, 256>>>(wk, bk, g1, b1, m1, v1, wkh, wkl, bkf, 512, 1);
    prep_w<<<256, 256>>>(wv, nullptr, nullptr, nullptr, nullptr, nullptr, wvh, wvl, nullptr, 512, 0);
    prep_w<<<512, 256>>>(wW, nullptr, nullptr, nullptr, nullptr, nullptr, wWh, wWl, nullptr, 256, 0);
    prep_w<<<512, 256>>>(wo, bo, g2, b2, m2, v2, woh, wol, bof, 512, 1);
    conv_x<<<dim3(TN/32, 16, NB), dim3(32,8)>>>(x, xh, xl);

    // k_t[n][cout] = relu(Wk_f x + bk_f):  A=x_t (M=n), B=wk (N=cout)
    gemm_tc<<<dim3(72,4,NB), 256, DSMEM>>>(xh, xl, (size_t)TN*512, 512,
        wkh, wkl, 0, 512, 512, F_BCOL|F_RELU, bkf, nullptr, 1.f,
        kh, kl, nullptr, (size_t)TN*512, 512);
    // val[v][n] = Wv x + bv:  A=wv (M=v), B=x_t (N=n)
    gemm_tc<<<dim3(2,72,NB), 256, DSMEM>>>(wvh, wvl, 0, 512,
        xh, xl, (size_t)TN*512, 512, 512, F_BROW, bv, nullptr, 1.f,
        vh, vl, nullptr, (size_t)256*TN, TN);
    // sim[i][j] = scale * k_t[i]·k_t[j]
    gemm_tc<<<dim3(72,72,NB), 256, DSMEM>>>(kh, kl, (size_t)TN*512, 512,
        kh, kl, (size_t)TN*512, 512, 512, 0, nullptr, nullptr, 0.0441941738241592f,
        aH, aL, nullptr, (size_t)TN*TN, TN);
    // softmax (unnormalized exp + rowsum), in place
    softmax_rows<<<dim3(TN, NB), 256>>>(aH, aL, rs);
    // ctx[n][v] = (att[n]·val[v]) / rowsum[n]:  A=att (M=n), B=val (N=v)
    gemm_tc<<<dim3(72,2,NB), 256, DSMEM>>>(aH, aL, (size_t)TN*TN, TN,
        vh, vl, (size_t)256*TN, TN, TN, F_ROWDIV, nullptr, rs, 1.f,
        ch, cl, nullptr, (size_t)TN*256, 256);
    // ctx2[n][co] = wW ctx + bW:  A=ctx_t (M=n), B=wW (N=co)
    gemm_tc<<<dim3(72,4,NB), 256, DSMEM>>>(ch, cl, (size_t)TN*256, 256,
        wWh, wWl, 0, 256, 256, F_BCOL, bW, nullptr, 1.f,
        c2h, c2l, nullptr, (size_t)TN*512, 512);
    // out[co][n] = relu(wo_f ctx2 + bo_f):  A=wo (M=co), B=ctx2_t (N=n), fp32 out
    gemm_tc<<<dim3(4,72,NB), 256, DSMEM>>>(woh, wol, 0, 512,
        c2h, c2l, (size_t)TN*512, 512, 512, F_BROW|F_RELU|F_F32, bof, nullptr, 1.f,
        nullptr, nullptr, out, (size_t)512*TN, TN);
}

// round 4
// speedup vs baseline: 2.7446x; 1.2038x over previous
#include <cuda_runtime.h>
#include <cuda_fp16.h>
#include <math.h>
#include <stdint.h>

#define TN 9216
#define NB 2
typedef unsigned int u32;
typedef unsigned long long u64;

#define F_RELU   1
#define F_BROW   2
#define F_BCOL   4
#define F_ROWDIV 8
#define F_F32    16

// ---------------- scratch (static device arrays; no cudaMalloc allowed) ----
__device__ __half g_xh[(size_t)NB*TN*512],  g_xl[(size_t)NB*TN*512];
__device__ __half g_kh[(size_t)NB*TN*512],  g_kl[(size_t)NB*TN*512];
__device__ __half g_vh[(size_t)NB*256*TN],  g_vl[(size_t)NB*256*TN];
__device__ __half g_ahh[(size_t)NB*TN*TN],  g_all[(size_t)NB*TN*TN];
__device__ __half g_ch[(size_t)NB*TN*256],  g_cl[(size_t)NB*TN*256];
__device__ __half g_c2h[(size_t)NB*TN*512], g_c2l[(size_t)NB*TN*512];
__device__ __half g_wkh[512*512], g_wkl[512*512];
__device__ __half g_wvh[256*512], g_wvl[256*512];
__device__ __half g_wWh[512*256], g_wWl[512*256];
__device__ __half g_woh[512*512], g_wol[512*512];
__device__ float g_bkf[512], g_bof[512];
__device__ float g_rs[NB*TN];
__device__ u32   g_rmax[NB*TN];

// ---------------- helpers ----------------------------------------------------
static __device__ __forceinline__ u32 smem_u32(const void* p){
    u32 a;
    asm("{ .reg .u64 t; cvta.to.shared.u64 t, %1; cvt.u32.u64 %0, t; }" : "=r"(a) : "l"(p));
    return a;
}
static __device__ __forceinline__ void cpasync16(u32 s, const void* g){
    asm volatile("cp.async.cg.shared.global [%0], [%1], 16;" :: "r"(s), "l"(g) : "memory");
}
#define CP_COMMIT() asm volatile("cp.async.commit_group;" ::: "memory")
#define CP_WAIT0()  asm volatile("cp.async.wait_group 0;" ::: "memory")

static __device__ __forceinline__ void ldsm4(u32& r0, u32& r1, u32& r2, u32& r3, u32 a){
    asm volatile("ldmatrix.sync.aligned.m8n8.x4.shared.b16 {%0,%1,%2,%3}, [%4];"
                 : "=r"(r0), "=r"(r1), "=r"(r2), "=r"(r3) : "r"(a));
}
static __device__ __forceinline__ void mma16816(float* d, const u32* a, const u32* b){
    asm volatile("mma.sync.aligned.m16n8k16.row.col.f32.f16.f16.f32 "
                 "{%0,%1,%2,%3}, {%4,%5,%6,%7}, {%8,%9}, {%0,%1,%2,%3};"
                 : "+f"(d[0]), "+f"(d[1]), "+f"(d[2]), "+f"(d[3])
                 : "r"(a[0]), "r"(a[1]), "r"(a[2]), "r"(a[3]), "r"(b[0]), "r"(b[1]));
}
static __device__ __forceinline__ void split2(float v, __half& h, __half& l){
    h = __float2half_rn(v);
    l = __float2half_rn(v - __half2float(h));
}
// order-preserving float<->u32 encoding for atomicMax
static __device__ __forceinline__ u32 fenc(float f){
    u32 u = __float_as_uint(f);
    return (u & 0x80000000u) ? ~u : (u | 0x80000000u);
}
static __device__ __forceinline__ float fdec(u32 u){
    return (u & 0x80000000u) ? __uint_as_float(u ^ 0x80000000u) : __uint_as_float(~u);
}

// ---------------- generic split-fp16 tensor GEMM -----------------------------
__global__ void __launch_bounds__(256,1) gemm_tc(
    const __half* __restrict__ ah, const __half* __restrict__ al, size_t a_bs, int lda,
    const __half* __restrict__ bh, const __half* __restrict__ bl, size_t b_bs, int ldb,
    int K, int flags, const float* __restrict__ bias, const float* __restrict__ rowsum,
    float scale, __half* oh, __half* ol, float* of, size_t o_bs, int ldo)
{
    extern __shared__ char dsm[];
    const int tid = threadIdx.x, wid = tid>>5, lid = tid&31;
    const int m0 = blockIdx.x*128, n0 = blockIdx.y*128, z = blockIdx.z;
    ah += (size_t)z*a_bs; al += (size_t)z*a_bs;
    bh += (size_t)z*b_bs; bl += (size_t)z*b_bs;
    const int wm = wid>>2, wn = wid&3;
    const u32 sb = smem_u32(dsm);
    const int lrow = tid>>3, lc = tid&7;
    const __half* gpA[2] = {ah, al};
    const __half* gpB[2] = {bh, bl};

    float acc[4][4][4];
#pragma unroll
    for (int i=0;i<4;i++)
#pragma unroll
        for (int j=0;j<4;j++)
#pragma unroll
            for (int q=0;q<4;q++) acc[i][j][q] = 0.f;

    const int S = K >> 6;
    auto issue = [&](int s){
        const int k0 = s << 6;
        const u32 bufo = (u32)(s & 1) << 16;
#pragma unroll
        for (int arr=0; arr<4; arr++){
            const __half* gp = (arr<2) ? gpA[arr] : gpB[arr-2];
            const int rb = (arr<2) ? m0 : n0;
            const int ld = (arr<2) ? lda : ldb;
            const u32 so = sb + bufo + arr*16384u;
#pragma unroll
            for (int i=0;i<4;i++){
                const int row = lrow + i*32;
                const void* g = gp + (size_t)(rb+row)*ld + k0 + lc*8;
                const u32 sa = so + (u32)(row*128) + (u32)((lc ^ (row&7)) << 4);
                cpasync16(sa, g);
            }
        }
        CP_COMMIT();
    };

    issue(0);
    for (int s=0; s<S; s++){
        CP_WAIT0();
        __syncthreads();
        if (s+1 < S) issue(s+1);
        const u32 bufo = (u32)(s & 1) << 16;
        const u32 bAh = sb+bufo, bAl = sb+bufo+16384u, bBh = sb+bufo+32768u, bBl = sb+bufo+49152u;
        const int prA = (wm*64 + (lid&15)) * 128;
        const int prB0 = (wn*32 +      (lid&7) + ((lid>>4)<<3)) * 128;
        const int prB1 = (wn*32 + 16 + (lid&7) + ((lid>>4)<<3)) * 128;
#pragma unroll
        for (int st=0; st<4; st++){
            u32 Ah[4][4], Al[4][4], Bh[4][2], Bl[4][2];
            const int xa = ((st*2 + (lid>>4))    ^ (lid&7)) << 4;
            const int xb = ((st*2 + ((lid>>3)&1)) ^ (lid&7)) << 4;
#pragma unroll
            for (int i=0;i<4;i++){
                ldsm4(Ah[i][0],Ah[i][1],Ah[i][2],Ah[i][3], bAh + prA + i*2048 + xa);
                ldsm4(Al[i][0],Al[i][1],Al[i][2],Al[i][3], bAl + prA + i*2048 + xa);
            }
            {
                u32 r0,r1,r2,r3;
                ldsm4(r0,r1,r2,r3, bBh + prB0 + xb);
                Bh[0][0]=r0; Bh[0][1]=r1; Bh[1][0]=r2; Bh[1][1]=r3;
                ldsm4(r0,r1,r2,r3, bBh + prB1 + xb);
                Bh[2][0]=r0; Bh[2][1]=r1; Bh[3][0]=r2; Bh[3][1]=r3;
                ldsm4(r0,r1,r2,r3, bBl + prB0 + xb);
                Bl[0][0]=r0; Bl[0][1]=r1; Bl[1][0]=r2; Bl[1][1]=r3;
                ldsm4(r0,r1,r2,r3, bBl + prB1 + xb);
                Bl[2][0]=r0; Bl[2][1]=r1; Bl[3][0]=r2; Bl[3][1]=r3;
            }
#pragma unroll
            for (int i=0;i<4;i++)
#pragma unroll
                for (int j=0;j<4;j++) mma16816(acc[i][j], Ah[i], Bh[j]);
#pragma unroll
            for (int i=0;i<4;i++)
#pragma unroll
                for (int j=0;j<4;j++) mma16816(acc[i][j], Ah[i], Bl[j]);
#pragma unroll
            for (int i=0;i<4;i++)
#pragma unroll
                for (int j=0;j<4;j++) mma16816(acc[i][j], Al[i], Bh[j]);
        }
    }

    const int tr = lid>>2, tc = (lid&3)*2;
    const int mBase = m0 + wm*64, nBase = n0 + wn*32;
#pragma unroll
    for (int i=0;i<4;i++){
#pragma unroll
        for (int hh=0; hh<2; hh++){
            const int row = mBase + i*16 + tr + hh*8;
            float brow = (flags & F_BROW) ? bias[row] : 0.f;
            float mult = scale;
            if (flags & F_ROWDIV) mult *= 1.0f / rowsum[(size_t)z*TN + row];
            if (flags & F_F32){
                float* op = of + (size_t)z*o_bs + (size_t)row*ldo;
#pragma unroll
                for (int j=0;j<4;j++){
                    const int n = nBase + j*8 + tc;
                    float v0 = acc[i][j][hh*2+0]*mult + brow;
                    float v1 = acc[i][j][hh*2+1]*mult + brow;
                    if (flags & F_BCOL){ v0 += bias[n]; v1 += bias[n+1]; }
                    if (flags & F_RELU){ v0 = fmaxf(v0,0.f); v1 = fmaxf(v1,0.f); }
                    float2 w; w.x = v0; w.y = v1;
                    *(float2*)(op + n) = w;
                }
            } else {
                __half* oph = oh + (size_t)z*o_bs + (size_t)row*ldo;
                __half* opl = ol + (size_t)z*o_bs + (size_t)row*ldo;
#pragma unroll
                for (int j=0;j<4;j++){
                    const int n = nBase + j*8 + tc;
                    float v0 = acc[i][j][hh*2+0]*mult + brow;
                    float v1 = acc[i][j][hh*2+1]*mult + brow;
                    if (flags & F_BCOL){ v0 += bias[n]; v1 += bias[n+1]; }
                    if (flags & F_RELU){ v0 = fmaxf(v0,0.f); v1 = fmaxf(v1,0.f); }
                    __half2 h2, l2;
                    split2(v0, h2.x, l2.x); split2(v1, h2.y, l2.y);
                    *(__half2*)(oph + n) = h2;
                    *(__half2*)(opl + n) = l2;
                }
            }
        }
    }
}

// ---------------- symmetric sim GEMM: upper-tri tiles, mirrored writes -------
// sim = scale * k k^T, k rows are [TN][512] hi/lo. Also publishes per-row max.
__global__ void __launch_bounds__(256,1) gemm_sym(
    const __half* __restrict__ kh, const __half* __restrict__ kl,
    float scale, __half* __restrict__ aH, __half* __restrict__ aL,
    u32* __restrict__ rmaxU)
{
    extern __shared__ char dsm[];
    const int tid = threadIdx.x, wid = tid>>5, lid = tid&31;
    const int z = blockIdx.z;
    // triangular decode: tiles (i,j), j>=i, 72x72 grid
    const int t = blockIdx.x;
    int i = (int)((145.0f - sqrtf(21025.0f - 8.0f*(float)t)) * 0.5f);
    while (i > 0 && i*72 - i*(i-1)/2 > t) i--;
    while ((i+1)*72 - (i+1)*i/2 <= t) i++;
    const int j = i + (t - (i*72 - i*(i-1)/2));
    const int m0 = i*128, n0 = j*128;

    const __half* ah = kh + (size_t)z*TN*512;
    const __half* al = kl + (size_t)z*TN*512;
    const int wm = wid>>2, wn = wid&3;
    const u32 sb = smem_u32(dsm);
    const int lrow = tid>>3, lc = tid&7;
    const __half* gp2[2] = {ah, al};

    float acc[4][4][4];
#pragma unroll
    for (int a=0;a<4;a++)
#pragma unroll
        for (int b=0;b<4;b++)
#pragma unroll
            for (int q=0;q<4;q++) acc[a][b][q] = 0.f;

    auto issue = [&](int s){
        const int k0 = s << 6;
        const u32 bufo = (u32)(s & 1) << 16;
#pragma unroll
        for (int arr=0; arr<4; arr++){
            const __half* gp = gp2[arr & 1];
            const int rb = (arr<2) ? m0 : n0;
            const u32 so = sb + bufo + arr*16384u;
#pragma unroll
            for (int q=0;q<4;q++){
                const int row = lrow + q*32;
                const void* g = gp + (size_t)(rb+row)*512 + k0 + lc*8;
                const u32 sa = so + (u32)(row*128) + (u32)((lc ^ (row&7)) << 4);
                cpasync16(sa, g);
            }
        }
        CP_COMMIT();
    };

    issue(0);
    for (int s=0; s<8; s++){
        CP_WAIT0();
        __syncthreads();
        if (s+1 < 8) issue(s+1);
        const u32 bufo = (u32)(s & 1) << 16;
        const u32 bAh = sb+bufo, bAl = sb+bufo+16384u, bBh = sb+bufo+32768u, bBl = sb+bufo+49152u;
        const int prA = (wm*64 + (lid&15)) * 128;
        const int prB0 = (wn*32 +      (lid&7) + ((lid>>4)<<3)) * 128;
        const int prB1 = (wn*32 + 16 + (lid&7) + ((lid>>4)<<3)) * 128;
#pragma unroll
        for (int st=0; st<4; st++){
            u32 Ah[4][4], Al[4][4], Bh[4][2], Bl[4][2];
            const int xa = ((st*2 + (lid>>4))    ^ (lid&7)) << 4;
            const int xb = ((st*2 + ((lid>>3)&1)) ^ (lid&7)) << 4;
#pragma unroll
            for (int a=0;a<4;a++){
                ldsm4(Ah[a][0],Ah[a][1],Ah[a][2],Ah[a][3], bAh + prA + a*2048 + xa);
                ldsm4(Al[a][0],Al[a][1],Al[a][2],Al[a][3], bAl + prA + a*2048 + xa);
            }
            {
                u32 r0,r1,r2,r3;
                ldsm4(r0,r1,r2,r3, bBh + prB0 + xb);
                Bh[0][0]=r0; Bh[0][1]=r1; Bh[1][0]=r2; Bh[1][1]=r3;
                ldsm4(r0,r1,r2,r3, bBh + prB1 + xb);
                Bh[2][0]=r0; Bh[2][1]=r1; Bh[3][0]=r2; Bh[3][1]=r3;
                ldsm4(r0,r1,r2,r3, bBl + prB0 + xb);
                Bl[0][0]=r0; Bl[0][1]=r1; Bl[1][0]=r2; Bl[1][1]=r3;
                ldsm4(r0,r1,r2,r3, bBl + prB1 + xb);
                Bl[2][0]=r0; Bl[2][1]=r1; Bl[3][0]=r2; Bl[3][1]=r3;
            }
#pragma unroll
            for (int a=0;a<4;a++)
#pragma unroll
                for (int b=0;b<4;b++) mma16816(acc[a][b], Ah[a], Bh[b]);
#pragma unroll
            for (int a=0;a<4;a++)
#pragma unroll
                for (int b=0;b<4;b++) mma16816(acc[a][b], Ah[a], Bl[b]);
#pragma unroll
            for (int a=0;a<4;a++)
#pragma unroll
                for (int b=0;b<4;b++) mma16816(acc[a][b], Al[a], Bh[b]);
        }
    }

    // ---- stage scaled tile to smem [128][129] ----
    __syncthreads();
    float* Sm = (float*)dsm;
    float* P  = Sm + 128*129;
    const int tr = lid>>2, tc = (lid&3)*2;
#pragma unroll
    for (int a=0;a<4;a++)
#pragma unroll
        for (int hh=0; hh<2; hh++){
            const int rl = wm*64 + a*16 + tr + hh*8;
#pragma unroll
            for (int b=0;b<4;b++){
                const int cl = wn*32 + b*8 + tc;
                Sm[rl*129 + cl]     = acc[a][b][hh*2+0]*scale;
                Sm[rl*129 + cl + 1] = acc[a][b][hh*2+1]*scale;
            }
        }
    __syncthreads();

    // ---- row / col max -> global atomicMax ----
    const int rr = tid & 127, hf2 = tid >> 7;
    {
        float m = -1e30f;
        for (int c=0;c<64;c++) m = fmaxf(m, Sm[rr*129 + hf2*64 + c]);
        P[rr*2 + hf2] = m;
    }
    __syncthreads();
    if (tid < 128) atomicMax(&rmaxU[(size_t)z*TN + m0 + tid], fenc(fmaxf(P[tid*2], P[tid*2+1])));
    __syncthreads();
    {
        float m = -1e30f;
        for (int r2=0;r2<64;r2++) m = fmaxf(m, Sm[(hf2*64 + r2)*129 + rr]);
        P[rr*2 + hf2] = m;
    }
    __syncthreads();
    if (tid < 128) atomicMax(&rmaxU[(size_t)z*TN + n0 + tid], fenc(fmaxf(P[tid*2], P[tid*2+1])));

    // ---- write tile (m0,n0) ----
    const size_t obase = (size_t)z*TN*TN;
    {
        const int r = tid>>1, c0 = (tid&1)*64;
        __half* oph = aH + obase + (size_t)(m0 + r)*TN + n0 + c0;
        __half* opl = aL + obase + (size_t)(m0 + r)*TN + n0 + c0;
        const float* Sr = Sm + r*129 + c0;
#pragma unroll
        for (int it=0; it<8; it++){
            __half2 hx[4], lx[4];
#pragma unroll
            for (int q=0;q<4;q++){
                split2(Sr[it*8 + 2*q],     hx[q].x, lx[q].x);
                split2(Sr[it*8 + 2*q + 1], hx[q].y, lx[q].y);
            }
            uint4 uh, ul;
            uh.x=*(u32*)&hx[0]; uh.y=*(u32*)&hx[1]; uh.z=*(u32*)&hx[2]; uh.w=*(u32*)&hx[3];
            ul.x=*(u32*)&lx[0]; ul.y=*(u32*)&lx[1]; ul.z=*(u32*)&lx[2]; ul.w=*(u32*)&lx[3];
            *(uint4*)(oph + it*8) = uh;
            *(uint4*)(opl + it*8) = ul;
        }
    }
    // ---- mirror tile (n0,m0) from transposed smem ----
    if (i != j){
        const int c = tid>>1, r0 = (tid&1)*64;
        __half* oph = aH + obase + (size_t)(n0 + c)*TN + m0 + r0;
        __half* opl = aL + obase + (size_t)(n0 + c)*TN + m0 + r0;
#pragma unroll
        for (int it=0; it<8; it++){
            __half2 hx[4], lx[4];
#pragma unroll
            for (int q=0;q<4;q++){
                float f0 = Sm[(r0 + it*8 + 2*q    )*129 + c];
                float f1 = Sm[(r0 + it*8 + 2*q + 1)*129 + c];
                split2(f0, hx[q].x, lx[q].x);
                split2(f1, hx[q].y, lx[q].y);
            }
            uint4 uh, ul;
            uh.x=*(u32*)&hx[0]; uh.y=*(u32*)&hx[1]; uh.z=*(u32*)&hx[2]; uh.w=*(u32*)&hx[3];
            ul.x=*(u32*)&lx[0]; ul.y=*(u32*)&lx[1]; ul.z=*(u32*)&lx[2]; ul.w=*(u32*)&lx[3];
            *(uint4*)(oph + it*8) = uh;
            *(uint4*)(opl + it*8) = ul;
        }
    }
}

// ---------------- misc prep --------------------------------------------------
__global__ void init_rmax(u32* r){
    int t = blockIdx.x*256 + threadIdx.x;
    if (t < NB*TN) r[t] = 0u;
}

__global__ void prep_w(const float* __restrict__ w, const float* __restrict__ cb,
                       const float* __restrict__ g, const float* __restrict__ bb,
                       const float* __restrict__ m, const float* __restrict__ v,
                       __half* __restrict__ wh, __half* __restrict__ wl,
                       float* __restrict__ bf_, int Kw, int has_bn)
{
    int o = blockIdx.x;
    float s = 1.f, off = 0.f;
    if (has_bn){ s = g[o] * rsqrtf(v[o] + 1e-5f); off = bb[o] - m[o]*s; }
    for (int c = threadIdx.x; c < Kw; c += blockDim.x){
        __half h, l; split2(w[o*Kw + c] * s, h, l);
        wh[o*Kw + c] = h; wl[o*Kw + c] = l;
    }
    if (threadIdx.x == 0 && bf_) bf_[o] = cb[o]*s + off;
}

__global__ void conv_x(const float* __restrict__ x, __half* __restrict__ xh, __half* __restrict__ xl)
{
    __shared__ float t[32][33];
    const int z = blockIdx.z;
    const float* xb = x + (size_t)z*512*TN;
    const int n0 = blockIdx.x*32, c0 = blockIdx.y*32;
    const int tx = threadIdx.x, ty = threadIdx.y;
#pragma unroll
    for (int i=0;i<4;i++)
        t[ty + i*8][tx] = xb[(size_t)(c0 + ty + i*8)*TN + n0 + tx];
    __syncthreads();
#pragma unroll
    for (int i=0;i<4;i++){
        int n = n0 + ty + i*8, c = c0 + tx;
        __half h, l; split2(t[tx][ty + i*8], h, l);
        size_t o = ((size_t)z*TN + n)*512 + c;
        xh[o] = h; xl[o] = l;
    }
}

// ---------------- single-pass softmax (uses precomputed rowmax) -------------
__global__ void __launch_bounds__(256) softmax_rows(__half* __restrict__ ah, __half* __restrict__ al,
                                                    const u32* __restrict__ rmaxU,
                                                    float* __restrict__ rowsum)
{
    const size_t ro = ((size_t)blockIdx.y*TN + blockIdx.x)*TN;
    uint2* ph = (uint2*)(ah + ro);
    uint2* pl = (uint2*)(al + ro);
    const int tid = threadIdx.x;
    __shared__ float red[8];
    const float mx = fdec(rmaxU[(size_t)blockIdx.y*TN + blockIdx.x]);

    float s = 0.f;
    for (int i = tid; i < TN/4; i += 256){
        uint2 uh = ph[i], ul = pl[i];
        __half2 h0 = *(__half2*)&uh.x, h1 = *(__half2*)&uh.y;
        __half2 l0 = *(__half2*)&ul.x, l1 = *(__half2*)&ul.y;
        float e0 = __expf(__half2float(h0.x)+__half2float(l0.x) - mx);
        float e1 = __expf(__half2float(h0.y)+__half2float(l0.y) - mx);
        float e2 = __expf(__half2float(h1.x)+__half2float(l1.x) - mx);
        float e3 = __expf(__half2float(h1.y)+__half2float(l1.y) - mx);
        s += e0+e1+e2+e3;
        __half2 oh0, ol0, oh1, ol1;
        split2(e0, oh0.x, ol0.x); split2(e1, oh0.y, ol0.y);
        split2(e2, oh1.x, ol1.x); split2(e3, oh1.y, ol1.y);
        uint2 wh, wl;
        wh.x = *(u32*)&oh0; wh.y = *(u32*)&oh1;
        wl.x = *(u32*)&ol0; wl.y = *(u32*)&ol1;
        ph[i] = wh; pl[i] = wl;
    }
#pragma unroll
    for (int o=16;o;o>>=1) s += __shfl_xor_sync(0xffffffffu, s, o);
    if ((tid&31)==0) red[tid>>5] = s;
    __syncthreads();
    if (tid==0)
        rowsum[(size_t)blockIdx.y*TN + blockIdx.x] =
            red[0]+red[1]+red[2]+red[3]+red[4]+red[5]+red[6]+red[7];
}

// ---------------- launch ----------------------------------------------------
#define DSMEM 131072

extern "C" void kernel_launch(void* const* d_in, const int* in_sizes, int n_in,
                              void* d_out, int out_size)
{
    const float* x  = (const float*)d_in[0];
    const float* wk = (const float*)d_in[1];
    const float* bk = (const float*)d_in[2];
    const float* g1 = (const float*)d_in[3];
    const float* b1 = (const float*)d_in[4];
    const float* m1 = (const float*)d_in[5];
    const float* v1 = (const float*)d_in[6];
    const float* wv = (const float*)d_in[7];
    const float* bv = (const float*)d_in[8];
    const float* wW = (const float*)d_in[9];
    const float* bW = (const float*)d_in[10];
    const float* wo = (const float*)d_in[11];
    const float* bo = (const float*)d_in[12];
    const float* g2 = (const float*)d_in[13];
    const float* b2 = (const float*)d_in[14];
    const float* m2 = (const float*)d_in[15];
    const float* v2 = (const float*)d_in[16];
    float* out = (float*)d_out;

    cudaFuncSetAttribute(gemm_tc,  cudaFuncAttributeMaxDynamicSharedMemorySize, DSMEM);
    cudaFuncSetAttribute(gemm_sym, cudaFuncAttributeMaxDynamicSharedMemorySize, DSMEM);

    __half *xh,*xl,*kh,*kl,*vh,*vl,*aH,*aL,*ch,*cl,*c2h,*c2l;
    __half *wkh,*wkl,*wvh,*wvl,*wWh,*wWl,*woh,*wol;
    float *bkf,*bof,*rs; u32 *rmx;
    cudaGetSymbolAddress((void**)&xh, g_xh);   cudaGetSymbolAddress((void**)&xl, g_xl);
    cudaGetSymbolAddress((void**)&kh, g_kh);   cudaGetSymbolAddress((void**)&kl, g_kl);
    cudaGetSymbolAddress((void**)&vh, g_vh);   cudaGetSymbolAddress((void**)&vl, g_vl);
    cudaGetSymbolAddress((void**)&aH, g_ahh);  cudaGetSymbolAddress((void**)&aL, g_all);
    cudaGetSymbolAddress((void**)&ch, g_ch);   cudaGetSymbolAddress((void**)&cl, g_cl);
    cudaGetSymbolAddress((void**)&c2h, g_c2h); cudaGetSymbolAddress((void**)&c2l, g_c2l);
    cudaGetSymbolAddress((void**)&wkh, g_wkh); cudaGetSymbolAddress((void**)&wkl, g_wkl);
    cudaGetSymbolAddress((void**)&wvh, g_wvh); cudaGetSymbolAddress((void**)&wvl, g_wvl);
    cudaGetSymbolAddress((void**)&wWh, g_wWh); cudaGetSymbolAddress((void**)&wWl, g_wWl);
    cudaGetSymbolAddress((void**)&woh, g_woh); cudaGetSymbolAddress((void**)&wol, g_wol);
    cudaGetSymbolAddress((void**)&bkf, g_bkf); cudaGetSymbolAddress((void**)&bof, g_bof);
    cudaGetSymbolAddress((void**)&rs,  g_rs);  cudaGetSymbolAddress((void**)&rmx, g_rmax);

    prep_w<<<512, 256>>>(wk, bk, g1, b1, m1, v1, wkh, wkl, bkf, 512, 1);
    prep_w<<<256, 256>>>(wv, nullptr, nullptr, nullptr, nullptr, nullptr, wvh, wvl, nullptr, 512, 0);
    prep_w<<<512, 256>>>(wW, nullptr, nullptr, nullptr, nullptr, nullptr, wWh, wWl, nullptr, 256, 0);
    prep_w<<<512, 256>>>(wo, bo, g2, b2, m2, v2, woh, wol, bof, 512, 1);
    conv_x<<<dim3(TN/32, 16, NB), dim3(32,8)>>>(x, xh, xl);
    init_rmax<<<(NB*TN + 255)/256, 256>>>(rmx);

    // k_t[n][cout] = relu(Wk_f x + bk_f)
    gemm_tc<<<dim3(72,4,NB), 256, DSMEM>>>(xh, xl, (size_t)TN*512, 512,
        wkh, wkl, 0, 512, 512, F_BCOL|F_RELU, bkf, nullptr, 1.f,
        kh, kl, nullptr, (size_t)TN*512, 512);
    // val[v][n] = Wv x + bv
    gemm_tc<<<dim3(2,72,NB), 256, DSMEM>>>(wvh, wvl, 0, 512,
        xh, xl, (size_t)TN*512, 512, 512, F_BROW, bv, nullptr, 1.f,
        vh, vl, nullptr, (size_t)256*TN, TN);
    // sim (symmetric): upper-tri tiles + mirror, fused rowmax
    gemm_sym<<<dim3(2628,1,NB), 256, DSMEM>>>(kh, kl, 0.0441941738241592f, aH, aL, rmx);
    // single-pass softmax (unnormalized exp + rowsum)
    softmax_rows<<<dim3(TN, NB), 256>>>(aH, aL, rmx, rs);
    // ctx[n][v] = (att[n]·val[v]) / rowsum[n]
    gemm_tc<<<dim3(72,2,NB), 256, DSMEM>>>(aH, aL, (size_t)TN*TN, TN,
        vh, vl, (size_t)256*TN, TN, TN, F_ROWDIV, nullptr, rs, 1.f,
        ch, cl, nullptr, (size_t)TN*256, 256);
    // ctx2[n][co] = wW ctx + bW
    gemm_tc<<<dim3(72,4,NB), 256, DSMEM>>>(ch, cl, (size_t)TN*256, 256,
        wWh, wWl, 0, 256, 256, F_BCOL, bW, nullptr, 1.f,
        c2h, c2l, nullptr, (size_t)TN*512, 512);
    // out[co][n] = relu(wo_f ctx2 + bo_f), fp32
    gemm_tc<<<dim3(4,72,NB), 256, DSMEM>>>(woh, wol, 0, 512,
        c2h, c2l, (size_t)TN*512, 512, 512, F_BROW|F_RELU|F_F32, bof, nullptr, 1.f,
        nullptr, nullptr, out, (size_t)512*TN, TN);
}

// round 6
// speedup vs baseline: 2.8567x; 1.0409x over previous
#include <cuda_runtime.h>
#include <cuda_fp16.h>
#include <math.h>
#include <stdint.h>

#define TN 9216
#define NB 2
typedef unsigned int u32;
typedef unsigned long long u64;

#define F_RELU   1
#define F_BROW   2
#define F_BCOL   4
#define F_ROWDIV 8
#define F_F32    16

// ---------------- scratch (static device arrays; no cudaMalloc allowed) ----
__device__ __half g_xh[(size_t)NB*TN*512],  g_xl[(size_t)NB*TN*512];
__device__ __half g_kh[(size_t)NB*TN*512],  g_kl[(size_t)NB*TN*512];
__device__ __half g_vh[(size_t)NB*256*TN],  g_vl[(size_t)NB*256*TN];
__device__ __half g_ahh[(size_t)NB*TN*TN],  g_all[(size_t)NB*TN*TN];
__device__ __half g_ch[(size_t)NB*TN*256],  g_cl[(size_t)NB*TN*256];
__device__ __half g_c2h[(size_t)NB*TN*512], g_c2l[(size_t)NB*TN*512];
__device__ __half g_wkh[512*512], g_wkl[512*512];
__device__ __half g_wvh[256*512], g_wvl[256*512];
__device__ __half g_wWh[512*256], g_wWl[512*256];
__device__ __half g_woh[512*512], g_wol[512*512];
__device__ float g_bkf[512], g_bof[512];
__device__ u32   g_rmax[NB*TN];

// ---------------- helpers ----------------------------------------------------
static __device__ __forceinline__ u32 smem_u32(const void* p){
    u32 a;
    asm("{ .reg .u64 t; cvta.to.shared.u64 t, %1; cvt.u32.u64 %0, t; }" : "=r"(a) : "l"(p));
    return a;
}
static __device__ __forceinline__ void cpasync16(u32 s, const void* g){
    asm volatile("cp.async.cg.shared.global [%0], [%1], 16;" :: "r"(s), "l"(g) : "memory");
}
#define CP_COMMIT() asm volatile("cp.async.commit_group;" ::: "memory")
#define CP_WAIT0()  asm volatile("cp.async.wait_group 0;" ::: "memory")

static __device__ __forceinline__ void ldsm4(u32& r0, u32& r1, u32& r2, u32& r3, u32 a){
    asm volatile("ldmatrix.sync.aligned.m8n8.x4.shared.b16 {%0,%1,%2,%3}, [%4];"
                 : "=r"(r0), "=r"(r1), "=r"(r2), "=r"(r3) : "r"(a));
}
static __device__ __forceinline__ void mma16816(float* d, const u32* a, const u32* b){
    asm volatile("mma.sync.aligned.m16n8k16.row.col.f32.f16.f16.f32 "
                 "{%0,%1,%2,%3}, {%4,%5,%6,%7}, {%8,%9}, {%0,%1,%2,%3};"
                 : "+f"(d[0]), "+f"(d[1]), "+f"(d[2]), "+f"(d[3])
                 : "r"(a[0]), "r"(a[1]), "r"(a[2]), "r"(a[3]), "r"(b[0]), "r"(b[1]));
}
static __device__ __forceinline__ void split2(float v, __half& h, __half& l){
    h = __float2half_rn(v);
    l = __float2half_rn(v - __half2float(h));
}
static __device__ __forceinline__ u32 fenc(float f){
    u32 u = __float_as_uint(f);
    return (u & 0x80000000u) ? ~u : (u | 0x80000000u);
}
static __device__ __forceinline__ float fdec(u32 u){
    return (u & 0x80000000u) ? __uint_as_float(u ^ 0x80000000u) : __uint_as_float(~u);
}

// ---------------- generic split-fp16 tensor GEMM -----------------------------
__global__ void __launch_bounds__(256,1) gemm_tc(
    const __half* __restrict__ ah, const __half* __restrict__ al, size_t a_bs, int lda,
    const __half* __restrict__ bh, const __half* __restrict__ bl, size_t b_bs, int ldb,
    int K, int flags, const float* __restrict__ bias,
    float scale, __half* oh, __half* ol, float* of, size_t o_bs, int ldo)
{
    extern __shared__ char dsm[];
    const int tid = threadIdx.x, wid = tid>>5, lid = tid&31;
    const int m0 = blockIdx.x*128, n0 = blockIdx.y*128, z = blockIdx.z;
    ah += (size_t)z*a_bs; al += (size_t)z*a_bs;
    bh += (size_t)z*b_bs; bl += (size_t)z*b_bs;
    const int wm = wid>>2, wn = wid&3;
    const u32 sb = smem_u32(dsm);
    const int lrow = tid>>3, lc = tid&7;
    const __half* gpA[2] = {ah, al};
    const __half* gpB[2] = {bh, bl};

    float acc[4][4][4];
#pragma unroll
    for (int i=0;i<4;i++)
#pragma unroll
        for (int j=0;j<4;j++)
#pragma unroll
            for (int q=0;q<4;q++) acc[i][j][q] = 0.f;

    const int S = K >> 6;
    auto issue = [&](int s){
        const int k0 = s << 6;
        const u32 bufo = (u32)(s & 1) << 16;
#pragma unroll
        for (int arr=0; arr<4; arr++){
            const __half* gp = (arr<2) ? gpA[arr] : gpB[arr-2];
            const int rb = (arr<2) ? m0 : n0;
            const int ld = (arr<2) ? lda : ldb;
            const u32 so = sb + bufo + arr*16384u;
#pragma unroll
            for (int i=0;i<4;i++){
                const int row = lrow + i*32;
                const void* g = gp + (size_t)(rb+row)*ld + k0 + lc*8;
                const u32 sa = so + (u32)(row*128) + (u32)((lc ^ (row&7)) << 4);
                cpasync16(sa, g);
            }
        }
        CP_COMMIT();
    };

    issue(0);
    for (int s=0; s<S; s++){
        CP_WAIT0();
        __syncthreads();
        if (s+1 < S) issue(s+1);
        const u32 bufo = (u32)(s & 1) << 16;
        const u32 bAh = sb+bufo, bAl = sb+bufo+16384u, bBh = sb+bufo+32768u, bBl = sb+bufo+49152u;
        const int prA = (wm*64 + (lid&15)) * 128;
        const int prB0 = (wn*32 +      (lid&7) + ((lid>>4)<<3)) * 128;
        const int prB1 = (wn*32 + 16 + (lid&7) + ((lid>>4)<<3)) * 128;
#pragma unroll
        for (int st=0; st<4; st++){
            u32 Ah[4][4], Al[4][4], Bh[4][2], Bl[4][2];
            const int xa = ((st*2 + (lid>>4))    ^ (lid&7)) << 4;
            const int xb = ((st*2 + ((lid>>3)&1)) ^ (lid&7)) << 4;
#pragma unroll
            for (int i=0;i<4;i++){
                ldsm4(Ah[i][0],Ah[i][1],Ah[i][2],Ah[i][3], bAh + prA + i*2048 + xa);
                ldsm4(Al[i][0],Al[i][1],Al[i][2],Al[i][3], bAl + prA + i*2048 + xa);
            }
            {
                u32 r0,r1,r2,r3;
                ldsm4(r0,r1,r2,r3, bBh + prB0 + xb);
                Bh[0][0]=r0; Bh[0][1]=r1; Bh[1][0]=r2; Bh[1][1]=r3;
                ldsm4(r0,r1,r2,r3, bBh + prB1 + xb);
                Bh[2][0]=r0; Bh[2][1]=r1; Bh[3][0]=r2; Bh[3][1]=r3;
                ldsm4(r0,r1,r2,r3, bBl + prB0 + xb);
                Bl[0][0]=r0; Bl[0][1]=r1; Bl[1][0]=r2; Bl[1][1]=r3;
                ldsm4(r0,r1,r2,r3, bBl + prB1 + xb);
                Bl[2][0]=r0; Bl[2][1]=r1; Bl[3][0]=r2; Bl[3][1]=r3;
            }
#pragma unroll
            for (int i=0;i<4;i++)
#pragma unroll
                for (int j=0;j<4;j++) mma16816(acc[i][j], Ah[i], Bh[j]);
#pragma unroll
            for (int i=0;i<4;i++)
#pragma unroll
                for (int j=0;j<4;j++) mma16816(acc[i][j], Ah[i], Bl[j]);
#pragma unroll
            for (int i=0;i<4;i++)
#pragma unroll
                for (int j=0;j<4;j++) mma16816(acc[i][j], Al[i], Bh[j]);
        }
    }

    const int tr = lid>>2, tc = (lid&3)*2;
    const int mBase = m0 + wm*64, nBase = n0 + wn*32;
#pragma unroll
    for (int i=0;i<4;i++){
#pragma unroll
        for (int hh=0; hh<2; hh++){
            const int row = mBase + i*16 + tr + hh*8;
            float brow = (flags & F_BROW) ? bias[row] : 0.f;
            if (flags & F_F32){
                float* op = of + (size_t)z*o_bs + (size_t)row*ldo;
#pragma unroll
                for (int j=0;j<4;j++){
                    const int n = nBase + j*8 + tc;
                    float v0 = acc[i][j][hh*2+0]*scale + brow;
                    float v1 = acc[i][j][hh*2+1]*scale + brow;
                    if (flags & F_BCOL){ v0 += bias[n]; v1 += bias[n+1]; }
                    if (flags & F_RELU){ v0 = fmaxf(v0,0.f); v1 = fmaxf(v1,0.f); }
                    float2 w; w.x = v0; w.y = v1;
                    *(float2*)(op + n) = w;
                }
            } else {
                __half* oph = oh + (size_t)z*o_bs + (size_t)row*ldo;
                __half* opl = ol + (size_t)z*o_bs + (size_t)row*ldo;
#pragma unroll
                for (int j=0;j<4;j++){
                    const int n = nBase + j*8 + tc;
                    float v0 = acc[i][j][hh*2+0]*scale + brow;
                    float v1 = acc[i][j][hh*2+1]*scale + brow;
                    if (flags & F_BCOL){ v0 += bias[n]; v1 += bias[n+1]; }
                    if (flags & F_RELU){ v0 = fmaxf(v0,0.f); v1 = fmaxf(v1,0.f); }
                    __half2 h2, l2;
                    split2(v0, h2.x, l2.x); split2(v1, h2.y, l2.y);
                    *(__half2*)(oph + n) = h2;
                    *(__half2*)(opl + n) = l2;
                }
            }
        }
    }
}

// ---------------- symmetric sim GEMM: upper-tri tiles, mirrored writes -------
__global__ void __launch_bounds__(256,1) gemm_sym(
    const __half* __restrict__ kh, const __half* __restrict__ kl,
    float scale, __half* __restrict__ aH, __half* __restrict__ aL,
    u32* __restrict__ rmaxU)
{
    extern __shared__ char dsm[];
    const int tid = threadIdx.x, wid = tid>>5, lid = tid&31;
    const int z = blockIdx.z;
    const int t = blockIdx.x;
    int i = (int)((145.0f - sqrtf(21025.0f - 8.0f*(float)t)) * 0.5f);
    while (i > 0 && i*72 - i*(i-1)/2 > t) i--;
    while ((i+1)*72 - (i+1)*i/2 <= t) i++;
    const int j = i + (t - (i*72 - i*(i-1)/2));
    const int m0 = i*128, n0 = j*128;

    const __half* ah = kh + (size_t)z*TN*512;
    const __half* al = kl + (size_t)z*TN*512;
    const int wm = wid>>2, wn = wid&3;
    const u32 sb = smem_u32(dsm);
    const int lrow = tid>>3, lc = tid&7;
    const __half* gp2[2] = {ah, al};

    float acc[4][4][4];
#pragma unroll
    for (int a=0;a<4;a++)
#pragma unroll
        for (int b=0;b<4;b++)
#pragma unroll
            for (int q=0;q<4;q++) acc[a][b][q] = 0.f;

    auto issue = [&](int s){
        const int k0 = s << 6;
        const u32 bufo = (u32)(s & 1) << 16;
#pragma unroll
        for (int arr=0; arr<4; arr++){
            const __half* gp = gp2[arr & 1];
            const int rb = (arr<2) ? m0 : n0;
            const u32 so = sb + bufo + arr*16384u;
#pragma unroll
            for (int q=0;q<4;q++){
                const int row = lrow + q*32;
                const void* g = gp + (size_t)(rb+row)*512 + k0 + lc*8;
                const u32 sa = so + (u32)(row*128) + (u32)((lc ^ (row&7)) << 4);
                cpasync16(sa, g);
            }
        }
        CP_COMMIT();
    };

    issue(0);
    for (int s=0; s<8; s++){
        CP_WAIT0();
        __syncthreads();
        if (s+1 < 8) issue(s+1);
        const u32 bufo = (u32)(s & 1) << 16;
        const u32 bAh = sb+bufo, bAl = sb+bufo+16384u, bBh = sb+bufo+32768u, bBl = sb+bufo+49152u;
        const int prA = (wm*64 + (lid&15)) * 128;
        const int prB0 = (wn*32 +      (lid&7) + ((lid>>4)<<3)) * 128;
        const int prB1 = (wn*32 + 16 + (lid&7) + ((lid>>4)<<3)) * 128;
#pragma unroll
        for (int st=0; st<4; st++){
            u32 Ah[4][4], Al[4][4], Bh[4][2], Bl[4][2];
            const int xa = ((st*2 + (lid>>4))    ^ (lid&7)) << 4;
            const int xb = ((st*2 + ((lid>>3)&1)) ^ (lid&7)) << 4;
#pragma unroll
            for (int a=0;a<4;a++){
                ldsm4(Ah[a][0],Ah[a][1],Ah[a][2],Ah[a][3], bAh + prA + a*2048 + xa);
                ldsm4(Al[a][0],Al[a][1],Al[a][2],Al[a][3], bAl + prA + a*2048 + xa);
            }
            {
                u32 r0,r1,r2,r3;
                ldsm4(r0,r1,r2,r3, bBh + prB0 + xb);
                Bh[0][0]=r0; Bh[0][1]=r1; Bh[1][0]=r2; Bh[1][1]=r3;
                ldsm4(r0,r1,r2,r3, bBh + prB1 + xb);
                Bh[2][0]=r0; Bh[2][1]=r1; Bh[3][0]=r2; Bh[3][1]=r3;
                ldsm4(r0,r1,r2,r3, bBl + prB0 + xb);
                Bl[0][0]=r0; Bl[0][1]=r1; Bl[1][0]=r2; Bl[1][1]=r3;
                ldsm4(r0,r1,r2,r3, bBl + prB1 + xb);
                Bl[2][0]=r0; Bl[2][1]=r1; Bl[3][0]=r2; Bl[3][1]=r3;
            }
#pragma unroll
            for (int a=0;a<4;a++)
#pragma unroll
                for (int b=0;b<4;b++) mma16816(acc[a][b], Ah[a], Bh[b]);
#pragma unroll
            for (int a=0;a<4;a++)
#pragma unroll
                for (int b=0;b<4;b++) mma16816(acc[a][b], Ah[a], Bl[b]);
#pragma unroll
            for (int a=0;a<4;a++)
#pragma unroll
                for (int b=0;b<4;b++) mma16816(acc[a][b], Al[a], Bh[b]);
        }
    }

    __syncthreads();
    float* Sm = (float*)dsm;
    float* P  = Sm + 128*129;
    const int tr = lid>>2, tc = (lid&3)*2;
#pragma unroll
    for (int a=0;a<4;a++)
#pragma unroll
        for (int hh=0; hh<2; hh++){
            const int rl = wm*64 + a*16 + tr + hh*8;
#pragma unroll
            for (int b=0;b<4;b++){
                const int cl = wn*32 + b*8 + tc;
                Sm[rl*129 + cl]     = acc[a][b][hh*2+0]*scale;
                Sm[rl*129 + cl + 1] = acc[a][b][hh*2+1]*scale;
            }
        }
    __syncthreads();

    const int rr = tid & 127, hf2 = tid >> 7;
    {
        float m = -1e30f;
        for (int c=0;c<64;c++) m = fmaxf(m, Sm[rr*129 + hf2*64 + c]);
        P[rr*2 + hf2] = m;
    }
    __syncthreads();
    if (tid < 128) atomicMax(&rmaxU[(size_t)z*TN + m0 + tid], fenc(fmaxf(P[tid*2], P[tid*2+1])));
    __syncthreads();
    {
        float m = -1e30f;
        for (int r2=0;r2<64;r2++) m = fmaxf(m, Sm[(hf2*64 + r2)*129 + rr]);
        P[rr*2 + hf2] = m;
    }
    __syncthreads();
    if (tid < 128) atomicMax(&rmaxU[(size_t)z*TN + n0 + tid], fenc(fmaxf(P[tid*2], P[tid*2+1])));

    const size_t obase = (size_t)z*TN*TN;
    {
        const int r = tid>>1, c0 = (tid&1)*64;
        __half* oph = aH + obase + (size_t)(m0 + r)*TN + n0 + c0;
        __half* opl = aL + obase + (size_t)(m0 + r)*TN + n0 + c0;
        const float* Sr = Sm + r*129 + c0;
#pragma unroll
        for (int it=0; it<8; it++){
            __half2 hx[4], lx[4];
#pragma unroll
            for (int q=0;q<4;q++){
                split2(Sr[it*8 + 2*q],     hx[q].x, lx[q].x);
                split2(Sr[it*8 + 2*q + 1], hx[q].y, lx[q].y);
            }
            uint4 uh, ul;
            uh.x=*(u32*)&hx[0]; uh.y=*(u32*)&hx[1]; uh.z=*(u32*)&hx[2]; uh.w=*(u32*)&hx[3];
            ul.x=*(u32*)&lx[0]; ul.y=*(u32*)&lx[1]; ul.z=*(u32*)&lx[2]; ul.w=*(u32*)&lx[3];
            *(uint4*)(oph + it*8) = uh;
            *(uint4*)(opl + it*8) = ul;
        }
    }
    if (i != j){
        const int c = tid>>1, r0 = (tid&1)*64;
        __half* oph = aH + obase + (size_t)(n0 + c)*TN + m0 + r0;
        __half* opl = aL + obase + (size_t)(n0 + c)*TN + m0 + r0;
#pragma unroll
        for (int it=0; it<8; it++){
            __half2 hx[4], lx[4];
#pragma unroll
            for (int q=0;q<4;q++){
                float f0 = Sm[(r0 + it*8 + 2*q    )*129 + c];
                float f1 = Sm[(r0 + it*8 + 2*q + 1)*129 + c];
                split2(f0, hx[q].x, lx[q].x);
                split2(f1, hx[q].y, lx[q].y);
            }
            uint4 uh, ul;
            uh.x=*(u32*)&hx[0]; uh.y=*(u32*)&hx[1]; uh.z=*(u32*)&hx[2]; uh.w=*(u32*)&hx[3];
            ul.x=*(u32*)&lx[0]; ul.y=*(u32*)&lx[1]; ul.z=*(u32*)&lx[2]; ul.w=*(u32*)&lx[3];
            *(uint4*)(oph + it*8) = uh;
            *(uint4*)(opl + it*8) = ul;
        }
    }
}

// ---------------- fused exp/rowsum/normalize ctx GEMM -----------------------
// ctx[n][v] = (1/Σ_m e[n][m]) Σ_m e[n][m]·val[v][m],  e = exp(sim - rowmax)
// M-tile 64 (att rows), N = 256 (all of val). K = TN.
// Stage layout (81920 B): Ah 8K | Al 8K | Bh 32K | Bl 32K; srow at 163840.
__global__ void __launch_bounds__(256,1) gemm_ctx_fused(
    const __half* __restrict__ aH, const __half* __restrict__ aL,
    const __half* __restrict__ vh, const __half* __restrict__ vl,
    const u32* __restrict__ rmaxU,
    __half* __restrict__ ch, __half* __restrict__ cl)
{
    extern __shared__ char dsm[];
    const int tid = threadIdx.x, wid = tid>>5, lid = tid&31;
    const int z = blockIdx.z;
    const int n0 = blockIdx.x*64;
    const size_t abase = (size_t)z*TN*TN;
    const __half* vhb = vh + (size_t)z*256*TN;
    const __half* vlb = vl + (size_t)z*256*TN;
    const u32 sb = smem_u32(dsm);
    float* srow = (float*)(dsm + 163840);

    const int wm = wid>>2, wn = wid&3;
    const int lr = tid>>3, lc = tid&7;

    const float mx0 = fdec(rmaxU[(size_t)z*TN + n0 + lr]);
    const float mx1 = fdec(rmaxU[(size_t)z*TN + n0 + lr + 32]);
    const __half* pA0h = aH + abase + (size_t)(n0+lr)*TN + lc*8;
    const __half* pA0l = aL + abase + (size_t)(n0+lr)*TN + lc*8;
    const __half* pA1h = pA0h + (size_t)32*TN;
    const __half* pA1l = pA0l + (size_t)32*TN;

    float acc[2][8][4];
#pragma unroll
    for (int i=0;i<2;i++)
#pragma unroll
        for (int j=0;j<8;j++)
#pragma unroll
            for (int q=0;q<4;q++) acc[i][j][q] = 0.f;
    float s0 = 0.f, s1 = 0.f;

    const int S = TN/64;   // 144
    uint4 ra[4];
    auto ldgA = [&](int s){
        const int k0 = s<<6;
        ra[0] = *(const uint4*)(pA0h + k0);
        ra[1] = *(const uint4*)(pA0l + k0);
        ra[2] = *(const uint4*)(pA1h + k0);
        ra[3] = *(const uint4*)(pA1l + k0);
    };
    auto issueB = [&](int s){
        const int k0 = s<<6;
        const u32 bufo = (u32)(s&1)*81920u;
#pragma unroll
        for (int arr=0; arr<2; arr++){
            const __half* gp = arr ? vlb : vhb;
            const u32 so = sb + bufo + 16384u + arr*32768u;
#pragma unroll
            for (int i=0;i<8;i++){
                const int row = lr + i*32;
                cpasync16(so + (u32)(row*128) + (u32)((lc ^ (row&7)) << 4),
                          gp + (size_t)row*TN + k0 + lc*8);
            }
        }
        CP_COMMIT();
    };
    auto exp8 = [&](uint4 uh4, uint4 ul4, float mxv, float& ssum, uint4& oh4, uint4& ol4){
        const __half2* hp = (const __half2*)&uh4;
        const __half2* lp = (const __half2*)&ul4;
        __half2 ho[4], lo[4];
#pragma unroll
        for (int q=0;q<4;q++){
            float e0 = __expf(__half2float(hp[q].x)+__half2float(lp[q].x) - mxv);
            float e1 = __expf(__half2float(hp[q].y)+__half2float(lp[q].y) - mxv);
            ssum += e0 + e1;
            split2(e0, ho[q].x, lo[q].x);
            split2(e1, ho[q].y, lo[q].y);
        }
        oh4 = *(uint4*)ho; ol4 = *(uint4*)lo;
    };

    issueB(0);
    ldgA(0);
    for (int s=0; s<S; s++){
        CP_WAIT0();
        __syncthreads();
        if (s+1 < S) issueB(s+1);
        {
            const u32 bufo = (u32)(s&1)*81920u;
            const int off0 = (int)bufo + lr*128 + ((lc ^ (lr&7)) << 4);
            uint4 oh4, ol4;
            exp8(ra[0], ra[1], mx0, s0, oh4, ol4);
            *(uint4*)(dsm + off0)         = oh4;
            *(uint4*)(dsm + off0 + 8192)  = ol4;
            exp8(ra[2], ra[3], mx1, s1, oh4, ol4);
            *(uint4*)(dsm + off0 + 4096)        = oh4;
            *(uint4*)(dsm + off0 + 4096 + 8192) = ol4;
        }
        if (s+1 < S) ldgA(s+1);
        __syncthreads();

        const u32 bufo = (u32)(s&1)*81920u;
        const u32 bA = sb + bufo, bB = sb + bufo + 16384u;
#pragma unroll
        for (int st=0; st<4; st++){
            u32 Ah[2][4], Al[2][4], Bh[8][2], Bl[8][2];
            const int xa = ((st*2 + (lid>>4))    ^ (lid&7)) << 4;
            const int xb = ((st*2 + ((lid>>3)&1)) ^ (lid&7)) << 4;
#pragma unroll
            for (int i=0;i<2;i++){
                const u32 pr = (u32)((wm*32 + i*16 + (lid&15)) * 128);
                ldsm4(Ah[i][0],Ah[i][1],Ah[i][2],Ah[i][3], bA + pr + xa);
                ldsm4(Al[i][0],Al[i][1],Al[i][2],Al[i][3], bA + 8192 + pr + xa);
            }
#pragma unroll
            for (int j2=0; j2<4; j2++){
                const u32 pr = (u32)((wn*64 + j2*16 + (lid&7) + ((lid>>4)<<3)) * 128);
                u32 r0,r1,r2,r3;
                ldsm4(r0,r1,r2,r3, bB + pr + xb);
                Bh[2*j2][0]=r0; Bh[2*j2][1]=r1; Bh[2*j2+1][0]=r2; Bh[2*j2+1][1]=r3;
                ldsm4(r0,r1,r2,r3, bB + 32768 + pr + xb);
                Bl[2*j2][0]=r0; Bl[2*j2][1]=r1; Bl[2*j2+1][0]=r2; Bl[2*j2+1][1]=r3;
            }
#pragma unroll
            for (int i=0;i<2;i++)
#pragma unroll
                for (int j=0;j<8;j++) mma16816(acc[i][j], Ah[i], Bh[j]);
#pragma unroll
            for (int i=0;i<2;i++)
#pragma unroll
                for (int j=0;j<8;j++) mma16816(acc[i][j], Ah[i], Bl[j]);
#pragma unroll
            for (int i=0;i<2;i++)
#pragma unroll
                for (int j=0;j<8;j++) mma16816(acc[i][j], Al[i], Bh[j]);
        }
    }

    // rowsum: reduce over the 8 lanes sharing each row
#pragma unroll
    for (int o=1;o<8;o<<=1){
        s0 += __shfl_xor_sync(0xffffffffu, s0, o);
        s1 += __shfl_xor_sync(0xffffffffu, s1, o);
    }
    __syncthreads();
    if ((tid&7)==0){ srow[lr] = s0; srow[lr+32] = s1; }
    __syncthreads();

    const int tr = lid>>2, tc2 = (lid&3)*2;
#pragma unroll
    for (int i=0;i<2;i++){
#pragma unroll
        for (int hh=0; hh<2; hh++){
            const int rowl = wm*32 + i*16 + tr + hh*8;
            const float inv = 1.0f / srow[rowl];
            const int row = n0 + rowl;
            __half* oph = ch + (size_t)z*TN*256 + (size_t)row*256 + wn*64;
            __half* opl = cl + (size_t)z*TN*256 + (size_t)row*256 + wn*64;
#pragma unroll
            for (int j=0;j<8;j++){
                const int col = j*8 + tc2;
                float v0 = acc[i][j][hh*2+0]*inv;
                float v1 = acc[i][j][hh*2+1]*inv;
                __half2 h2, l2;
                split2(v0, h2.x, l2.x); split2(v1, h2.y, l2.y);
                *(__half2*)(oph + col) = h2;
                *(__half2*)(opl + col) = l2;
            }
        }
    }
}

// ---------------- misc prep --------------------------------------------------
__global__ void init_rmax(u32* r){
    int t = blockIdx.x*256 + threadIdx.x;
    if (t < NB*TN) r[t] = 0u;
}

__global__ void prep_w(const float* __restrict__ w, const float* __restrict__ cb,
                       const float* __restrict__ g, const float* __restrict__ bb,
                       const float* __restrict__ m, const float* __restrict__ v,
                       __half* __restrict__ wh, __half* __restrict__ wl,
                       float* __restrict__ bf_, int Kw, int has_bn)
{
    int o = blockIdx.x;
    float s = 1.f, off = 0.f;
    if (has_bn){ s = g[o] * rsqrtf(v[o] + 1e-5f); off = bb[o] - m[o]*s; }
    for (int c = threadIdx.x; c < Kw; c += blockDim.x){
        __half h, l; split2(w[o*Kw + c] * s, h, l);
        wh[o*Kw + c] = h; wl[o*Kw + c] = l;
    }
    if (threadIdx.x == 0 && bf_) bf_[o] = cb[o]*s + off;
}

__global__ void conv_x(const float* __restrict__ x, __half* __restrict__ xh, __half* __restrict__ xl)
{
    __shared__ float t[32][33];
    const int z = blockIdx.z;
    const float* xb = x + (size_t)z*512*TN;
    const int n0 = blockIdx.x*32, c0 = blockIdx.y*32;
    const int tx = threadIdx.x, ty = threadIdx.y;
#pragma unroll
    for (int i=0;i<4;i++)
        t[ty + i*8][tx] = xb[(size_t)(c0 + ty + i*8)*TN + n0 + tx];
    __syncthreads();
#pragma unroll
    for (int i=0;i<4;i++){
        int n = n0 + ty + i*8, c = c0 + tx;
        __half h, l; split2(t[tx][ty + i*8], h, l);
        size_t o = ((size_t)z*TN + n)*512 + c;
        xh[o] = h; xl[o] = l;
    }
}

// ---------------- launch ----------------------------------------------------
#define DSMEM     131072
#define DSMEM_CTX 164096

extern "C" void kernel_launch(void* const* d_in, const int* in_sizes, int n_in,
                              void* d_out, int out_size)
{
    const float* x  = (const float*)d_in[0];
    const float* wk = (const float*)d_in[1];
    const float* bk = (const float*)d_in[2];
    const float* g1 = (const float*)d_in[3];
    const float* b1 = (const float*)d_in[4];
    const float* m1 = (const float*)d_in[5];
    const float* v1 = (const float*)d_in[6];
    const float* wv = (const float*)d_in[7];
    const float* bv = (const float*)d_in[8];
    const float* wW = (const float*)d_in[9];
    const float* bW = (const float*)d_in[10];
    const float* wo = (const float*)d_in[11];
    const float* bo = (const float*)d_in[12];
    const float* g2 = (const float*)d_in[13];
    const float* b2 = (const float*)d_in[14];
    const float* m2 = (const float*)d_in[15];
    const float* v2 = (const float*)d_in[16];
    float* out = (float*)d_out;

    cudaFuncSetAttribute(gemm_tc,        cudaFuncAttributeMaxDynamicSharedMemorySize, DSMEM);
    cudaFuncSetAttribute(gemm_sym,       cudaFuncAttributeMaxDynamicSharedMemorySize, DSMEM);
    cudaFuncSetAttribute(gemm_ctx_fused, cudaFuncAttributeMaxDynamicSharedMemorySize, DSMEM_CTX);

    __half *xh,*xl,*kh,*kl,*vh,*vl,*aH,*aL,*ch,*cl,*c2h,*c2l;
    __half *wkh,*wkl,*wvh,*wvl,*wWh,*wWl,*woh,*wol;
    float *bkf,*bof; u32 *rmx;
    cudaGetSymbolAddress((void**)&xh, g_xh);   cudaGetSymbolAddress((void**)&xl, g_xl);
    cudaGetSymbolAddress((void**)&kh, g_kh);   cudaGetSymbolAddress((void**)&kl, g_kl);
    cudaGetSymbolAddress((void**)&vh, g_vh);   cudaGetSymbolAddress((void**)&vl, g_vl);
    cudaGetSymbolAddress((void**)&aH, g_ahh);  cudaGetSymbolAddress((void**)&aL, g_all);
    cudaGetSymbolAddress((void**)&ch, g_ch);   cudaGetSymbolAddress((void**)&cl, g_cl);
    cudaGetSymbolAddress((void**)&c2h, g_c2h); cudaGetSymbolAddress((void**)&c2l, g_c2l);
    cudaGetSymbolAddress((void**)&wkh, g_wkh); cudaGetSymbolAddress((void**)&wkl, g_wkl);
    cudaGetSymbolAddress((void**)&wvh, g_wvh); cudaGetSymbolAddress((void**)&wvl, g_wvl);
    cudaGetSymbolAddress((void**)&wWh, g_wWh); cudaGetSymbolAddress((void**)&wWl, g_wWl);
    cudaGetSymbolAddress((void**)&woh, g_woh); cudaGetSymbolAddress((void**)&wol, g_wol);
    cudaGetSymbolAddress((void**)&bkf, g_bkf); cudaGetSymbolAddress((void**)&bof, g_bof);
    cudaGetSymbolAddress((void**)&rmx, g_rmax);

    prep_w<<<512, 256>>>(wk, bk, g1, b1, m1, v1, wkh, wkl, bkf, 512, 1);
    prep_w<<<256, 256>>>(wv, nullptr, nullptr, nullptr, nullptr, nullptr, wvh, wvl, nullptr, 512, 0);
    prep_w<<<512, 256>>>(wW, nullptr, nullptr, nullptr, nullptr, nullptr, wWh, wWl, nullptr, 256, 0);
    prep_w<<<512, 256>>>(wo, bo, g2, b2, m2, v2, woh, wol, bof, 512, 1);
    conv_x<<<dim3(TN/32, 16, NB), dim3(32,8)>>>(x, xh, xl);
    init_rmax<<<(NB*TN + 255)/256, 256>>>(rmx);

    // k_t[n][cout] = relu(Wk_f x + bk_f)
    gemm_tc<<<dim3(72,4,NB), 256, DSMEM>>>(xh, xl, (size_t)TN*512, 512,
        wkh, wkl, 0, 512, 512, F_BCOL|F_RELU, bkf, 1.f,
        kh, kl, nullptr, (size_t)TN*512, 512);
    // val[v][n] = Wv x + bv
    gemm_tc<<<dim3(2,72,NB), 256, DSMEM>>>(wvh, wvl, 0, 512,
        xh, xl, (size_t)TN*512, 512, 512, F_BROW, bv, 1.f,
        vh, vl, nullptr, (size_t)256*TN, TN);
    // sim (symmetric): upper-tri tiles + mirror + fused rowmax
    gemm_sym<<<dim3(2628,1,NB), 256, DSMEM>>>(kh, kl, 0.0441941738241592f, aH, aL, rmx);
    // ctx with fused exp/rowsum/normalize
    gemm_ctx_fused<<<dim3(TN/64,1,NB), 256, DSMEM_CTX>>>(aH, aL, vh, vl, rmx, ch, cl);
    // ctx2[n][co] = wW ctx + bW
    gemm_tc<<<dim3(72,4,NB), 256, DSMEM>>>(ch, cl, (size_t)TN*256, 256,
        wWh, wWl, 0, 256, 256, F_BCOL, bW, 1.f,
        c2h, c2l, nullptr, (size_t)TN*512, 512);
    // out[co][n] = relu(wo_f ctx2 + bo_f), fp32
    gemm_tc<<<dim3(4,72,NB), 256, DSMEM>>>(woh, wol, 0, 512,
        c2h, c2l, (size_t)TN*512, 512, 512, F_BROW|F_RELU|F_F32, bof, 1.f,
        nullptr, nullptr, out, (size_t)512*TN, TN);
}

// round 7
// speedup vs baseline: 3.1600x; 1.1062x over previous
#include <cuda_runtime.h>
#include <cuda_fp16.h>
#include <math.h>
#include <stdint.h>

#define TN 9216
#define NB 2
typedef unsigned int u32;
typedef unsigned long long u64;

#define F_RELU   1
#define F_BROW   2
#define F_BCOL   4
#define F_F32    16

// ---------------- scratch (static device arrays; no cudaMalloc allowed) ----
__device__ __half g_xh[(size_t)NB*TN*512],  g_xl[(size_t)NB*TN*512];
__device__ __half g_kh[(size_t)NB*TN*512],  g_kl[(size_t)NB*TN*512];
__device__ __half g_vh[(size_t)NB*256*TN],  g_vl[(size_t)NB*256*TN];
__device__ __half g_ahh[(size_t)NB*TN*TN],  g_all[(size_t)NB*TN*TN];
__device__ __half g_ch[(size_t)NB*TN*256],  g_cl[(size_t)NB*TN*256];
__device__ __half g_c2h[(size_t)NB*TN*512], g_c2l[(size_t)NB*TN*512];
__device__ __half g_wkh[512*512], g_wkl[512*512];
__device__ __half g_wvh[256*512], g_wvl[256*512];
__device__ __half g_wWh[512*256], g_wWl[512*256];
__device__ __half g_woh[512*512], g_wol[512*512];
__device__ float g_bkf[512], g_bof[512];
__device__ u32   g_rmax[NB*TN];

// ---------------- helpers ----------------------------------------------------
static __device__ __forceinline__ u32 smem_u32(const void* p){
    u32 a;
    asm("{ .reg .u64 t; cvta.to.shared.u64 t, %1; cvt.u32.u64 %0, t; }" : "=r"(a) : "l"(p));
    return a;
}
static __device__ __forceinline__ void cpasync16(u32 s, const void* g){
    asm volatile("cp.async.cg.shared.global [%0], [%1], 16;" :: "r"(s), "l"(g) : "memory");
}
#define CP_COMMIT() asm volatile("cp.async.commit_group;" ::: "memory")
#define CP_WAIT0()  asm volatile("cp.async.wait_group 0;" ::: "memory")

static __device__ __forceinline__ void ldsm4(u32& r0, u32& r1, u32& r2, u32& r3, u32 a){
    asm volatile("ldmatrix.sync.aligned.m8n8.x4.shared.b16 {%0,%1,%2,%3}, [%4];"
                 : "=r"(r0), "=r"(r1), "=r"(r2), "=r"(r3) : "r"(a));
}
static __device__ __forceinline__ void mma16816(float* d, const u32* a, const u32* b){
    asm volatile("mma.sync.aligned.m16n8k16.row.col.f32.f16.f16.f32 "
                 "{%0,%1,%2,%3}, {%4,%5,%6,%7}, {%8,%9}, {%0,%1,%2,%3};"
                 : "+f"(d[0]), "+f"(d[1]), "+f"(d[2]), "+f"(d[3])
                 : "r"(a[0]), "r"(a[1]), "r"(a[2]), "r"(a[3]), "r"(b[0]), "r"(b[1]));
}
static __device__ __forceinline__ void split2(float v, __half& h, __half& l){
    h = __float2half_rn(v);
    l = __float2half_rn(v - __half2float(h));
}
static __device__ __forceinline__ u32 fenc(float f){
    u32 u = __float_as_uint(f);
    return (u & 0x80000000u) ? ~u : (u | 0x80000000u);
}
static __device__ __forceinline__ float fdec(u32 u){
    return (u & 0x80000000u) ? __uint_as_float(u ^ 0x80000000u) : __uint_as_float(~u);
}

// ---------------- generic split-fp16 tensor GEMM -----------------------------
__global__ void __launch_bounds__(256,1) gemm_tc(
    const __half* __restrict__ ah, const __half* __restrict__ al, size_t a_bs, int lda,
    const __half* __restrict__ bh, const __half* __restrict__ bl, size_t b_bs, int ldb,
    int K, int flags, const float* __restrict__ bias,
    float scale, __half* oh, __half* ol, float* of, size_t o_bs, int ldo)
{
    extern __shared__ char dsm[];
    const int tid = threadIdx.x, wid = tid>>5, lid = tid&31;
    const int m0 = blockIdx.x*128, n0 = blockIdx.y*128, z = blockIdx.z;
    ah += (size_t)z*a_bs; al += (size_t)z*a_bs;
    bh += (size_t)z*b_bs; bl += (size_t)z*b_bs;
    const int wm = wid>>2, wn = wid&3;
    const u32 sb = smem_u32(dsm);
    const int lrow = tid>>3, lc = tid&7;
    const __half* gpA[2] = {ah, al};
    const __half* gpB[2] = {bh, bl};

    float acc[4][4][4];
#pragma unroll
    for (int i=0;i<4;i++)
#pragma unroll
        for (int j=0;j<4;j++)
#pragma unroll
            for (int q=0;q<4;q++) acc[i][j][q] = 0.f;

    const int S = K >> 6;
    auto issue = [&](int s){
        const int k0 = s << 6;
        const u32 bufo = (u32)(s & 1) << 16;
#pragma unroll
        for (int arr=0; arr<4; arr++){
            const __half* gp = (arr<2) ? gpA[arr] : gpB[arr-2];
            const int rb = (arr<2) ? m0 : n0;
            const int ld = (arr<2) ? lda : ldb;
            const u32 so = sb + bufo + arr*16384u;
#pragma unroll
            for (int i=0;i<4;i++){
                const int row = lrow + i*32;
                const void* g = gp + (size_t)(rb+row)*ld + k0 + lc*8;
                const u32 sa = so + (u32)(row*128) + (u32)((lc ^ (row&7)) << 4);
                cpasync16(sa, g);
            }
        }
        CP_COMMIT();
    };

    issue(0);
    for (int s=0; s<S; s++){
        CP_WAIT0();
        __syncthreads();
        if (s+1 < S) issue(s+1);
        const u32 bufo = (u32)(s & 1) << 16;
        const u32 bAh = sb+bufo, bAl = sb+bufo+16384u, bBh = sb+bufo+32768u, bBl = sb+bufo+49152u;
        const int prA = (wm*64 + (lid&15)) * 128;
        const int prB0 = (wn*32 +      (lid&7) + ((lid>>4)<<3)) * 128;
        const int prB1 = (wn*32 + 16 + (lid&7) + ((lid>>4)<<3)) * 128;
#pragma unroll
        for (int st=0; st<4; st++){
            u32 Ah[4][4], Al[4][4], Bh[4][2], Bl[4][2];
            const int xa = ((st*2 + (lid>>4))    ^ (lid&7)) << 4;
            const int xb = ((st*2 + ((lid>>3)&1)) ^ (lid&7)) << 4;
#pragma unroll
            for (int i=0;i<4;i++){
                ldsm4(Ah[i][0],Ah[i][1],Ah[i][2],Ah[i][3], bAh + prA + i*2048 + xa);
                ldsm4(Al[i][0],Al[i][1],Al[i][2],Al[i][3], bAl + prA + i*2048 + xa);
            }
            {
                u32 r0,r1,r2,r3;
                ldsm4(r0,r1,r2,r3, bBh + prB0 + xb);
                Bh[0][0]=r0; Bh[0][1]=r1; Bh[1][0]=r2; Bh[1][1]=r3;
                ldsm4(r0,r1,r2,r3, bBh + prB1 + xb);
                Bh[2][0]=r0; Bh[2][1]=r1; Bh[3][0]=r2; Bh[3][1]=r3;
                ldsm4(r0,r1,r2,r3, bBl + prB0 + xb);
                Bl[0][0]=r0; Bl[0][1]=r1; Bl[1][0]=r2; Bl[1][1]=r3;
                ldsm4(r0,r1,r2,r3, bBl + prB1 + xb);
                Bl[2][0]=r0; Bl[2][1]=r1; Bl[3][0]=r2; Bl[3][1]=r3;
            }
#pragma unroll
            for (int i=0;i<4;i++)
#pragma unroll
                for (int j=0;j<4;j++) mma16816(acc[i][j], Ah[i], Bh[j]);
#pragma unroll
            for (int i=0;i<4;i++)
#pragma unroll
                for (int j=0;j<4;j++) mma16816(acc[i][j], Ah[i], Bl[j]);
#pragma unroll
            for (int i=0;i<4;i++)
#pragma unroll
                for (int j=0;j<4;j++) mma16816(acc[i][j], Al[i], Bh[j]);
        }
    }

    const int tr = lid>>2, tc = (lid&3)*2;
    const int mBase = m0 + wm*64, nBase = n0 + wn*32;
#pragma unroll
    for (int i=0;i<4;i++){
#pragma unroll
        for (int hh=0; hh<2; hh++){
            const int row = mBase + i*16 + tr + hh*8;
            float brow = (flags & F_BROW) ? bias[row] : 0.f;
            if (flags & F_F32){
                float* op = of + (size_t)z*o_bs + (size_t)row*ldo;
#pragma unroll
                for (int j=0;j<4;j++){
                    const int n = nBase + j*8 + tc;
                    float v0 = acc[i][j][hh*2+0]*scale + brow;
                    float v1 = acc[i][j][hh*2+1]*scale + brow;
                    if (flags & F_BCOL){ v0 += bias[n]; v1 += bias[n+1]; }
                    if (flags & F_RELU){ v0 = fmaxf(v0,0.f); v1 = fmaxf(v1,0.f); }
                    float2 w; w.x = v0; w.y = v1;
                    *(float2*)(op + n) = w;
                }
            } else {
                __half* oph = oh + (size_t)z*o_bs + (size_t)row*ldo;
                __half* opl = ol + (size_t)z*o_bs + (size_t)row*ldo;
#pragma unroll
                for (int j=0;j<4;j++){
                    const int n = nBase + j*8 + tc;
                    float v0 = acc[i][j][hh*2+0]*scale + brow;
                    float v1 = acc[i][j][hh*2+1]*scale + brow;
                    if (flags & F_BCOL){ v0 += bias[n]; v1 += bias[n+1]; }
                    if (flags & F_RELU){ v0 = fmaxf(v0,0.f); v1 = fmaxf(v1,0.f); }
                    __half2 h2, l2;
                    split2(v0, h2.x, l2.x); split2(v1, h2.y, l2.y);
                    *(__half2*)(oph + n) = h2;
                    *(__half2*)(opl + n) = l2;
                }
            }
        }
    }
}

// ---------------- symmetric sim GEMM: upper-tri tiles, mirrored writes -------
__global__ void __launch_bounds__(256,1) gemm_sym(
    const __half* __restrict__ kh, const __half* __restrict__ kl,
    float scale, __half* __restrict__ aH, __half* __restrict__ aL,
    u32* __restrict__ rmaxU)
{
    extern __shared__ char dsm[];
    const int tid = threadIdx.x, wid = tid>>5, lid = tid&31;
    const int z = blockIdx.z;
    const int t = blockIdx.x;
    int i = (int)((145.0f - sqrtf(21025.0f - 8.0f*(float)t)) * 0.5f);
    while (i > 0 && i*72 - i*(i-1)/2 > t) i--;
    while ((i+1)*72 - (i+1)*i/2 <= t) i++;
    const int j = i + (t - (i*72 - i*(i-1)/2));
    const int m0 = i*128, n0 = j*128;

    const __half* ah = kh + (size_t)z*TN*512;
    const __half* al = kl + (size_t)z*TN*512;
    const int wm = wid>>2, wn = wid&3;
    const u32 sb = smem_u32(dsm);
    const int lrow = tid>>3, lc = tid&7;
    const __half* gp2[2] = {ah, al};

    float acc[4][4][4];
#pragma unroll
    for (int a=0;a<4;a++)
#pragma unroll
        for (int b=0;b<4;b++)
#pragma unroll
            for (int q=0;q<4;q++) acc[a][b][q] = 0.f;

    auto issue = [&](int s){
        const int k0 = s << 6;
        const u32 bufo = (u32)(s & 1) << 16;
#pragma unroll
        for (int arr=0; arr<4; arr++){
            const __half* gp = gp2[arr & 1];
            const int rb = (arr<2) ? m0 : n0;
            const u32 so = sb + bufo + arr*16384u;
#pragma unroll
            for (int q=0;q<4;q++){
                const int row = lrow + q*32;
                const void* g = gp + (size_t)(rb+row)*512 + k0 + lc*8;
                const u32 sa = so + (u32)(row*128) + (u32)((lc ^ (row&7)) << 4);
                cpasync16(sa, g);
            }
        }
        CP_COMMIT();
    };

    issue(0);
    for (int s=0; s<8; s++){
        CP_WAIT0();
        __syncthreads();
        if (s+1 < 8) issue(s+1);
        const u32 bufo = (u32)(s & 1) << 16;
        const u32 bAh = sb+bufo, bAl = sb+bufo+16384u, bBh = sb+bufo+32768u, bBl = sb+bufo+49152u;
        const int prA = (wm*64 + (lid&15)) * 128;
        const int prB0 = (wn*32 +      (lid&7) + ((lid>>4)<<3)) * 128;
        const int prB1 = (wn*32 + 16 + (lid&7) + ((lid>>4)<<3)) * 128;
#pragma unroll
        for (int st=0; st<4; st++){
            u32 Ah[4][4], Al[4][4], Bh[4][2], Bl[4][2];
            const int xa = ((st*2 + (lid>>4))    ^ (lid&7)) << 4;
            const int xb = ((st*2 + ((lid>>3)&1)) ^ (lid&7)) << 4;
#pragma unroll
            for (int a=0;a<4;a++){
                ldsm4(Ah[a][0],Ah[a][1],Ah[a][2],Ah[a][3], bAh + prA + a*2048 + xa);
                ldsm4(Al[a][0],Al[a][1],Al[a][2],Al[a][3], bAl + prA + a*2048 + xa);
            }
            {
                u32 r0,r1,r2,r3;
                ldsm4(r0,r1,r2,r3, bBh + prB0 + xb);
                Bh[0][0]=r0; Bh[0][1]=r1; Bh[1][0]=r2; Bh[1][1]=r3;
                ldsm4(r0,r1,r2,r3, bBh + prB1 + xb);
                Bh[2][0]=r0; Bh[2][1]=r1; Bh[3][0]=r2; Bh[3][1]=r3;
                ldsm4(r0,r1,r2,r3, bBl + prB0 + xb);
                Bl[0][0]=r0; Bl[0][1]=r1; Bl[1][0]=r2; Bl[1][1]=r3;
                ldsm4(r0,r1,r2,r3, bBl + prB1 + xb);
                Bl[2][0]=r0; Bl[2][1]=r1; Bl[3][0]=r2; Bl[3][1]=r3;
            }
#pragma unroll
            for (int a=0;a<4;a++)
#pragma unroll
                for (int b=0;b<4;b++) mma16816(acc[a][b], Ah[a], Bh[b]);
#pragma unroll
            for (int a=0;a<4;a++)
#pragma unroll
                for (int b=0;b<4;b++) mma16816(acc[a][b], Ah[a], Bl[b]);
#pragma unroll
            for (int a=0;a<4;a++)
#pragma unroll
                for (int b=0;b<4;b++) mma16816(acc[a][b], Al[a], Bh[b]);
        }
    }

    __syncthreads();
    float* Sm = (float*)dsm;
    float* P  = Sm + 128*129;
    const int tr = lid>>2, tc = (lid&3)*2;
#pragma unroll
    for (int a=0;a<4;a++)
#pragma unroll
        for (int hh=0; hh<2; hh++){
            const int rl = wm*64 + a*16 + tr + hh*8;
#pragma unroll
            for (int b=0;b<4;b++){
                const int cl = wn*32 + b*8 + tc;
                Sm[rl*129 + cl]     = acc[a][b][hh*2+0]*scale;
                Sm[rl*129 + cl + 1] = acc[a][b][hh*2+1]*scale;
            }
        }
    __syncthreads();

    const int rr = tid & 127, hf2 = tid >> 7;
    {
        float m = -1e30f;
        for (int c=0;c<64;c++) m = fmaxf(m, Sm[rr*129 + hf2*64 + c]);
        P[rr*2 + hf2] = m;
    }
    __syncthreads();
    if (tid < 128) atomicMax(&rmaxU[(size_t)z*TN + m0 + tid], fenc(fmaxf(P[tid*2], P[tid*2+1])));
    __syncthreads();
    {
        float m = -1e30f;
        for (int r2=0;r2<64;r2++) m = fmaxf(m, Sm[(hf2*64 + r2)*129 + rr]);
        P[rr*2 + hf2] = m;
    }
    __syncthreads();
    if (tid < 128) atomicMax(&rmaxU[(size_t)z*TN + n0 + tid], fenc(fmaxf(P[tid*2], P[tid*2+1])));

    const size_t obase = (size_t)z*TN*TN;
    {
        const int r = tid>>1, c0 = (tid&1)*64;
        __half* oph = aH + obase + (size_t)(m0 + r)*TN + n0 + c0;
        __half* opl = aL + obase + (size_t)(m0 + r)*TN + n0 + c0;
        const float* Sr = Sm + r*129 + c0;
#pragma unroll
        for (int it=0; it<8; it++){
            __half2 hx[4], lx[4];
#pragma unroll
            for (int q=0;q<4;q++){
                split2(Sr[it*8 + 2*q],     hx[q].x, lx[q].x);
                split2(Sr[it*8 + 2*q + 1], hx[q].y, lx[q].y);
            }
            uint4 uh, ul;
            uh.x=*(u32*)&hx[0]; uh.y=*(u32*)&hx[1]; uh.z=*(u32*)&hx[2]; uh.w=*(u32*)&hx[3];
            ul.x=*(u32*)&lx[0]; ul.y=*(u32*)&lx[1]; ul.z=*(u32*)&lx[2]; ul.w=*(u32*)&lx[3];
            *(uint4*)(oph + it*8) = uh;
            *(uint4*)(opl + it*8) = ul;
        }
    }
    if (i != j){
        const int c = tid>>1, r0 = (tid&1)*64;
        __half* oph = aH + obase + (size_t)(n0 + c)*TN + m0 + r0;
        __half* opl = aL + obase + (size_t)(n0 + c)*TN + m0 + r0;
#pragma unroll
        for (int it=0; it<8; it++){
            __half2 hx[4], lx[4];
#pragma unroll
            for (int q=0;q<4;q++){
                float f0 = Sm[(r0 + it*8 + 2*q    )*129 + c];
                float f1 = Sm[(r0 + it*8 + 2*q + 1)*129 + c];
                split2(f0, hx[q].x, lx[q].x);
                split2(f1, hx[q].y, lx[q].y);
            }
            uint4 uh, ul;
            uh.x=*(u32*)&hx[0]; uh.y=*(u32*)&hx[1]; uh.z=*(u32*)&hx[2]; uh.w=*(u32*)&hx[3];
            ul.x=*(u32*)&lx[0]; ul.y=*(u32*)&lx[1]; ul.z=*(u32*)&lx[2]; ul.w=*(u32*)&lx[3];
            *(uint4*)(oph + it*8) = uh;
            *(uint4*)(opl + it*8) = ul;
        }
    }
}

// ---------------- fused exp/rowsum/normalize ctx GEMM -----------------------
// ctx[n][v] = (1/Σ_m e[n][m]) Σ_m e[n][m]·val[v][m],  e = exp(sim - rowmax)
// A-operand: single fp16 e (lo dropped; e∈(0,1], rel err ≤2^-12).
// M-tile 64, N = 256, K = TN. Stage (73728 B): Ah 8K | Bh 32K | Bl 32K.
// exp/STS for stage s+1 overlaps MMA of stage s (writes the idle buffer).
#define CTX_STAGE 73728u
__global__ void __launch_bounds__(256,1) gemm_ctx_fused(
    const __half* __restrict__ aH, const __half* __restrict__ aL,
    const __half* __restrict__ vh, const __half* __restrict__ vl,
    const u32* __restrict__ rmaxU,
    __half* __restrict__ ch, __half* __restrict__ cl)
{
    extern __shared__ char dsm[];
    const int tid = threadIdx.x, wid = tid>>5, lid = tid&31;
    const int z = blockIdx.z;
    const int n0 = blockIdx.x*64;
    const size_t abase = (size_t)z*TN*TN;
    const __half* vhb = vh + (size_t)z*256*TN;
    const __half* vlb = vl + (size_t)z*256*TN;
    const u32 sb = smem_u32(dsm);
    float* srow = (float*)(dsm + 2*CTX_STAGE);

    const int wm = wid>>2, wn = wid&3;
    const int lr = tid>>3, lc = tid&7;

    const float mx0 = fdec(rmaxU[(size_t)z*TN + n0 + lr]);
    const float mx1 = fdec(rmaxU[(size_t)z*TN + n0 + lr + 32]);
    const __half* pA0h = aH + abase + (size_t)(n0+lr)*TN + lc*8;
    const __half* pA0l = aL + abase + (size_t)(n0+lr)*TN + lc*8;
    const __half* pA1h = pA0h + (size_t)32*TN;
    const __half* pA1l = pA0l + (size_t)32*TN;

    float acc[2][8][4];
#pragma unroll
    for (int i=0;i<2;i++)
#pragma unroll
        for (int j=0;j<8;j++)
#pragma unroll
            for (int q=0;q<4;q++) acc[i][j][q] = 0.f;
    float s0 = 0.f, s1 = 0.f;

    const int S = TN/64;   // 144
    uint4 ra[4];
    auto ldgA = [&](int s){
        const int k0 = s<<6;
        ra[0] = *(const uint4*)(pA0h + k0);
        ra[1] = *(const uint4*)(pA0l + k0);
        ra[2] = *(const uint4*)(pA1h + k0);
        ra[3] = *(const uint4*)(pA1l + k0);
    };
    auto issueB = [&](int s){
        const int k0 = s<<6;
        const u32 bufo = (u32)(s&1)*CTX_STAGE;
#pragma unroll
        for (int arr=0; arr<2; arr++){
            const __half* gp = arr ? vlb : vhb;
            const u32 so = sb + bufo + 8192u + arr*32768u;
#pragma unroll
            for (int i=0;i<8;i++){
                const int row = lr + i*32;
                cpasync16(so + (u32)(row*128) + (u32)((lc ^ (row&7)) << 4),
                          gp + (size_t)row*TN + k0 + lc*8);
            }
        }
        CP_COMMIT();
    };
    auto exp8h = [&](uint4 uh4, uint4 ul4, float mxv, float& ssum)->uint4{
        const __half2* hp = (const __half2*)&uh4;
        const __half2* lp = (const __half2*)&ul4;
        __half2 ho[4];
#pragma unroll
        for (int q=0;q<4;q++){
            float e0 = __expf(__half2float(hp[q].x)+__half2float(lp[q].x) - mxv);
            float e1 = __expf(__half2float(hp[q].y)+__half2float(lp[q].y) - mxv);
            ssum += e0 + e1;
            ho[q] = __floats2half2_rn(e0, e1);
        }
        return *(uint4*)ho;
    };
    const int aoff = lr*128 + ((lc ^ (lr&7)) << 4);

    // prologue: exp/STS for stage 0 into buf0, start B pipeline
    ldgA(0);
    {
        uint4 h0 = exp8h(ra[0], ra[1], mx0, s0);
        uint4 h1 = exp8h(ra[2], ra[3], mx1, s1);
        *(uint4*)(dsm + aoff)        = h0;
        *(uint4*)(dsm + aoff + 4096) = h1;
    }
    issueB(0);

    for (int s=0; s<S; s++){
        if (s+1 < S) ldgA(s+1);
        CP_WAIT0();
        __syncthreads();
        if (s+1 < S) issueB(s+1);

        const u32 bufo = (u32)(s&1)*CTX_STAGE;
        const u32 bA = sb + bufo, bBh_ = sb + bufo + 8192u, bBl_ = sb + bufo + 40960u;
#pragma unroll
        for (int st=0; st<4; st++){
            u32 Ah[2][4], Bh[8][2], Bl[8][2];
            const int xa = ((st*2 + (lid>>4))    ^ (lid&7)) << 4;
            const int xb = ((st*2 + ((lid>>3)&1)) ^ (lid&7)) << 4;
#pragma unroll
            for (int i=0;i<2;i++){
                const u32 pr = (u32)((wm*32 + i*16 + (lid&15)) * 128);
                ldsm4(Ah[i][0],Ah[i][1],Ah[i][2],Ah[i][3], bA + pr + xa);
            }
#pragma unroll
            for (int j2=0; j2<4; j2++){
                const u32 pr = (u32)((wn*64 + j2*16 + (lid&7) + ((lid>>4)<<3)) * 128);
                u32 r0,r1,r2,r3;
                ldsm4(r0,r1,r2,r3, bBh_ + pr + xb);
                Bh[2*j2][0]=r0; Bh[2*j2][1]=r1; Bh[2*j2+1][0]=r2; Bh[2*j2+1][1]=r3;
                ldsm4(r0,r1,r2,r3, bBl_ + pr + xb);
                Bl[2*j2][0]=r0; Bl[2*j2][1]=r1; Bl[2*j2+1][0]=r2; Bl[2*j2+1][1]=r3;
            }
#pragma unroll
            for (int i=0;i<2;i++)
#pragma unroll
                for (int j=0;j<8;j++) mma16816(acc[i][j], Ah[i], Bh[j]);
#pragma unroll
            for (int i=0;i<2;i++)
#pragma unroll
                for (int j=0;j<8;j++) mma16816(acc[i][j], Ah[i], Bl[j]);
        }

        // overlap: exp+STS for stage s+1 into the idle buffer
        if (s+1 < S){
            const int off2 = (int)((u32)((s+1)&1)*CTX_STAGE) + aoff;
            uint4 h0 = exp8h(ra[0], ra[1], mx0, s0);
            uint4 h1 = exp8h(ra[2], ra[3], mx1, s1);
            *(uint4*)(dsm + off2)        = h0;
            *(uint4*)(dsm + off2 + 4096) = h1;
        }
    }

    // rowsum: reduce over the 8 lanes sharing each row
#pragma unroll
    for (int o=1;o<8;o<<=1){
        s0 += __shfl_xor_sync(0xffffffffu, s0, o);
        s1 += __shfl_xor_sync(0xffffffffu, s1, o);
    }
    __syncthreads();
    if ((tid&7)==0){ srow[lr] = s0; srow[lr+32] = s1; }
    __syncthreads();

    const int tr = lid>>2, tc2 = (lid&3)*2;
#pragma unroll
    for (int i=0;i<2;i++){
#pragma unroll
        for (int hh=0; hh<2; hh++){
            const int rowl = wm*32 + i*16 + tr + hh*8;
            const float inv = 1.0f / srow[rowl];
            const int row = n0 + rowl;
            __half* oph = ch + (size_t)z*TN*256 + (size_t)row*256 + wn*64;
            __half* opl = cl + (size_t)z*TN*256 + (size_t)row*256 + wn*64;
#pragma unroll
            for (int j=0;j<8;j++){
                const int col = j*8 + tc2;
                float v0 = acc[i][j][hh*2+0]*inv;
                float v1 = acc[i][j][hh*2+1]*inv;
                __half2 h2, l2;
                split2(v0, h2.x, l2.x); split2(v1, h2.y, l2.y);
                *(__half2*)(oph + col) = h2;
                *(__half2*)(opl + col) = l2;
            }
        }
    }
}

// ---------------- merged prep: all 4 weights in one launch -------------------
__global__ void prep_all(
    const float* __restrict__ wk, const float* __restrict__ bk,
    const float* __restrict__ g1, const float* __restrict__ b1,
    const float* __restrict__ m1, const float* __restrict__ v1,
    const float* __restrict__ wv,
    const float* __restrict__ wW,
    const float* __restrict__ wo, const float* __restrict__ bo,
    const float* __restrict__ g2, const float* __restrict__ b2,
    const float* __restrict__ m2, const float* __restrict__ v2,
    __half* __restrict__ wkh, __half* __restrict__ wkl, float* __restrict__ bkf,
    __half* __restrict__ wvh, __half* __restrict__ wvl,
    __half* __restrict__ wWh, __half* __restrict__ wWl,
    __half* __restrict__ woh, __half* __restrict__ wol, float* __restrict__ bof)
{
    const int o = blockIdx.x, which = blockIdx.y;
    if (which == 0){
        float s = g1[o] * rsqrtf(v1[o] + 1e-5f);
        for (int c = threadIdx.x; c < 512; c += blockDim.x){
            __half h, l; split2(wk[o*512 + c] * s, h, l);
            wkh[o*512 + c] = h; wkl[o*512 + c] = l;
        }
        if (threadIdx.x == 0) bkf[o] = bk[o]*s + b1[o] - m1[o]*s;
    } else if (which == 1){
        if (o < 256)
            for (int c = threadIdx.x; c < 512; c += blockDim.x){
                __half h, l; split2(wv[o*512 + c], h, l);
                wvh[o*512 + c] = h; wvl[o*512 + c] = l;
            }
    } else if (which == 2){
        for (int c = threadIdx.x; c < 256; c += blockDim.x){
            __half h, l; split2(wW[o*256 + c], h, l);
            wWh[o*256 + c] = h; wWl[o*256 + c] = l;
        }
    } else {
        float s = g2[o] * rsqrtf(v2[o] + 1e-5f);
        for (int c = threadIdx.x; c < 512; c += blockDim.x){
            __half h, l; split2(wo[o*512 + c] * s, h, l);
            woh[o*512 + c] = h; wol[o*512 + c] = l;
        }
        if (threadIdx.x == 0) bof[o] = bo[o]*s + b2[o] - m2[o]*s;
    }
}

__global__ void init_rmax(u32* r){
    int t = blockIdx.x*256 + threadIdx.x;
    if (t < NB*TN) r[t] = 0u;
}

__global__ void conv_x(const float* __restrict__ x, __half* __restrict__ xh, __half* __restrict__ xl)
{
    __shared__ float t[32][33];
    const int z = blockIdx.z;
    const float* xb = x + (size_t)z*512*TN;
    const int n0 = blockIdx.x*32, c0 = blockIdx.y*32;
    const int tx = threadIdx.x, ty = threadIdx.y;
#pragma unroll
    for (int i=0;i<4;i++)
        t[ty + i*8][tx] = xb[(size_t)(c0 + ty + i*8)*TN + n0 + tx];
    __syncthreads();
#pragma unroll
    for (int i=0;i<4;i++){
        int n = n0 + ty + i*8, c = c0 + tx;
        __half h, l; split2(t[tx][ty + i*8], h, l);
        size_t o = ((size_t)z*TN + n)*512 + c;
        xh[o] = h; xl[o] = l;
    }
}

// ---------------- launch ----------------------------------------------------
#define DSMEM     131072
#define DSMEM_CTX (2*73728 + 256)

extern "C" void kernel_launch(void* const* d_in, const int* in_sizes, int n_in,
                              void* d_out, int out_size)
{
    const float* x  = (const float*)d_in[0];
    const float* wk = (const float*)d_in[1];
    const float* bk = (const float*)d_in[2];
    const float* g1 = (const float*)d_in[3];
    const float* b1 = (const float*)d_in[4];
    const float* m1 = (const float*)d_in[5];
    const float* v1 = (const float*)d_in[6];
    const float* wv = (const float*)d_in[7];
    const float* bv = (const float*)d_in[8];
    const float* wW = (const float*)d_in[9];
    const float* bW = (const float*)d_in[10];
    const float* wo = (const float*)d_in[11];
    const float* bo = (const float*)d_in[12];
    const float* g2 = (const float*)d_in[13];
    const float* b2 = (const float*)d_in[14];
    const float* m2 = (const float*)d_in[15];
    const float* v2 = (const float*)d_in[16];
    float* out = (float*)d_out;

    cudaFuncSetAttribute(gemm_tc,        cudaFuncAttributeMaxDynamicSharedMemorySize, DSMEM);
    cudaFuncSetAttribute(gemm_sym,       cudaFuncAttributeMaxDynamicSharedMemorySize, DSMEM);
    cudaFuncSetAttribute(gemm_ctx_fused, cudaFuncAttributeMaxDynamicSharedMemorySize, DSMEM_CTX);

    __half *xh,*xl,*kh,*kl,*vh,*vl,*aH,*aL,*ch,*cl,*c2h,*c2l;
    __half *wkh,*wkl,*wvh,*wvl,*wWh,*wWl,*woh,*wol;
    float *bkf,*bof; u32 *rmx;
    cudaGetSymbolAddress((void**)&xh, g_xh);   cudaGetSymbolAddress((void**)&xl, g_xl);
    cudaGetSymbolAddress((void**)&kh, g_kh);   cudaGetSymbolAddress((void**)&kl, g_kl);
    cudaGetSymbolAddress((void**)&vh, g_vh);   cudaGetSymbolAddress((void**)&vl, g_vl);
    cudaGetSymbolAddress((void**)&aH, g_ahh);  cudaGetSymbolAddress((void**)&aL, g_all);
    cudaGetSymbolAddress((void**)&ch, g_ch);   cudaGetSymbolAddress((void**)&cl, g_cl);
    cudaGetSymbolAddress((void**)&c2h, g_c2h); cudaGetSymbolAddress((void**)&c2l, g_c2l);
    cudaGetSymbolAddress((void**)&wkh, g_wkh); cudaGetSymbolAddress((void**)&wkl, g_wkl);
    cudaGetSymbolAddress((void**)&wvh, g_wvh); cudaGetSymbolAddress((void**)&wvl, g_wvl);
    cudaGetSymbolAddress((void**)&wWh, g_wWh); cudaGetSymbolAddress((void**)&wWl, g_wWl);
    cudaGetSymbolAddress((void**)&woh, g_woh); cudaGetSymbolAddress((void**)&wol, g_wol);
    cudaGetSymbolAddress((void**)&bkf, g_bkf); cudaGetSymbolAddress((void**)&bof, g_bof);
    cudaGetSymbolAddress((void**)&rmx, g_rmax);

    // launches 0-2: prep (merged), transpose, init
    prep_all<<<dim3(512,4), 256>>>(wk, bk, g1, b1, m1, v1, wv, wW, wo, bo, g2, b2, m2, v2,
                                   wkh, wkl, bkf, wvh, wvl, wWh, wWl, woh, wol, bof);
    conv_x<<<dim3(TN/32, 16, NB), dim3(32,8)>>>(x, xh, xl);
    init_rmax<<<(NB*TN + 255)/256, 256>>>(rmx);

    // 3: k_t[n][cout] = relu(Wk_f x + bk_f)
    gemm_tc<<<dim3(72,4,NB), 256, DSMEM>>>(xh, xl, (size_t)TN*512, 512,
        wkh, wkl, 0, 512, 512, F_BCOL|F_RELU, bkf, 1.f,
        kh, kl, nullptr, (size_t)TN*512, 512);
    // 4: val[v][n] = Wv x + bv
    gemm_tc<<<dim3(2,72,NB), 256, DSMEM>>>(wvh, wvl, 0, 512,
        xh, xl, (size_t)TN*512, 512, 512, F_BROW, bv, 1.f,
        vh, vl, nullptr, (size_t)256*TN, TN);
    // 5: sim (symmetric) — ncu -s 5 -c 1 lands here
    gemm_sym<<<dim3(2628,1,NB), 256, DSMEM>>>(kh, kl, 0.0441941738241592f, aH, aL, rmx);
    // 6: ctx with fused exp/rowsum/normalize
    gemm_ctx_fused<<<dim3(TN/64,1,NB), 256, DSMEM_CTX>>>(aH, aL, vh, vl, rmx, ch, cl);
    // 7: ctx2[n][co] = wW ctx + bW
    gemm_tc<<<dim3(72,4,NB), 256, DSMEM>>>(ch, cl, (size_t)TN*256, 256,
        wWh, wWl, 0, 256, 256, F_BCOL, bW, 1.f,
        c2h, c2l, nullptr, (size_t)TN*512, 512);
    // 8: out[co][n] = relu(wo_f ctx2 + bo_f), fp32
    gemm_tc<<<dim3(4,72,NB), 256, DSMEM>>>(woh, wol, 0, 512,
        c2h, c2l, (size_t)TN*512, 512, 512, F_BROW|F_RELU|F_F32, bof, 1.f,
        nullptr, nullptr, out, (size_t)512*TN, TN);
}

// round 8
// speedup vs baseline: 3.5390x; 1.1200x over previous
#include <cuda_runtime.h>
#include <cuda_fp16.h>
#include <math.h>
#include <stdint.h>

#define TN 9216
#define NB 2
typedef unsigned int u32;
typedef unsigned long long u64;

#define F_RELU   1
#define F_BROW   2
#define F_BCOL   4
#define F_F32    16

// ---------------- scratch (static device arrays; no cudaMalloc allowed) ----
__device__ __half g_xh[(size_t)NB*TN*512],  g_xl[(size_t)NB*TN*512];
__device__ __half g_kh[(size_t)NB*TN*512],  g_kl[(size_t)NB*TN*512];
__device__ __half g_vh[(size_t)NB*256*TN],  g_vl[(size_t)NB*256*TN];
__device__ __half g_ahh[(size_t)NB*TN*TN],  g_all[(size_t)NB*TN*TN];
__device__ __half g_ch[(size_t)NB*TN*256],  g_cl[(size_t)NB*TN*256];
__device__ __half g_c2h[(size_t)NB*TN*512], g_c2l[(size_t)NB*TN*512];
__device__ __half g_wkh[512*512], g_wkl[512*512];
__device__ __half g_wvh[256*512], g_wvl[256*512];
__device__ __half g_wWh[512*256], g_wWl[512*256];
__device__ __half g_woh[512*512], g_wol[512*512];
__device__ float g_bkf[512], g_bof[512];
__device__ u32   g_rmax[NB*TN];

// ---------------- helpers ----------------------------------------------------
static __device__ __forceinline__ u32 smem_u32(const void* p){
    u32 a;
    asm("{ .reg .u64 t; cvta.to.shared.u64 t, %1; cvt.u32.u64 %0, t; }" : "=r"(a) : "l"(p));
    return a;
}
static __device__ __forceinline__ void cpasync16(u32 s, const void* g){
    asm volatile("cp.async.cg.shared.global [%0], [%1], 16;" :: "r"(s), "l"(g) : "memory");
}
#define CP_COMMIT() asm volatile("cp.async.commit_group;" ::: "memory")
#define CP_WAIT0()  asm volatile("cp.async.wait_group 0;" ::: "memory")
#define CP_WAIT1()  asm volatile("cp.async.wait_group 1;" ::: "memory")

static __device__ __forceinline__ void ldsm4(u32& r0, u32& r1, u32& r2, u32& r3, u32 a){
    asm volatile("ldmatrix.sync.aligned.m8n8.x4.shared.b16 {%0,%1,%2,%3}, [%4];"
                 : "=r"(r0), "=r"(r1), "=r"(r2), "=r"(r3) : "r"(a));
}
static __device__ __forceinline__ void mma16816(float* d, const u32* a, const u32* b){
    asm volatile("mma.sync.aligned.m16n8k16.row.col.f32.f16.f16.f32 "
                 "{%0,%1,%2,%3}, {%4,%5,%6,%7}, {%8,%9}, {%0,%1,%2,%3};"
                 : "+f"(d[0]), "+f"(d[1]), "+f"(d[2]), "+f"(d[3])
                 : "r"(a[0]), "r"(a[1]), "r"(a[2]), "r"(a[3]), "r"(b[0]), "r"(b[1]));
}
static __device__ __forceinline__ void split2(float v, __half& h, __half& l){
    h = __float2half_rn(v);
    l = __float2half_rn(v - __half2float(h));
}
static __device__ __forceinline__ u32 fenc(float f){
    u32 u = __float_as_uint(f);
    return (u & 0x80000000u) ? ~u : (u | 0x80000000u);
}
static __device__ __forceinline__ float fdec(u32 u){
    return (u & 0x80000000u) ? __uint_as_float(u ^ 0x80000000u) : __uint_as_float(~u);
}

// ---------------- generic split-fp16 tensor GEMM (3-stage pipeline) ----------
__global__ void __launch_bounds__(256,1) gemm_tc(
    const __half* __restrict__ ah, const __half* __restrict__ al, size_t a_bs, int lda,
    const __half* __restrict__ bh, const __half* __restrict__ bl, size_t b_bs, int ldb,
    int K, int flags, const float* __restrict__ bias,
    float scale, __half* oh, __half* ol, float* of, size_t o_bs, int ldo)
{
    extern __shared__ char dsm[];
    const int tid = threadIdx.x, wid = tid>>5, lid = tid&31;
    const int m0 = blockIdx.x*128, n0 = blockIdx.y*128, z = blockIdx.z;
    ah += (size_t)z*a_bs; al += (size_t)z*a_bs;
    bh += (size_t)z*b_bs; bl += (size_t)z*b_bs;
    const int wm = wid>>2, wn = wid&3;
    const u32 sb = smem_u32(dsm);
    const int lrow = tid>>3, lc = tid&7;
    const __half* gpA[2] = {ah, al};
    const __half* gpB[2] = {bh, bl};

    float acc[4][4][4];
#pragma unroll
    for (int i=0;i<4;i++)
#pragma unroll
        for (int j=0;j<4;j++)
#pragma unroll
            for (int q=0;q<4;q++) acc[i][j][q] = 0.f;

    const int S = K >> 6;
    auto issue = [&](int s){
        const int k0 = s << 6;
        const u32 bufo = (u32)(s % 3) * 65536u;
#pragma unroll
        for (int arr=0; arr<4; arr++){
            const __half* gp = (arr<2) ? gpA[arr] : gpB[arr-2];
            const int rb = (arr<2) ? m0 : n0;
            const int ld = (arr<2) ? lda : ldb;
            const u32 so = sb + bufo + arr*16384u;
#pragma unroll
            for (int i=0;i<4;i++){
                const int row = lrow + i*32;
                const void* g = gp + (size_t)(rb+row)*ld + k0 + lc*8;
                const u32 sa = so + (u32)(row*128) + (u32)((lc ^ (row&7)) << 4);
                cpasync16(sa, g);
            }
        }
        CP_COMMIT();
    };

    issue(0);
    issue(1);
    for (int s=0; s<S; s++){
        if (s+1 < S) { CP_WAIT1(); } else { CP_WAIT0(); }
        __syncthreads();
        if (s+2 < S) issue(s+2);
        const u32 bufo = (u32)(s % 3) * 65536u;
        const u32 bAh = sb+bufo, bAl = sb+bufo+16384u, bBh = sb+bufo+32768u, bBl = sb+bufo+49152u;
        const int prA = (wm*64 + (lid&15)) * 128;
        const int prB0 = (wn*32 +      (lid&7) + ((lid>>4)<<3)) * 128;
        const int prB1 = (wn*32 + 16 + (lid&7) + ((lid>>4)<<3)) * 128;
#pragma unroll
        for (int st=0; st<4; st++){
            u32 Ah[4][4], Al[4][4], Bh[4][2], Bl[4][2];
            const int xa = ((st*2 + (lid>>4))    ^ (lid&7)) << 4;
            const int xb = ((st*2 + ((lid>>3)&1)) ^ (lid&7)) << 4;
#pragma unroll
            for (int i=0;i<4;i++){
                ldsm4(Ah[i][0],Ah[i][1],Ah[i][2],Ah[i][3], bAh + prA + i*2048 + xa);
                ldsm4(Al[i][0],Al[i][1],Al[i][2],Al[i][3], bAl + prA + i*2048 + xa);
            }
            {
                u32 r0,r1,r2,r3;
                ldsm4(r0,r1,r2,r3, bBh + prB0 + xb);
                Bh[0][0]=r0; Bh[0][1]=r1; Bh[1][0]=r2; Bh[1][1]=r3;
                ldsm4(r0,r1,r2,r3, bBh + prB1 + xb);
                Bh[2][0]=r0; Bh[2][1]=r1; Bh[3][0]=r2; Bh[3][1]=r3;
                ldsm4(r0,r1,r2,r3, bBl + prB0 + xb);
                Bl[0][0]=r0; Bl[0][1]=r1; Bl[1][0]=r2; Bl[1][1]=r3;
                ldsm4(r0,r1,r2,r3, bBl + prB1 + xb);
                Bl[2][0]=r0; Bl[2][1]=r1; Bl[3][0]=r2; Bl[3][1]=r3;
            }
#pragma unroll
            for (int i=0;i<4;i++)
#pragma unroll
                for (int j=0;j<4;j++) mma16816(acc[i][j], Ah[i], Bh[j]);
#pragma unroll
            for (int i=0;i<4;i++)
#pragma unroll
                for (int j=0;j<4;j++) mma16816(acc[i][j], Ah[i], Bl[j]);
#pragma unroll
            for (int i=0;i<4;i++)
#pragma unroll
                for (int j=0;j<4;j++) mma16816(acc[i][j], Al[i], Bh[j]);
        }
    }

    const int tr = lid>>2, tc = (lid&3)*2;
    const int mBase = m0 + wm*64, nBase = n0 + wn*32;
#pragma unroll
    for (int i=0;i<4;i++){
#pragma unroll
        for (int hh=0; hh<2; hh++){
            const int row = mBase + i*16 + tr + hh*8;
            float brow = (flags & F_BROW) ? bias[row] : 0.f;
            if (flags & F_F32){
                float* op = of + (size_t)z*o_bs + (size_t)row*ldo;
#pragma unroll
                for (int j=0;j<4;j++){
                    const int n = nBase + j*8 + tc;
                    float v0 = acc[i][j][hh*2+0]*scale + brow;
                    float v1 = acc[i][j][hh*2+1]*scale + brow;
                    if (flags & F_BCOL){ v0 += bias[n]; v1 += bias[n+1]; }
                    if (flags & F_RELU){ v0 = fmaxf(v0,0.f); v1 = fmaxf(v1,0.f); }
                    float2 w; w.x = v0; w.y = v1;
                    *(float2*)(op + n) = w;
                }
            } else {
                __half* oph = oh + (size_t)z*o_bs + (size_t)row*ldo;
                __half* opl = ol + (size_t)z*o_bs + (size_t)row*ldo;
#pragma unroll
                for (int j=0;j<4;j++){
                    const int n = nBase + j*8 + tc;
                    float v0 = acc[i][j][hh*2+0]*scale + brow;
                    float v1 = acc[i][j][hh*2+1]*scale + brow;
                    if (flags & F_BCOL){ v0 += bias[n]; v1 += bias[n+1]; }
                    if (flags & F_RELU){ v0 = fmaxf(v0,0.f); v1 = fmaxf(v1,0.f); }
                    __half2 h2, l2;
                    split2(v0, h2.x, l2.x); split2(v1, h2.y, l2.y);
                    *(__half2*)(oph + n) = h2;
                    *(__half2*)(opl + n) = l2;
                }
            }
        }
    }
}

// ---------------- symmetric sim GEMM (3-stage), mirrored writes --------------
__global__ void __launch_bounds__(256,1) gemm_sym(
    const __half* __restrict__ kh, const __half* __restrict__ kl,
    float scale, __half* __restrict__ aH, __half* __restrict__ aL,
    u32* __restrict__ rmaxU)
{
    extern __shared__ char dsm[];
    const int tid = threadIdx.x, wid = tid>>5, lid = tid&31;
    const int z = blockIdx.z;
    const int t = blockIdx.x;
    int i = (int)((145.0f - sqrtf(21025.0f - 8.0f*(float)t)) * 0.5f);
    while (i > 0 && i*72 - i*(i-1)/2 > t) i--;
    while ((i+1)*72 - (i+1)*i/2 <= t) i++;
    const int j = i + (t - (i*72 - i*(i-1)/2));
    const int m0 = i*128, n0 = j*128;

    const __half* ah = kh + (size_t)z*TN*512;
    const __half* al = kl + (size_t)z*TN*512;
    const int wm = wid>>2, wn = wid&3;
    const u32 sb = smem_u32(dsm);
    const int lrow = tid>>3, lc = tid&7;
    const __half* gp2[2] = {ah, al};

    float acc[4][4][4];
#pragma unroll
    for (int a=0;a<4;a++)
#pragma unroll
        for (int b=0;b<4;b++)
#pragma unroll
            for (int q=0;q<4;q++) acc[a][b][q] = 0.f;

    auto issue = [&](int s){
        const int k0 = s << 6;
        const u32 bufo = (u32)(s % 3) * 65536u;
#pragma unroll
        for (int arr=0; arr<4; arr++){
            const __half* gp = gp2[arr & 1];
            const int rb = (arr<2) ? m0 : n0;
            const u32 so = sb + bufo + arr*16384u;
#pragma unroll
            for (int q=0;q<4;q++){
                const int row = lrow + q*32;
                const void* g = gp + (size_t)(rb+row)*512 + k0 + lc*8;
                const u32 sa = so + (u32)(row*128) + (u32)((lc ^ (row&7)) << 4);
                cpasync16(sa, g);
            }
        }
        CP_COMMIT();
    };

    issue(0);
    issue(1);
    for (int s=0; s<8; s++){
        if (s+1 < 8) { CP_WAIT1(); } else { CP_WAIT0(); }
        __syncthreads();
        if (s+2 < 8) issue(s+2);
        const u32 bufo = (u32)(s % 3) * 65536u;
        const u32 bAh = sb+bufo, bAl = sb+bufo+16384u, bBh = sb+bufo+32768u, bBl = sb+bufo+49152u;
        const int prA = (wm*64 + (lid&15)) * 128;
        const int prB0 = (wn*32 +      (lid&7) + ((lid>>4)<<3)) * 128;
        const int prB1 = (wn*32 + 16 + (lid&7) + ((lid>>4)<<3)) * 128;
#pragma unroll
        for (int st=0; st<4; st++){
            u32 Ah[4][4], Al[4][4], Bh[4][2], Bl[4][2];
            const int xa = ((st*2 + (lid>>4))    ^ (lid&7)) << 4;
            const int xb = ((st*2 + ((lid>>3)&1)) ^ (lid&7)) << 4;
#pragma unroll
            for (int a=0;a<4;a++){
                ldsm4(Ah[a][0],Ah[a][1],Ah[a][2],Ah[a][3], bAh + prA + a*2048 + xa);
                ldsm4(Al[a][0],Al[a][1],Al[a][2],Al[a][3], bAl + prA + a*2048 + xa);
            }
            {
                u32 r0,r1,r2,r3;
                ldsm4(r0,r1,r2,r3, bBh + prB0 + xb);
                Bh[0][0]=r0; Bh[0][1]=r1; Bh[1][0]=r2; Bh[1][1]=r3;
                ldsm4(r0,r1,r2,r3, bBh + prB1 + xb);
                Bh[2][0]=r0; Bh[2][1]=r1; Bh[3][0]=r2; Bh[3][1]=r3;
                ldsm4(r0,r1,r2,r3, bBl + prB0 + xb);
                Bl[0][0]=r0; Bl[0][1]=r1; Bl[1][0]=r2; Bl[1][1]=r3;
                ldsm4(r0,r1,r2,r3, bBl + prB1 + xb);
                Bl[2][0]=r0; Bl[2][1]=r1; Bl[3][0]=r2; Bl[3][1]=r3;
            }
#pragma unroll
            for (int a=0;a<4;a++)
#pragma unroll
                for (int b=0;b<4;b++) mma16816(acc[a][b], Ah[a], Bh[b]);
#pragma unroll
            for (int a=0;a<4;a++)
#pragma unroll
                for (int b=0;b<4;b++) mma16816(acc[a][b], Ah[a], Bl[b]);
#pragma unroll
            for (int a=0;a<4;a++)
#pragma unroll
                for (int b=0;b<4;b++) mma16816(acc[a][b], Al[a], Bh[b]);
        }
    }

    __syncthreads();
    float* Sm = (float*)dsm;
    float* P  = Sm + 128*129;
    const int tr = lid>>2, tc = (lid&3)*2;
#pragma unroll
    for (int a=0;a<4;a++)
#pragma unroll
        for (int hh=0; hh<2; hh++){
            const int rl = wm*64 + a*16 + tr + hh*8;
#pragma unroll
            for (int b=0;b<4;b++){
                const int cl = wn*32 + b*8 + tc;
                Sm[rl*129 + cl]     = acc[a][b][hh*2+0]*scale;
                Sm[rl*129 + cl + 1] = acc[a][b][hh*2+1]*scale;
            }
        }
    __syncthreads();

    const int rr = tid & 127, hf2 = tid >> 7;
    {
        float m = -1e30f;
        for (int c=0;c<64;c++) m = fmaxf(m, Sm[rr*129 + hf2*64 + c]);
        P[rr*2 + hf2] = m;
    }
    __syncthreads();
    if (tid < 128) atomicMax(&rmaxU[(size_t)z*TN + m0 + tid], fenc(fmaxf(P[tid*2], P[tid*2+1])));
    __syncthreads();
    {
        float m = -1e30f;
        for (int r2=0;r2<64;r2++) m = fmaxf(m, Sm[(hf2*64 + r2)*129 + rr]);
        P[rr*2 + hf2] = m;
    }
    __syncthreads();
    if (tid < 128) atomicMax(&rmaxU[(size_t)z*TN + n0 + tid], fenc(fmaxf(P[tid*2], P[tid*2+1])));

    const size_t obase = (size_t)z*TN*TN;
    {
        const int r = tid>>1, c0 = (tid&1)*64;
        __half* oph = aH + obase + (size_t)(m0 + r)*TN + n0 + c0;
        __half* opl = aL + obase + (size_t)(m0 + r)*TN + n0 + c0;
        const float* Sr = Sm + r*129 + c0;
#pragma unroll
        for (int it=0; it<8; it++){
            __half2 hx[4], lx[4];
#pragma unroll
            for (int q=0;q<4;q++){
                split2(Sr[it*8 + 2*q],     hx[q].x, lx[q].x);
                split2(Sr[it*8 + 2*q + 1], hx[q].y, lx[q].y);
            }
            uint4 uh, ul;
            uh.x=*(u32*)&hx[0]; uh.y=*(u32*)&hx[1]; uh.z=*(u32*)&hx[2]; uh.w=*(u32*)&hx[3];
            ul.x=*(u32*)&lx[0]; ul.y=*(u32*)&lx[1]; ul.z=*(u32*)&lx[2]; ul.w=*(u32*)&lx[3];
            *(uint4*)(oph + it*8) = uh;
            *(uint4*)(opl + it*8) = ul;
        }
    }
    if (i != j){
        const int c = tid>>1, r0 = (tid&1)*64;
        __half* oph = aH + obase + (size_t)(n0 + c)*TN + m0 + r0;
        __half* opl = aL + obase + (size_t)(n0 + c)*TN + m0 + r0;
#pragma unroll
        for (int it=0; it<8; it++){
            __half2 hx[4], lx[4];
#pragma unroll
            for (int q=0;q<4;q++){
                float f0 = Sm[(r0 + it*8 + 2*q    )*129 + c];
                float f1 = Sm[(r0 + it*8 + 2*q + 1)*129 + c];
                split2(f0, hx[q].x, lx[q].x);
                split2(f1, hx[q].y, lx[q].y);
            }
            uint4 uh, ul;
            uh.x=*(u32*)&hx[0]; uh.y=*(u32*)&hx[1]; uh.z=*(u32*)&hx[2]; uh.w=*(u32*)&hx[3];
            ul.x=*(u32*)&lx[0]; ul.y=*(u32*)&lx[1]; ul.z=*(u32*)&lx[2]; ul.w=*(u32*)&lx[3];
            *(uint4*)(oph + it*8) = uh;
            *(uint4*)(opl + it*8) = ul;
        }
    }
}

// ---------------- fused exp/rowsum/normalize ctx GEMM (1-pass, 3-stage) ------
// ctx[n][v] = (1/Σe) Σ e[n][m]·valh[v][m], e = fp16(exp(sim-rowmax)), val lo dropped.
// Stage (40960 B): A 8K | Bh 32K. 3 stages + srow.
#define CTX_STAGE 40960u
__global__ void __launch_bounds__(256,1) gemm_ctx_fused(
    const __half* __restrict__ aH, const __half* __restrict__ aL,
    const __half* __restrict__ vh,
    const u32* __restrict__ rmaxU,
    __half* __restrict__ ch, __half* __restrict__ cl)
{
    extern __shared__ char dsm[];
    const int tid = threadIdx.x, wid = tid>>5, lid = tid&31;
    const int z = blockIdx.z;
    const int n0 = blockIdx.x*64;
    const size_t abase = (size_t)z*TN*TN;
    const __half* vhb = vh + (size_t)z*256*TN;
    const u32 sb = smem_u32(dsm);
    float* srow = (float*)(dsm + 3*CTX_STAGE);

    const int wm = wid>>2, wn = wid&3;
    const int lr = tid>>3, lc = tid&7;

    const float mx0 = fdec(rmaxU[(size_t)z*TN + n0 + lr]);
    const float mx1 = fdec(rmaxU[(size_t)z*TN + n0 + lr + 32]);
    const __half* pA0h = aH + abase + (size_t)(n0+lr)*TN + lc*8;
    const __half* pA0l = aL + abase + (size_t)(n0+lr)*TN + lc*8;
    const __half* pA1h = pA0h + (size_t)32*TN;
    const __half* pA1l = pA0l + (size_t)32*TN;

    float acc[2][8][4];
#pragma unroll
    for (int i=0;i<2;i++)
#pragma unroll
        for (int j=0;j<8;j++)
#pragma unroll
            for (int q=0;q<4;q++) acc[i][j][q] = 0.f;
    float s0 = 0.f, s1 = 0.f;

    const int S = TN/64;   // 144
    uint4 ra[4];
    auto ldgA = [&](int s){
        const int k0 = s<<6;
        ra[0] = *(const uint4*)(pA0h + k0);
        ra[1] = *(const uint4*)(pA0l + k0);
        ra[2] = *(const uint4*)(pA1h + k0);
        ra[3] = *(const uint4*)(pA1l + k0);
    };
    auto issueB = [&](int s){
        const int k0 = s<<6;
        const u32 so = sb + (u32)(s%3)*CTX_STAGE + 8192u;
#pragma unroll
        for (int i=0;i<8;i++){
            const int row = lr + i*32;
            cpasync16(so + (u32)(row*128) + (u32)((lc ^ (row&7)) << 4),
                      vhb + (size_t)row*TN + k0 + lc*8);
        }
        CP_COMMIT();
    };
    auto exp8h = [&](uint4 uh4, uint4 ul4, float mxv, float& ssum)->uint4{
        const __half2* hp = (const __half2*)&uh4;
        const __half2* lp = (const __half2*)&ul4;
        __half2 ho[4];
#pragma unroll
        for (int q=0;q<4;q++){
            float e0 = __expf(__half2float(hp[q].x)+__half2float(lp[q].x) - mxv);
            float e1 = __expf(__half2float(hp[q].y)+__half2float(lp[q].y) - mxv);
            ssum += e0 + e1;
            ho[q] = __floats2half2_rn(e0, e1);
        }
        return *(uint4*)ho;
    };
    const int aoff = lr*128 + ((lc ^ (lr&7)) << 4);

    // prologue: A exp for stage 0 into buf0; B stages 0,1 in flight
    ldgA(0);
    {
        uint4 h0 = exp8h(ra[0], ra[1], mx0, s0);
        uint4 h1 = exp8h(ra[2], ra[3], mx1, s1);
        *(uint4*)(dsm + aoff)        = h0;
        *(uint4*)(dsm + aoff + 4096) = h1;
    }
    issueB(0);
    issueB(1);

    for (int s=0; s<S; s++){
        if (s+1 < S) ldgA(s+1);
        if (s+1 < S) { CP_WAIT1(); } else { CP_WAIT0(); }
        __syncthreads();
        if (s+2 < S) issueB(s+2);

        const u32 bufo = (u32)(s%3)*CTX_STAGE;
        const u32 bA = sb + bufo, bB = sb + bufo + 8192u;
#pragma unroll
        for (int st=0; st<4; st++){
            u32 Ah[2][4], Bh[8][2];
            const int xa = ((st*2 + (lid>>4))    ^ (lid&7)) << 4;
            const int xb = ((st*2 + ((lid>>3)&1)) ^ (lid&7)) << 4;
#pragma unroll
            for (int i=0;i<2;i++){
                const u32 pr = (u32)((wm*32 + i*16 + (lid&15)) * 128);
                ldsm4(Ah[i][0],Ah[i][1],Ah[i][2],Ah[i][3], bA + pr + xa);
            }
#pragma unroll
            for (int j2=0; j2<4; j2++){
                const u32 pr = (u32)((wn*64 + j2*16 + (lid&7) + ((lid>>4)<<3)) * 128);
                u32 r0,r1,r2,r3;
                ldsm4(r0,r1,r2,r3, bB + pr + xb);
                Bh[2*j2][0]=r0; Bh[2*j2][1]=r1; Bh[2*j2+1][0]=r2; Bh[2*j2+1][1]=r3;
            }
#pragma unroll
            for (int i=0;i<2;i++)
#pragma unroll
                for (int j=0;j<8;j++) mma16816(acc[i][j], Ah[i], Bh[j]);
        }

        // overlap: exp+STS for stage s+1 into its buffer
        if (s+1 < S){
            const int off2 = (int)((u32)((s+1)%3)*CTX_STAGE) + aoff;
            uint4 h0 = exp8h(ra[0], ra[1], mx0, s0);
            uint4 h1 = exp8h(ra[2], ra[3], mx1, s1);
            *(uint4*)(dsm + off2)        = h0;
            *(uint4*)(dsm + off2 + 4096) = h1;
        }
    }

    // rowsum: reduce over the 8 lanes sharing each row
#pragma unroll
    for (int o=1;o<8;o<<=1){
        s0 += __shfl_xor_sync(0xffffffffu, s0, o);
        s1 += __shfl_xor_sync(0xffffffffu, s1, o);
    }
    __syncthreads();
    if ((tid&7)==0){ srow[lr] = s0; srow[lr+32] = s1; }
    __syncthreads();

    const int tr = lid>>2, tc2 = (lid&3)*2;
#pragma unroll
    for (int i=0;i<2;i++){
#pragma unroll
        for (int hh=0; hh<2; hh++){
            const int rowl = wm*32 + i*16 + tr + hh*8;
            const float inv = 1.0f / srow[rowl];
            const int row = n0 + rowl;
            __half* oph = ch + (size_t)z*TN*256 + (size_t)row*256 + wn*64;
            __half* opl = cl + (size_t)z*TN*256 + (size_t)row*256 + wn*64;
#pragma unroll
            for (int j=0;j<8;j++){
                const int col = j*8 + tc2;
                float v0 = acc[i][j][hh*2+0]*inv;
                float v1 = acc[i][j][hh*2+1]*inv;
                __half2 h2, l2;
                split2(v0, h2.x, l2.x); split2(v1, h2.y, l2.y);
                *(__half2*)(oph + col) = h2;
                *(__half2*)(opl + col) = l2;
            }
        }
    }
}

// ---------------- merged prep: all 4 weights in one launch -------------------
__global__ void prep_all(
    const float* __restrict__ wk, const float* __restrict__ bk,
    const float* __restrict__ g1, const float* __restrict__ b1,
    const float* __restrict__ m1, const float* __restrict__ v1,
    const float* __restrict__ wv,
    const float* __restrict__ wW,
    const float* __restrict__ wo, const float* __restrict__ bo,
    const float* __restrict__ g2, const float* __restrict__ b2,
    const float* __restrict__ m2, const float* __restrict__ v2,
    __half* __restrict__ wkh, __half* __restrict__ wkl, float* __restrict__ bkf,
    __half* __restrict__ wvh, __half* __restrict__ wvl,
    __half* __restrict__ wWh, __half* __restrict__ wWl,
    __half* __restrict__ woh, __half* __restrict__ wol, float* __restrict__ bof)
{
    const int o = blockIdx.x, which = blockIdx.y;
    if (which == 0){
        float s = g1[o] * rsqrtf(v1[o] + 1e-5f);
        for (int c = threadIdx.x; c < 512; c += blockDim.x){
            __half h, l; split2(wk[o*512 + c] * s, h, l);
            wkh[o*512 + c] = h; wkl[o*512 + c] = l;
        }
        if (threadIdx.x == 0) bkf[o] = bk[o]*s + b1[o] - m1[o]*s;
    } else if (which == 1){
        if (o < 256)
            for (int c = threadIdx.x; c < 512; c += blockDim.x){
                __half h, l; split2(wv[o*512 + c], h, l);
                wvh[o*512 + c] = h; wvl[o*512 + c] = l;
            }
    } else if (which == 2){
        for (int c = threadIdx.x; c < 256; c += blockDim.x){
            __half h, l; split2(wW[o*256 + c], h, l);
            wWh[o*256 + c] = h; wWl[o*256 + c] = l;
        }
    } else {
        float s = g2[o] * rsqrtf(v2[o] + 1e-5f);
        for (int c = threadIdx.x; c < 512; c += blockDim.x){
            __half h, l; split2(wo[o*512 + c] * s, h, l);
            woh[o*512 + c] = h; wol[o*512 + c] = l;
        }
        if (threadIdx.x == 0) bof[o] = bo[o]*s + b2[o] - m2[o]*s;
    }
}

__global__ void init_rmax(u32* r){
    int t = blockIdx.x*256 + threadIdx.x;
    if (t < NB*TN) r[t] = 0u;
}

__global__ void conv_x(const float* __restrict__ x, __half* __restrict__ xh, __half* __restrict__ xl)
{
    __shared__ float t[32][33];
    const int z = blockIdx.z;
    const float* xb = x + (size_t)z*512*TN;
    const int n0 = blockIdx.x*32, c0 = blockIdx.y*32;
    const int tx = threadIdx.x, ty = threadIdx.y;
#pragma unroll
    for (int i=0;i<4;i++)
        t[ty + i*8][tx] = xb[(size_t)(c0 + ty + i*8)*TN + n0 + tx];
    __syncthreads();
#pragma unroll
    for (int i=0;i<4;i++){
        int n = n0 + ty + i*8, c = c0 + tx;
        __half h, l; split2(t[tx][ty + i*8], h, l);
        size_t o = ((size_t)z*TN + n)*512 + c;
        xh[o] = h; xl[o] = l;
    }
}

// ---------------- launch ----------------------------------------------------
#define DSMEM     196608
#define DSMEM_CTX (3*40960 + 256)

extern "C" void kernel_launch(void* const* d_in, const int* in_sizes, int n_in,
                              void* d_out, int out_size)
{
    const float* x  = (const float*)d_in[0];
    const float* wk = (const float*)d_in[1];
    const float* bk = (const float*)d_in[2];
    const float* g1 = (const float*)d_in[3];
    const float* b1 = (const float*)d_in[4];
    const float* m1 = (const float*)d_in[5];
    const float* v1 = (const float*)d_in[6];
    const float* wv = (const float*)d_in[7];
    const float* bv = (const float*)d_in[8];
    const float* wW = (const float*)d_in[9];
    const float* bW = (const float*)d_in[10];
    const float* wo = (const float*)d_in[11];
    const float* bo = (const float*)d_in[12];
    const float* g2 = (const float*)d_in[13];
    const float* b2 = (const float*)d_in[14];
    const float* m2 = (const float*)d_in[15];
    const float* v2 = (const float*)d_in[16];
    float* out = (float*)d_out;

    cudaFuncSetAttribute(gemm_tc,        cudaFuncAttributeMaxDynamicSharedMemorySize, DSMEM);
    cudaFuncSetAttribute(gemm_sym,       cudaFuncAttributeMaxDynamicSharedMemorySize, DSMEM);
    cudaFuncSetAttribute(gemm_ctx_fused, cudaFuncAttributeMaxDynamicSharedMemorySize, DSMEM_CTX);

    __half *xh,*xl,*kh,*kl,*vh,*vl,*aH,*aL,*ch,*cl,*c2h,*c2l;
    __half *wkh,*wkl,*wvh,*wvl,*wWh,*wWl,*woh,*wol;
    float *bkf,*bof; u32 *rmx;
    cudaGetSymbolAddress((void**)&xh, g_xh);   cudaGetSymbolAddress((void**)&xl, g_xl);
    cudaGetSymbolAddress((void**)&kh, g_kh);   cudaGetSymbolAddress((void**)&kl, g_kl);
    cudaGetSymbolAddress((void**)&vh, g_vh);   cudaGetSymbolAddress((void**)&vl, g_vl);
    cudaGetSymbolAddress((void**)&aH, g_ahh);  cudaGetSymbolAddress((void**)&aL, g_all);
    cudaGetSymbolAddress((void**)&ch, g_ch);   cudaGetSymbolAddress((void**)&cl, g_cl);
    cudaGetSymbolAddress((void**)&c2h, g_c2h); cudaGetSymbolAddress((void**)&c2l, g_c2l);
    cudaGetSymbolAddress((void**)&wkh, g_wkh); cudaGetSymbolAddress((void**)&wkl, g_wkl);
    cudaGetSymbolAddress((void**)&wvh, g_wvh); cudaGetSymbolAddress((void**)&wvl, g_wvl);
    cudaGetSymbolAddress((void**)&wWh, g_wWh); cudaGetSymbolAddress((void**)&wWl, g_wWl);
    cudaGetSymbolAddress((void**)&woh, g_woh); cudaGetSymbolAddress((void**)&wol, g_wol);
    cudaGetSymbolAddress((void**)&bkf, g_bkf); cudaGetSymbolAddress((void**)&bof, g_bof);
    cudaGetSymbolAddress((void**)&rmx, g_rmax);

    // launches 0-2
    prep_all<<<dim3(512,4), 256>>>(wk, bk, g1, b1, m1, v1, wv, wW, wo, bo, g2, b2, m2, v2,
                                   wkh, wkl, bkf, wvh, wvl, wWh, wWl, woh, wol, bof);
    conv_x<<<dim3(TN/32, 16, NB), dim3(32,8)>>>(x, xh, xl);
    init_rmax<<<(NB*TN + 255)/256, 256>>>(rmx);

    // 3: k_t[n][cout] = relu(Wk_f x + bk_f)
    gemm_tc<<<dim3(72,4,NB), 256, DSMEM>>>(xh, xl, (size_t)TN*512, 512,
        wkh, wkl, 0, 512, 512, F_BCOL|F_RELU, bkf, 1.f,
        kh, kl, nullptr, (size_t)TN*512, 512);
    // 4: val[v][n] = Wv x + bv
    gemm_tc<<<dim3(2,72,NB), 256, DSMEM>>>(wvh, wvl, 0, 512,
        xh, xl, (size_t)TN*512, 512, 512, F_BROW, bv, 1.f,
        vh, vl, nullptr, (size_t)256*TN, TN);
    // 5: sim (symmetric) — ncu -s 5 -c 1 lands here
    gemm_sym<<<dim3(2628,1,NB), 256, DSMEM>>>(kh, kl, 0.0441941738241592f, aH, aL, rmx);
    // 6: ctx with fused exp/rowsum/normalize (val lo dropped)
    gemm_ctx_fused<<<dim3(TN/64,1,NB), 256, DSMEM_CTX>>>(aH, aL, vh, rmx, ch, cl);
    // 7: ctx2[n][co] = wW ctx + bW
    gemm_tc<<<dim3(72,4,NB), 256, DSMEM>>>(ch, cl, (size_t)TN*256, 256,
        wWh, wWl, 0, 256, 256, F_BCOL, bW, 1.f,
        c2h, c2l, nullptr, (size_t)TN*512, 512);
    // 8: out[co][n] = relu(wo_f ctx2 + bo_f), fp32
    gemm_tc<<<dim3(4,72,NB), 256, DSMEM>>>(woh, wol, 0, 512,
        c2h, c2l, (size_t)TN*512, 512, 512, F_BROW|F_RELU|F_F32, bof, 1.f,
        nullptr, nullptr, out, (size_t)512*TN, TN);
}

// round 9
// speedup vs baseline: 4.6016x; 1.3002x over previous
#include <cuda_runtime.h>
#include <cuda_fp16.h>
#include <math.h>
#include <stdint.h>

#define TN 9216
#define NB 2
typedef unsigned int u32;
typedef unsigned long long u64;

#define F_RELU   1
#define F_BROW   2
#define F_BCOL   4
#define F_F32    16

// ---------------- scratch (static device arrays; no cudaMalloc allowed) ----
__device__ __half g_xh[(size_t)NB*TN*512],  g_xl[(size_t)NB*TN*512];
__device__ __half g_kh[(size_t)NB*TN*512],  g_kl[(size_t)NB*TN*512];
__device__ __half g_vh[(size_t)NB*256*TN],  g_vl[(size_t)NB*256*TN];
__device__ __half g_ahh[(size_t)NB*TN*TN],  g_all[(size_t)NB*TN*TN];
__device__ __half g_ch[(size_t)NB*TN*256],  g_cl[(size_t)NB*TN*256];
__device__ __half g_c2h[(size_t)NB*TN*512], g_c2l[(size_t)NB*TN*512];
__device__ __half g_wkh[512*512], g_wkl[512*512];
__device__ __half g_wvh[256*512], g_wvl[256*512];
__device__ __half g_wWh[512*256], g_wWl[512*256];
__device__ __half g_woh[512*512], g_wol[512*512];
__device__ float g_bkf[512], g_bof[512];
__device__ u32   g_rmax[NB*TN];

// ---------------- helpers ----------------------------------------------------
static __device__ __forceinline__ u32 smem_u32(const void* p){
    u32 a;
    asm("{ .reg .u64 t; cvta.to.shared.u64 t, %1; cvt.u32.u64 %0, t; }" : "=r"(a) : "l"(p));
    return a;
}
static __device__ __forceinline__ void cpasync16(u32 s, const void* g){
    asm volatile("cp.async.cg.shared.global [%0], [%1], 16;" :: "r"(s), "l"(g) : "memory");
}
#define CP_COMMIT() asm volatile("cp.async.commit_group;" ::: "memory")
#define CP_WAIT0()  asm volatile("cp.async.wait_group 0;" ::: "memory")
#define CP_WAIT1()  asm volatile("cp.async.wait_group 1;" ::: "memory")
#define CP_WAIT2()  asm volatile("cp.async.wait_group 2;" ::: "memory")

static __device__ __forceinline__ void ldsm4(u32& r0, u32& r1, u32& r2, u32& r3, u32 a){
    asm volatile("ldmatrix.sync.aligned.m8n8.x4.shared.b16 {%0,%1,%2,%3}, [%4];"
                 : "=r"(r0), "=r"(r1), "=r"(r2), "=r"(r3) : "r"(a));
}
static __device__ __forceinline__ void mma16816(float* d, const u32* a, const u32* b){
    asm volatile("mma.sync.aligned.m16n8k16.row.col.f32.f16.f16.f32 "
                 "{%0,%1,%2,%3}, {%4,%5,%6,%7}, {%8,%9}, {%0,%1,%2,%3};"
                 : "+f"(d[0]), "+f"(d[1]), "+f"(d[2]), "+f"(d[3])
                 : "r"(a[0]), "r"(a[1]), "r"(a[2]), "r"(a[3]), "r"(b[0]), "r"(b[1]));
}
static __device__ __forceinline__ void split2(float v, __half& h, __half& l){
    h = __float2half_rn(v);
    l = __float2half_rn(v - __half2float(h));
}
static __device__ __forceinline__ u32 fenc(float f){
    u32 u = __float_as_uint(f);
    return (u & 0x80000000u) ? ~u : (u | 0x80000000u);
}
static __device__ __forceinline__ float fdec(u32 u){
    return (u & 0x80000000u) ? __uint_as_float(u ^ 0x80000000u) : __uint_as_float(~u);
}

// ---------------- generic split-fp16 tensor GEMM (3-stage pipeline) ----------
__global__ void __launch_bounds__(256,1) gemm_tc(
    const __half* __restrict__ ah, const __half* __restrict__ al, size_t a_bs, int lda,
    const __half* __restrict__ bh, const __half* __restrict__ bl, size_t b_bs, int ldb,
    int K, int flags, const float* __restrict__ bias,
    float scale, __half* oh, __half* ol, float* of, size_t o_bs, int ldo)
{
    extern __shared__ char dsm[];
    const int tid = threadIdx.x, wid = tid>>5, lid = tid&31;
    const int m0 = blockIdx.x*128, n0 = blockIdx.y*128, z = blockIdx.z;
    ah += (size_t)z*a_bs; al += (size_t)z*a_bs;
    bh += (size_t)z*b_bs; bl += (size_t)z*b_bs;
    const int wm = wid>>2, wn = wid&3;
    const u32 sb = smem_u32(dsm);
    const int lrow = tid>>3, lc = tid&7;
    const __half* gpA[2] = {ah, al};
    const __half* gpB[2] = {bh, bl};

    float acc[4][4][4];
#pragma unroll
    for (int i=0;i<4;i++)
#pragma unroll
        for (int j=0;j<4;j++)
#pragma unroll
            for (int q=0;q<4;q++) acc[i][j][q] = 0.f;

    const int S = K >> 6;
    auto issue = [&](int s){
        const int k0 = s << 6;
        const u32 bufo = (u32)(s % 3) * 65536u;
#pragma unroll
        for (int arr=0; arr<4; arr++){
            const __half* gp = (arr<2) ? gpA[arr] : gpB[arr-2];
            const int rb = (arr<2) ? m0 : n0;
            const int ld = (arr<2) ? lda : ldb;
            const u32 so = sb + bufo + arr*16384u;
#pragma unroll
            for (int i=0;i<4;i++){
                const int row = lrow + i*32;
                const void* g = gp + (size_t)(rb+row)*ld + k0 + lc*8;
                const u32 sa = so + (u32)(row*128) + (u32)((lc ^ (row&7)) << 4);
                cpasync16(sa, g);
            }
        }
        CP_COMMIT();
    };

    issue(0);
    issue(1);
    for (int s=0; s<S; s++){
        if (s+1 < S) { CP_WAIT1(); } else { CP_WAIT0(); }
        __syncthreads();
        if (s+2 < S) issue(s+2);
        const u32 bufo = (u32)(s % 3) * 65536u;
        const u32 bAh = sb+bufo, bAl = sb+bufo+16384u, bBh = sb+bufo+32768u, bBl = sb+bufo+49152u;
        const int prA = (wm*64 + (lid&15)) * 128;
        const int prB0 = (wn*32 +      (lid&7) + ((lid>>4)<<3)) * 128;
        const int prB1 = (wn*32 + 16 + (lid&7) + ((lid>>4)<<3)) * 128;
#pragma unroll
        for (int st=0; st<4; st++){
            u32 Ah[4][4], Al[4][4], Bh[4][2], Bl[4][2];
            const int xa = ((st*2 + (lid>>4))    ^ (lid&7)) << 4;
            const int xb = ((st*2 + ((lid>>3)&1)) ^ (lid&7)) << 4;
#pragma unroll
            for (int i=0;i<4;i++){
                ldsm4(Ah[i][0],Ah[i][1],Ah[i][2],Ah[i][3], bAh + prA + i*2048 + xa);
                ldsm4(Al[i][0],Al[i][1],Al[i][2],Al[i][3], bAl + prA + i*2048 + xa);
            }
            {
                u32 r0,r1,r2,r3;
                ldsm4(r0,r1,r2,r3, bBh + prB0 + xb);
                Bh[0][0]=r0; Bh[0][1]=r1; Bh[1][0]=r2; Bh[1][1]=r3;
                ldsm4(r0,r1,r2,r3, bBh + prB1 + xb);
                Bh[2][0]=r0; Bh[2][1]=r1; Bh[3][0]=r2; Bh[3][1]=r3;
                ldsm4(r0,r1,r2,r3, bBl + prB0 + xb);
                Bl[0][0]=r0; Bl[0][1]=r1; Bl[1][0]=r2; Bl[1][1]=r3;
                ldsm4(r0,r1,r2,r3, bBl + prB1 + xb);
                Bl[2][0]=r0; Bl[2][1]=r1; Bl[3][0]=r2; Bl[3][1]=r3;
            }
#pragma unroll
            for (int i=0;i<4;i++)
#pragma unroll
                for (int j=0;j<4;j++) mma16816(acc[i][j], Ah[i], Bh[j]);
#pragma unroll
            for (int i=0;i<4;i++)
#pragma unroll
                for (int j=0;j<4;j++) mma16816(acc[i][j], Ah[i], Bl[j]);
#pragma unroll
            for (int i=0;i<4;i++)
#pragma unroll
                for (int j=0;j<4;j++) mma16816(acc[i][j], Al[i], Bh[j]);
        }
    }

    const int tr = lid>>2, tc = (lid&3)*2;
    const int mBase = m0 + wm*64, nBase = n0 + wn*32;
#pragma unroll
    for (int i=0;i<4;i++){
#pragma unroll
        for (int hh=0; hh<2; hh++){
            const int row = mBase + i*16 + tr + hh*8;
            float brow = (flags & F_BROW) ? bias[row] : 0.f;
            if (flags & F_F32){
                float* op = of + (size_t)z*o_bs + (size_t)row*ldo;
#pragma unroll
                for (int j=0;j<4;j++){
                    const int n = nBase + j*8 + tc;
                    float v0 = acc[i][j][hh*2+0]*scale + brow;
                    float v1 = acc[i][j][hh*2+1]*scale + brow;
                    if (flags & F_BCOL){ v0 += bias[n]; v1 += bias[n+1]; }
                    if (flags & F_RELU){ v0 = fmaxf(v0,0.f); v1 = fmaxf(v1,0.f); }
                    float2 w; w.x = v0; w.y = v1;
                    *(float2*)(op + n) = w;
                }
            } else {
                __half* oph = oh + (size_t)z*o_bs + (size_t)row*ldo;
                __half* opl = ol + (size_t)z*o_bs + (size_t)row*ldo;
#pragma unroll
                for (int j=0;j<4;j++){
                    const int n = nBase + j*8 + tc;
                    float v0 = acc[i][j][hh*2+0]*scale + brow;
                    float v1 = acc[i][j][hh*2+1]*scale + brow;
                    if (flags & F_BCOL){ v0 += bias[n]; v1 += bias[n+1]; }
                    if (flags & F_RELU){ v0 = fmaxf(v0,0.f); v1 = fmaxf(v1,0.f); }
                    __half2 h2, l2;
                    split2(v0, h2.x, l2.x); split2(v1, h2.y, l2.y);
                    *(__half2*)(oph + n) = h2;
                    *(__half2*)(opl + n) = l2;
                }
            }
        }
    }
}

// ---------------- symmetric sim GEMM: single fp16 pass, 4-stage --------------
// sim = scale * kh kh^T (kl dropped; ~4e-4 abs err in exp arg).
// Stage (32768 B): A 16K | B 16K. Output stays hi/lo fp16 + rowmax atomics.
#define SYM_STAGE 32768u
__global__ void __launch_bounds__(256,1) gemm_sym(
    const __half* __restrict__ kh,
    float scale, __half* __restrict__ aH, __half* __restrict__ aL,
    u32* __restrict__ rmaxU)
{
    extern __shared__ char dsm[];
    const int tid = threadIdx.x, wid = tid>>5, lid = tid&31;
    const int z = blockIdx.z;
    const int t = blockIdx.x;
    int i = (int)((145.0f - sqrtf(21025.0f - 8.0f*(float)t)) * 0.5f);
    while (i > 0 && i*72 - i*(i-1)/2 > t) i--;
    while ((i+1)*72 - (i+1)*i/2 <= t) i++;
    const int j = i + (t - (i*72 - i*(i-1)/2));
    const int m0 = i*128, n0 = j*128;

    const __half* ah = kh + (size_t)z*TN*512;
    const int wm = wid>>2, wn = wid&3;
    const u32 sb = smem_u32(dsm);
    const int lrow = tid>>3, lc = tid&7;

    float acc[4][4][4];
#pragma unroll
    for (int a=0;a<4;a++)
#pragma unroll
        for (int b=0;b<4;b++)
#pragma unroll
            for (int q=0;q<4;q++) acc[a][b][q] = 0.f;

    auto issue = [&](int s){
        const int k0 = s << 6;
        const u32 bufo = (u32)(s & 3) * SYM_STAGE;
#pragma unroll
        for (int arr=0; arr<2; arr++){
            const int rb = arr ? n0 : m0;
            const u32 so = sb + bufo + arr*16384u;
#pragma unroll
            for (int q=0;q<4;q++){
                const int row = lrow + q*32;
                const void* g = ah + (size_t)(rb+row)*512 + k0 + lc*8;
                const u32 sa = so + (u32)(row*128) + (u32)((lc ^ (row&7)) << 4);
                cpasync16(sa, g);
            }
        }
        CP_COMMIT();
    };

    issue(0); issue(1); issue(2);
    for (int s=0; s<8; s++){
        if (s+3 <= 8-1)      { CP_WAIT2(); }
        else if (s+2 <= 8-1) { CP_WAIT1(); }
        else                 { CP_WAIT0(); }
        __syncthreads();
        if (s+3 < 8) issue(s+3);
        const u32 bufo = (u32)(s & 3) * SYM_STAGE;
        const u32 bA = sb+bufo, bB = sb+bufo+16384u;
        const int prA = (wm*64 + (lid&15)) * 128;
        const int prB0 = (wn*32 +      (lid&7) + ((lid>>4)<<3)) * 128;
        const int prB1 = (wn*32 + 16 + (lid&7) + ((lid>>4)<<3)) * 128;
#pragma unroll
        for (int st=0; st<4; st++){
            u32 Ah[4][4], Bh[4][2];
            const int xa = ((st*2 + (lid>>4))    ^ (lid&7)) << 4;
            const int xb = ((st*2 + ((lid>>3)&1)) ^ (lid&7)) << 4;
#pragma unroll
            for (int a=0;a<4;a++)
                ldsm4(Ah[a][0],Ah[a][1],Ah[a][2],Ah[a][3], bA + prA + a*2048 + xa);
            {
                u32 r0,r1,r2,r3;
                ldsm4(r0,r1,r2,r3, bB + prB0 + xb);
                Bh[0][0]=r0; Bh[0][1]=r1; Bh[1][0]=r2; Bh[1][1]=r3;
                ldsm4(r0,r1,r2,r3, bB + prB1 + xb);
                Bh[2][0]=r0; Bh[2][1]=r1; Bh[3][0]=r2; Bh[3][1]=r3;
            }
#pragma unroll
            for (int a=0;a<4;a++)
#pragma unroll
                for (int b=0;b<4;b++) mma16816(acc[a][b], Ah[a], Bh[b]);
        }
    }

    __syncthreads();
    float* Sm = (float*)dsm;
    float* P  = Sm + 128*129;
    const int tr = lid>>2, tc = (lid&3)*2;
#pragma unroll
    for (int a=0;a<4;a++)
#pragma unroll
        for (int hh=0; hh<2; hh++){
            const int rl = wm*64 + a*16 + tr + hh*8;
#pragma unroll
            for (int b=0;b<4;b++){
                const int cl = wn*32 + b*8 + tc;
                Sm[rl*129 + cl]     = acc[a][b][hh*2+0]*scale;
                Sm[rl*129 + cl + 1] = acc[a][b][hh*2+1]*scale;
            }
        }
    __syncthreads();

    const int rr = tid & 127, hf2 = tid >> 7;
    {
        float m = -1e30f;
        for (int c=0;c<64;c++) m = fmaxf(m, Sm[rr*129 + hf2*64 + c]);
        P[rr*2 + hf2] = m;
    }
    __syncthreads();
    if (tid < 128) atomicMax(&rmaxU[(size_t)z*TN + m0 + tid], fenc(fmaxf(P[tid*2], P[tid*2+1])));
    __syncthreads();
    {
        float m = -1e30f;
        for (int r2=0;r2<64;r2++) m = fmaxf(m, Sm[(hf2*64 + r2)*129 + rr]);
        P[rr*2 + hf2] = m;
    }
    __syncthreads();
    if (tid < 128) atomicMax(&rmaxU[(size_t)z*TN + n0 + tid], fenc(fmaxf(P[tid*2], P[tid*2+1])));

    const size_t obase = (size_t)z*TN*TN;
    {
        const int r = tid>>1, c0 = (tid&1)*64;
        __half* oph = aH + obase + (size_t)(m0 + r)*TN + n0 + c0;
        __half* opl = aL + obase + (size_t)(m0 + r)*TN + n0 + c0;
        const float* Sr = Sm + r*129 + c0;
#pragma unroll
        for (int it=0; it<8; it++){
            __half2 hx[4], lx[4];
#pragma unroll
            for (int q=0;q<4;q++){
                split2(Sr[it*8 + 2*q],     hx[q].x, lx[q].x);
                split2(Sr[it*8 + 2*q + 1], hx[q].y, lx[q].y);
            }
            uint4 uh, ul;
            uh.x=*(u32*)&hx[0]; uh.y=*(u32*)&hx[1]; uh.z=*(u32*)&hx[2]; uh.w=*(u32*)&hx[3];
            ul.x=*(u32*)&lx[0]; ul.y=*(u32*)&lx[1]; ul.z=*(u32*)&lx[2]; ul.w=*(u32*)&lx[3];
            *(uint4*)(oph + it*8) = uh;
            *(uint4*)(opl + it*8) = ul;
        }
    }
    if (i != j){
        const int c = tid>>1, r0 = (tid&1)*64;
        __half* oph = aH + obase + (size_t)(n0 + c)*TN + m0 + r0;
        __half* opl = aL + obase + (size_t)(n0 + c)*TN + m0 + r0;
#pragma unroll
        for (int it=0; it<8; it++){
            __half2 hx[4], lx[4];
#pragma unroll
            for (int q=0;q<4;q++){
                float f0 = Sm[(r0 + it*8 + 2*q    )*129 + c];
                float f1 = Sm[(r0 + it*8 + 2*q + 1)*129 + c];
                split2(f0, hx[q].x, lx[q].x);
                split2(f1, hx[q].y, lx[q].y);
            }
            uint4 uh, ul;
            uh.x=*(u32*)&hx[0]; uh.y=*(u32*)&hx[1]; uh.z=*(u32*)&hx[2]; uh.w=*(u32*)&hx[3];
            ul.x=*(u32*)&lx[0]; ul.y=*(u32*)&lx[1]; ul.z=*(u32*)&lx[2]; ul.w=*(u32*)&lx[3];
            *(uint4*)(oph + it*8) = uh;
            *(uint4*)(opl + it*8) = ul;
        }
    }
}

// ---------------- fused exp/rowsum/normalize ctx GEMM (1-pass, 3-stage) ------
#define CTX_STAGE 40960u
__global__ void __launch_bounds__(256,1) gemm_ctx_fused(
    const __half* __restrict__ aH, const __half* __restrict__ aL,
    const __half* __restrict__ vh,
    const u32* __restrict__ rmaxU,
    __half* __restrict__ ch, __half* __restrict__ cl)
{
    extern __shared__ char dsm[];
    const int tid = threadIdx.x, wid = tid>>5, lid = tid&31;
    const int z = blockIdx.z;
    const int n0 = blockIdx.x*64;
    const size_t abase = (size_t)z*TN*TN;
    const __half* vhb = vh + (size_t)z*256*TN;
    const u32 sb = smem_u32(dsm);
    float* srow = (float*)(dsm + 3*CTX_STAGE);

    const int wm = wid>>2, wn = wid&3;
    const int lr = tid>>3, lc = tid&7;

    const float mx0 = fdec(rmaxU[(size_t)z*TN + n0 + lr]);
    const float mx1 = fdec(rmaxU[(size_t)z*TN + n0 + lr + 32]);
    const __half* pA0h = aH + abase + (size_t)(n0+lr)*TN + lc*8;
    const __half* pA0l = aL + abase + (size_t)(n0+lr)*TN + lc*8;
    const __half* pA1h = pA0h + (size_t)32*TN;
    const __half* pA1l = pA0l + (size_t)32*TN;

    float acc[2][8][4];
#pragma unroll
    for (int i=0;i<2;i++)
#pragma unroll
        for (int j=0;j<8;j++)
#pragma unroll
            for (int q=0;q<4;q++) acc[i][j][q] = 0.f;
    float s0 = 0.f, s1 = 0.f;

    const int S = TN/64;   // 144
    uint4 ra[4];
    auto ldgA = [&](int s){
        const int k0 = s<<6;
        ra[0] = *(const uint4*)(pA0h + k0);
        ra[1] = *(const uint4*)(pA0l + k0);
        ra[2] = *(const uint4*)(pA1h + k0);
        ra[3] = *(const uint4*)(pA1l + k0);
    };
    auto issueB = [&](int s){
        const int k0 = s<<6;
        const u32 so = sb + (u32)(s%3)*CTX_STAGE + 8192u;
#pragma unroll
        for (int i=0;i<8;i++){
            const int row = lr + i*32;
            cpasync16(so + (u32)(row*128) + (u32)((lc ^ (row&7)) << 4),
                      vhb + (size_t)row*TN + k0 + lc*8);
        }
        CP_COMMIT();
    };
    auto exp8h = [&](uint4 uh4, uint4 ul4, float mxv, float& ssum)->uint4{
        const __half2* hp = (const __half2*)&uh4;
        const __half2* lp = (const __half2*)&ul4;
        __half2 ho[4];
#pragma unroll
        for (int q=0;q<4;q++){
            float e0 = __expf(__half2float(hp[q].x)+__half2float(lp[q].x) - mxv);
            float e1 = __expf(__half2float(hp[q].y)+__half2float(lp[q].y) - mxv);
            ssum += e0 + e1;
            ho[q] = __floats2half2_rn(e0, e1);
        }
        return *(uint4*)ho;
    };
    const int aoff = lr*128 + ((lc ^ (lr&7)) << 4);

    ldgA(0);
    {
        uint4 h0 = exp8h(ra[0], ra[1], mx0, s0);
        uint4 h1 = exp8h(ra[2], ra[3], mx1, s1);
        *(uint4*)(dsm + aoff)        = h0;
        *(uint4*)(dsm + aoff + 4096) = h1;
    }
    issueB(0);
    issueB(1);

    for (int s=0; s<S; s++){
        if (s+1 < S) ldgA(s+1);
        if (s+1 < S) { CP_WAIT1(); } else { CP_WAIT0(); }
        __syncthreads();
        if (s+2 < S) issueB(s+2);

        const u32 bufo = (u32)(s%3)*CTX_STAGE;
        const u32 bA = sb + bufo, bB = sb + bufo + 8192u;
#pragma unroll
        for (int st=0; st<4; st++){
            u32 Ah[2][4], Bh[8][2];
            const int xa = ((st*2 + (lid>>4))    ^ (lid&7)) << 4;
            const int xb = ((st*2 + ((lid>>3)&1)) ^ (lid&7)) << 4;
#pragma unroll
            for (int i=0;i<2;i++){
                const u32 pr = (u32)((wm*32 + i*16 + (lid&15)) * 128);
                ldsm4(Ah[i][0],Ah[i][1],Ah[i][2],Ah[i][3], bA + pr + xa);
            }
#pragma unroll
            for (int j2=0; j2<4; j2++){
                const u32 pr = (u32)((wn*64 + j2*16 + (lid&7) + ((lid>>4)<<3)) * 128);
                u32 r0,r1,r2,r3;
                ldsm4(r0,r1,r2,r3, bB + pr + xb);
                Bh[2*j2][0]=r0; Bh[2*j2][1]=r1; Bh[2*j2+1][0]=r2; Bh[2*j2+1][1]=r3;
            }
#pragma unroll
            for (int i=0;i<2;i++)
#pragma unroll
                for (int j=0;j<8;j++) mma16816(acc[i][j], Ah[i], Bh[j]);
        }

        if (s+1 < S){
            const int off2 = (int)((u32)((s+1)%3)*CTX_STAGE) + aoff;
            uint4 h0 = exp8h(ra[0], ra[1], mx0, s0);
            uint4 h1 = exp8h(ra[2], ra[3], mx1, s1);
            *(uint4*)(dsm + off2)        = h0;
            *(uint4*)(dsm + off2 + 4096) = h1;
        }
    }

#pragma unroll
    for (int o=1;o<8;o<<=1){
        s0 += __shfl_xor_sync(0xffffffffu, s0, o);
        s1 += __shfl_xor_sync(0xffffffffu, s1, o);
    }
    __syncthreads();
    if ((tid&7)==0){ srow[lr] = s0; srow[lr+32] = s1; }
    __syncthreads();

    const int tr = lid>>2, tc2 = (lid&3)*2;
#pragma unroll
    for (int i=0;i<2;i++){
#pragma unroll
        for (int hh=0; hh<2; hh++){
            const int rowl = wm*32 + i*16 + tr + hh*8;
            const float inv = 1.0f / srow[rowl];
            const int row = n0 + rowl;
            __half* oph = ch + (size_t)z*TN*256 + (size_t)row*256 + wn*64;
            __half* opl = cl + (size_t)z*TN*256 + (size_t)row*256 + wn*64;
#pragma unroll
            for (int j=0;j<8;j++){
                const int col = j*8 + tc2;
                float v0 = acc[i][j][hh*2+0]*inv;
                float v1 = acc[i][j][hh*2+1]*inv;
                __half2 h2, l2;
                split2(v0, h2.x, l2.x); split2(v1, h2.y, l2.y);
                *(__half2*)(oph + col) = h2;
                *(__half2*)(opl + col) = l2;
            }
        }
    }
}

// ---------------- merged prep: all 4 weights in one launch -------------------
__global__ void prep_all(
    const float* __restrict__ wk, const float* __restrict__ bk,
    const float* __restrict__ g1, const float* __restrict__ b1,
    const float* __restrict__ m1, const float* __restrict__ v1,
    const float* __restrict__ wv,
    const float* __restrict__ wW,
    const float* __restrict__ wo, const float* __restrict__ bo,
    const float* __restrict__ g2, const float* __restrict__ b2,
    const float* __restrict__ m2, const float* __restrict__ v2,
    __half* __restrict__ wkh, __half* __restrict__ wkl, float* __restrict__ bkf,
    __half* __restrict__ wvh, __half* __restrict__ wvl,
    __half* __restrict__ wWh, __half* __restrict__ wWl,
    __half* __restrict__ woh, __half* __restrict__ wol, float* __restrict__ bof)
{
    const int o = blockIdx.x, which = blockIdx.y;
    if (which == 0){
        float s = g1[o] * rsqrtf(v1[o] + 1e-5f);
        for (int c = threadIdx.x; c < 512; c += blockDim.x){
            __half h, l; split2(wk[o*512 + c] * s, h, l);
            wkh[o*512 + c] = h; wkl[o*512 + c] = l;
        }
        if (threadIdx.x == 0) bkf[o] = bk[o]*s + b1[o] - m1[o]*s;
    } else if (which == 1){
        if (o < 256)
            for (int c = threadIdx.x; c < 512; c += blockDim.x){
                __half h, l; split2(wv[o*512 + c], h, l);
                wvh[o*512 + c] = h; wvl[o*512 + c] = l;
            }
    } else if (which == 2){
        for (int c = threadIdx.x; c < 256; c += blockDim.x){
            __half h, l; split2(wW[o*256 + c], h, l);
            wWh[o*256 + c] = h; wWl[o*256 + c] = l;
        }
    } else {
        float s = g2[o] * rsqrtf(v2[o] + 1e-5f);
        for (int c = threadIdx.x; c < 512; c += blockDim.x){
            __half h, l; split2(wo[o*512 + c] * s, h, l);
            woh[o*512 + c] = h; wol[o*512 + c] = l;
        }
        if (threadIdx.x == 0) bof[o] = bo[o]*s + b2[o] - m2[o]*s;
    }
}

__global__ void init_rmax(u32* r){
    int t = blockIdx.x*256 + threadIdx.x;
    if (t < NB*TN) r[t] = 0u;
}

__global__ void conv_x(const float* __restrict__ x, __half* __restrict__ xh, __half* __restrict__ xl)
{
    __shared__ float t[32][33];
    const int z = blockIdx.z;
    const float* xb = x + (size_t)z*512*TN;
    const int n0 = blockIdx.x*32, c0 = blockIdx.y*32;
    const int tx = threadIdx.x, ty = threadIdx.y;
#pragma unroll
    for (int i=0;i<4;i++)
        t[ty + i*8][tx] = xb[(size_t)(c0 + ty + i*8)*TN + n0 + tx];
    __syncthreads();
#pragma unroll
    for (int i=0;i<4;i++){
        int n = n0 + ty + i*8, c = c0 + tx;
        __half h, l; split2(t[tx][ty + i*8], h, l);
        size_t o = ((size_t)z*TN + n)*512 + c;
        xh[o] = h; xl[o] = l;
    }
}

// ---------------- launch ----------------------------------------------------
#define DSMEM     196608
#define DSMEM_SYM 131072
#define DSMEM_CTX (3*40960 + 256)

extern "C" void kernel_launch(void* const* d_in, const int* in_sizes, int n_in,
                              void* d_out, int out_size)
{
    const float* x  = (const float*)d_in[0];
    const float* wk = (const float*)d_in[1];
    const float* bk = (const float*)d_in[2];
    const float* g1 = (const float*)d_in[3];
    const float* b1 = (const float*)d_in[4];
    const float* m1 = (const float*)d_in[5];
    const float* v1 = (const float*)d_in[6];
    const float* wv = (const float*)d_in[7];
    const float* bv = (const float*)d_in[8];
    const float* wW = (const float*)d_in[9];
    const float* bW = (const float*)d_in[10];
    const float* wo = (const float*)d_in[11];
    const float* bo = (const float*)d_in[12];
    const float* g2 = (const float*)d_in[13];
    const float* b2 = (const float*)d_in[14];
    const float* m2 = (const float*)d_in[15];
    const float* v2 = (const float*)d_in[16];
    float* out = (float*)d_out;

    cudaFuncSetAttribute(gemm_tc,        cudaFuncAttributeMaxDynamicSharedMemorySize, DSMEM);
    cudaFuncSetAttribute(gemm_sym,       cudaFuncAttributeMaxDynamicSharedMemorySize, DSMEM_SYM);
    cudaFuncSetAttribute(gemm_ctx_fused, cudaFuncAttributeMaxDynamicSharedMemorySize, DSMEM_CTX);

    __half *xh,*xl,*kh,*kl,*vh,*vl,*aH,*aL,*ch,*cl,*c2h,*c2l;
    __half *wkh,*wkl,*wvh,*wvl,*wWh,*wWl,*woh,*wol;
    float *bkf,*bof; u32 *rmx;
    cudaGetSymbolAddress((void**)&xh, g_xh);   cudaGetSymbolAddress((void**)&xl, g_xl);
    cudaGetSymbolAddress((void**)&kh, g_kh);   cudaGetSymbolAddress((void**)&kl, g_kl);
    cudaGetSymbolAddress((void**)&vh, g_vh);   cudaGetSymbolAddress((void**)&vl, g_vl);
    cudaGetSymbolAddress((void**)&aH, g_ahh);  cudaGetSymbolAddress((void**)&aL, g_all);
    cudaGetSymbolAddress((void**)&ch, g_ch);   cudaGetSymbolAddress((void**)&cl, g_cl);
    cudaGetSymbolAddress((void**)&c2h, g_c2h); cudaGetSymbolAddress((void**)&c2l, g_c2l);
    cudaGetSymbolAddress((void**)&wkh, g_wkh); cudaGetSymbolAddress((void**)&wkl, g_wkl);
    cudaGetSymbolAddress((void**)&wvh, g_wvh); cudaGetSymbolAddress((void**)&wvl, g_wvl);
    cudaGetSymbolAddress((void**)&wWh, g_wWh); cudaGetSymbolAddress((void**)&wWl, g_wWl);
    cudaGetSymbolAddress((void**)&woh, g_woh); cudaGetSymbolAddress((void**)&wol, g_wol);
    cudaGetSymbolAddress((void**)&bkf, g_bkf); cudaGetSymbolAddress((void**)&bof, g_bof);
    cudaGetSymbolAddress((void**)&rmx, g_rmax);

    // launches 0-2
    prep_all<<<dim3(512,4), 256>>>(wk, bk, g1, b1, m1, v1, wv, wW, wo, bo, g2, b2, m2, v2,
                                   wkh, wkl, bkf, wvh, wvl, wWh, wWl, woh, wol, bof);
    conv_x<<<dim3(TN/32, 16, NB), dim3(32,8)>>>(x, xh, xl);
    init_rmax<<<(NB*TN + 255)/256, 256>>>(rmx);

    // 3: k_t[n][cout] = relu(Wk_f x + bk_f)  (kl written but unused)
    gemm_tc<<<dim3(72,4,NB), 256, DSMEM>>>(xh, xl, (size_t)TN*512, 512,
        wkh, wkl, 0, 512, 512, F_BCOL|F_RELU, bkf, 1.f,
        kh, kl, nullptr, (size_t)TN*512, 512);
    // 4: val[v][n] = Wv x + bv
    gemm_tc<<<dim3(2,72,NB), 256, DSMEM>>>(wvh, wvl, 0, 512,
        xh, xl, (size_t)TN*512, 512, 512, F_BROW, bv, 1.f,
        vh, vl, nullptr, (size_t)256*TN, TN);
    // 5: sim (symmetric, fp16 single pass) — ncu lands here
    gemm_sym<<<dim3(2628,1,NB), 256, DSMEM_SYM>>>(kh, 0.0441941738241592f, aH, aL, rmx);
    // 6: ctx with fused exp/rowsum/normalize (val lo dropped)
    gemm_ctx_fused<<<dim3(TN/64,1,NB), 256, DSMEM_CTX>>>(aH, aL, vh, rmx, ch, cl);
    // 7: ctx2[n][co] = wW ctx + bW
    gemm_tc<<<dim3(72,4,NB), 256, DSMEM>>>(ch, cl, (size_t)TN*256, 256,
        wWh, wWl, 0, 256, 256, F_BCOL, bW, 1.f,
        c2h, c2l, nullptr, (size_t)TN*512, 512);
    // 8: out[co][n] = relu(wo_f ctx2 + bo_f), fp32
    gemm_tc<<<dim3(4,72,NB), 256, DSMEM>>>(woh, wol, 0, 512,
        c2h, c2l, (size_t)TN*512, 512, 512, F_BROW|F_RELU|F_F32, bof, 1.f,
        nullptr, nullptr, out, (size_t)512*TN, TN);
}

// round 12
// speedup vs baseline: 5.9585x; 1.2949x over previous
#include <cuda_runtime.h>
#include <cuda_fp16.h>
#include <math.h>
#include <stdint.h>

#define TN 9216
#define NB 2
typedef unsigned int u32;
typedef unsigned long long u64;

#define F_RELU   1
#define F_BROW   2
#define F_BCOL   4
#define F_F32    16

// ---------------- scratch (static device arrays; no cudaMalloc allowed) ----
__device__ __half g_xh[(size_t)NB*TN*512];
__device__ __half g_kh[(size_t)NB*TN*512];
__device__ __half g_vh[(size_t)NB*256*TN];
__device__ float  g_att[(size_t)NB*TN*TN];      // 680 MB fp32 sim
__device__ __half g_ch[(size_t)NB*TN*256];
__device__ __half g_c2h[(size_t)NB*TN*512];
__device__ __half g_wkh[512*512];
__device__ __half g_wvh[256*512];
__device__ __half g_wWh[512*256];
__device__ __half g_woh[512*512];
__device__ float g_bkf[512], g_bof[512];
__device__ u32   g_rmax[NB*TN];

// ---------------- helpers ----------------------------------------------------
static __device__ __forceinline__ u32 smem_u32(const void* p){
    u32 a;
    asm("{ .reg .u64 t; cvta.to.shared.u64 t, %1; cvt.u32.u64 %0, t; }" : "=r"(a) : "l"(p));
    return a;
}
static __device__ __forceinline__ void cpasync16(u32 s, const void* g){
    asm volatile("cp.async.cg.shared.global [%0], [%1], 16;" :: "r"(s), "l"(g) : "memory");
}
#define CP_COMMIT() asm volatile("cp.async.commit_group;" ::: "memory")
#define CP_WAIT0()  asm volatile("cp.async.wait_group 0;" ::: "memory")
#define CP_WAIT1()  asm volatile("cp.async.wait_group 1;" ::: "memory")

static __device__ __forceinline__ void ldsm4(u32& r0, u32& r1, u32& r2, u32& r3, u32 a){
    asm volatile("ldmatrix.sync.aligned.m8n8.x4.shared.b16 {%0,%1,%2,%3}, [%4];"
                 : "=r"(r0), "=r"(r1), "=r"(r2), "=r"(r3) : "r"(a));
}
static __device__ __forceinline__ void mma16816(float* d, const u32* a, const u32* b){
    asm volatile("mma.sync.aligned.m16n8k16.row.col.f32.f16.f16.f32 "
                 "{%0,%1,%2,%3}, {%4,%5,%6,%7}, {%8,%9}, {%0,%1,%2,%3};"
                 : "+f"(d[0]), "+f"(d[1]), "+f"(d[2]), "+f"(d[3])
                 : "r"(a[0]), "r"(a[1]), "r"(a[2]), "r"(a[3]), "r"(b[0]), "r"(b[1]));
}
static __device__ __forceinline__ u32 fenc(float f){
    u32 u = __float_as_uint(f);
    return (u & 0x80000000u) ? ~u : (u | 0x80000000u);
}
static __device__ __forceinline__ float fdec(u32 u){
    return (u & 0x80000000u) ? __uint_as_float(u ^ 0x80000000u) : __uint_as_float(~u);
}

// ---------------- single-pass fp16 tensor GEMM (3-stage, 2 CTAs/SM) ----------
// D[m0..+128][n0..+128] = A[m][k]·B[n][k] + bias, epilogue flags.
// Stage 32768 B: A 16K | B 16K.
__global__ void __launch_bounds__(256,2) gemm_tc(
    const __half* __restrict__ a, size_t a_bs, int lda,
    const __half* __restrict__ b, size_t b_bs, int ldb,
    int K, int flags, const float* __restrict__ bias,
    __half* oh, float* of, size_t o_bs, int ldo)
{
    extern __shared__ char dsm[];
    const int tid = threadIdx.x, wid = tid>>5, lid = tid&31;
    const int m0 = blockIdx.x*128, n0 = blockIdx.y*128, z = blockIdx.z;
    a += (size_t)z*a_bs; b += (size_t)z*b_bs;
    const int wm = wid>>2, wn = wid&3;
    const u32 sb = smem_u32(dsm);
    const int lrow = tid>>3, lc = tid&7;

    float acc[4][4][4];
#pragma unroll
    for (int i=0;i<4;i++)
#pragma unroll
        for (int j=0;j<4;j++)
#pragma unroll
            for (int q=0;q<4;q++) acc[i][j][q] = 0.f;

    const int S = K >> 6;
    auto issue = [&](int s){
        const int k0 = s << 6;
        const u32 bufo = (u32)(s % 3) * 32768u;
#pragma unroll
        for (int arr=0; arr<2; arr++){
            const __half* gp = arr ? b : a;
            const int rb = arr ? n0 : m0;
            const int ld = arr ? ldb : lda;
            const u32 so = sb + bufo + arr*16384u;
#pragma unroll
            for (int i=0;i<4;i++){
                const int row = lrow + i*32;
                const void* g = gp + (size_t)(rb+row)*ld + k0 + lc*8;
                const u32 sa = so + (u32)(row*128) + (u32)((lc ^ (row&7)) << 4);
                cpasync16(sa, g);
            }
        }
        CP_COMMIT();
    };

    issue(0);
    issue(1);
    for (int s=0; s<S; s++){
        if (s+1 < S) { CP_WAIT1(); } else { CP_WAIT0(); }
        __syncthreads();
        if (s+2 < S) issue(s+2);
        const u32 bufo = (u32)(s % 3) * 32768u;
        const u32 bA = sb+bufo, bB = sb+bufo+16384u;
        const int prA = (wm*64 + (lid&15)) * 128;
        const int prB0 = (wn*32 +      (lid&7) + ((lid>>4)<<3)) * 128;
        const int prB1 = (wn*32 + 16 + (lid&7) + ((lid>>4)<<3)) * 128;
#pragma unroll
        for (int st=0; st<4; st++){
            u32 Ah[4][4], Bh[4][2];
            const int xa = ((st*2 + (lid>>4))    ^ (lid&7)) << 4;
            const int xb = ((st*2 + ((lid>>3)&1)) ^ (lid&7)) << 4;
#pragma unroll
            for (int i=0;i<4;i++)
                ldsm4(Ah[i][0],Ah[i][1],Ah[i][2],Ah[i][3], bA + prA + i*2048 + xa);
            {
                u32 r0,r1,r2,r3;
                ldsm4(r0,r1,r2,r3, bB + prB0 + xb);
                Bh[0][0]=r0; Bh[0][1]=r1; Bh[1][0]=r2; Bh[1][1]=r3;
                ldsm4(r0,r1,r2,r3, bB + prB1 + xb);
                Bh[2][0]=r0; Bh[2][1]=r1; Bh[3][0]=r2; Bh[3][1]=r3;
            }
#pragma unroll
            for (int i=0;i<4;i++)
#pragma unroll
                for (int j=0;j<4;j++) mma16816(acc[i][j], Ah[i], Bh[j]);
        }
    }

    const int tr = lid>>2, tc = (lid&3)*2;
    const int mBase = m0 + wm*64, nBase = n0 + wn*32;
#pragma unroll
    for (int i=0;i<4;i++){
#pragma unroll
        for (int hh=0; hh<2; hh++){
            const int row = mBase + i*16 + tr + hh*8;
            float brow = (flags & F_BROW) ? bias[row] : 0.f;
            if (flags & F_F32){
                float* op = of + (size_t)z*o_bs + (size_t)row*ldo;
#pragma unroll
                for (int j=0;j<4;j++){
                    const int n = nBase + j*8 + tc;
                    float v0 = acc[i][j][hh*2+0] + brow;
                    float v1 = acc[i][j][hh*2+1] + brow;
                    if (flags & F_BCOL){ v0 += bias[n]; v1 += bias[n+1]; }
                    if (flags & F_RELU){ v0 = fmaxf(v0,0.f); v1 = fmaxf(v1,0.f); }
                    float2 w; w.x = v0; w.y = v1;
                    *(float2*)(op + n) = w;
                }
            } else {
                __half* oph = oh + (size_t)z*o_bs + (size_t)row*ldo;
#pragma unroll
                for (int j=0;j<4;j++){
                    const int n = nBase + j*8 + tc;
                    float v0 = acc[i][j][hh*2+0] + brow;
                    float v1 = acc[i][j][hh*2+1] + brow;
                    if (flags & F_BCOL){ v0 += bias[n]; v1 += bias[n+1]; }
                    if (flags & F_RELU){ v0 = fmaxf(v0,0.f); v1 = fmaxf(v1,0.f); }
                    *(__half2*)(oph + n) = __floats2half2_rn(v0, v1);
                }
            }
        }
    }
}

// ---------------- symmetric sim GEMM: fp16 1-pass, fp32 out, 3-stage ---------
__global__ void __launch_bounds__(256,2) gemm_sym(
    const __half* __restrict__ kh,
    float scale, float* __restrict__ att, u32* __restrict__ rmaxU)
{
    extern __shared__ char dsm[];
    const int tid = threadIdx.x, wid = tid>>5, lid = tid&31;
    const int z = blockIdx.z;
    const int t = blockIdx.x;
    int i = (int)((145.0f - sqrtf(21025.0f - 8.0f*(float)t)) * 0.5f);
    while (i > 0 && i*72 - i*(i-1)/2 > t) i--;
    while ((i+1)*72 - (i+1)*i/2 <= t) i++;
    const int j = i + (t - (i*72 - i*(i-1)/2));
    const int m0 = i*128, n0 = j*128;

    const __half* ah = kh + (size_t)z*TN*512;
    const int wm = wid>>2, wn = wid&3;
    const u32 sb = smem_u32(dsm);
    const int lrow = tid>>3, lc = tid&7;

    float acc[4][4][4];
#pragma unroll
    for (int a=0;a<4;a++)
#pragma unroll
        for (int b=0;b<4;b++)
#pragma unroll
            for (int q=0;q<4;q++) acc[a][b][q] = 0.f;

    auto issue = [&](int s){
        const int k0 = s << 6;
        const u32 bufo = (u32)(s % 3) * 32768u;
#pragma unroll
        for (int arr=0; arr<2; arr++){
            const int rb = arr ? n0 : m0;
            const u32 so = sb + bufo + arr*16384u;
#pragma unroll
            for (int q=0;q<4;q++){
                const int row = lrow + q*32;
                const void* g = ah + (size_t)(rb+row)*512 + k0 + lc*8;
                const u32 sa = so + (u32)(row*128) + (u32)((lc ^ (row&7)) << 4);
                cpasync16(sa, g);
            }
        }
        CP_COMMIT();
    };

    issue(0); issue(1);
    for (int s=0; s<8; s++){
        if (s+1 < 8) { CP_WAIT1(); } else { CP_WAIT0(); }
        __syncthreads();
        if (s+2 < 8) issue(s+2);
        const u32 bufo = (u32)(s % 3) * 32768u;
        const u32 bA = sb+bufo, bB = sb+bufo+16384u;
        const int prA = (wm*64 + (lid&15)) * 128;
        const int prB0 = (wn*32 +      (lid&7) + ((lid>>4)<<3)) * 128;
        const int prB1 = (wn*32 + 16 + (lid&7) + ((lid>>4)<<3)) * 128;
#pragma unroll
        for (int st=0; st<4; st++){
            u32 Ah[4][4], Bh[4][2];
            const int xa = ((st*2 + (lid>>4))    ^ (lid&7)) << 4;
            const int xb = ((st*2 + ((lid>>3)&1)) ^ (lid&7)) << 4;
#pragma unroll
            for (int a=0;a<4;a++)
                ldsm4(Ah[a][0],Ah[a][1],Ah[a][2],Ah[a][3], bA + prA + a*2048 + xa);
            {
                u32 r0,r1,r2,r3;
                ldsm4(r0,r1,r2,r3, bB + prB0 + xb);
                Bh[0][0]=r0; Bh[0][1]=r1; Bh[1][0]=r2; Bh[1][1]=r3;
                ldsm4(r0,r1,r2,r3, bB + prB1 + xb);
                Bh[2][0]=r0; Bh[2][1]=r1; Bh[3][0]=r2; Bh[3][1]=r3;
            }
#pragma unroll
            for (int a=0;a<4;a++)
#pragma unroll
                for (int b=0;b<4;b++) mma16816(acc[a][b], Ah[a], Bh[b]);
        }
    }

    // stage scaled fp32 tile (stride 129 floats — scalar LDS only!)
    __syncthreads();
    float* Sm = (float*)dsm;
    float* P  = Sm + 128*129;
    const int tr = lid>>2, tc = (lid&3)*2;
#pragma unroll
    for (int a=0;a<4;a++)
#pragma unroll
        for (int hh=0; hh<2; hh++){
            const int rl = wm*64 + a*16 + tr + hh*8;
#pragma unroll
            for (int b=0;b<4;b++){
                const int cl = wn*32 + b*8 + tc;
                Sm[rl*129 + cl]     = acc[a][b][hh*2+0]*scale;
                Sm[rl*129 + cl + 1] = acc[a][b][hh*2+1]*scale;
            }
        }
    __syncthreads();

    const int rr = tid & 127, hf2 = tid >> 7;
    {
        float m = -1e30f;
        for (int c=0;c<64;c++) m = fmaxf(m, Sm[rr*129 + hf2*64 + c]);
        P[rr*2 + hf2] = m;
    }
    __syncthreads();
    if (tid < 128) atomicMax(&rmaxU[(size_t)z*TN + m0 + tid], fenc(fmaxf(P[tid*2], P[tid*2+1])));
    __syncthreads();
    {
        float m = -1e30f;
        for (int r2=0;r2<64;r2++) m = fmaxf(m, Sm[(hf2*64 + r2)*129 + rr]);
        P[rr*2 + hf2] = m;
    }
    __syncthreads();
    if (tid < 128) atomicMax(&rmaxU[(size_t)z*TN + n0 + tid], fenc(fmaxf(P[tid*2], P[tid*2+1])));

    const size_t obase = (size_t)z*TN*TN;
    // tile (m0,n0): scalar LDS (odd stride!) -> vector STG (aligned)
    {
        const int r = tid>>1, c0 = (tid&1)*64;
        float* op = att + obase + (size_t)(m0 + r)*TN + n0 + c0;
        const float* Sr = Sm + r*129 + c0;
#pragma unroll
        for (int it=0; it<16; it++){
            float4 w;
            w.x = Sr[it*4 + 0];
            w.y = Sr[it*4 + 1];
            w.z = Sr[it*4 + 2];
            w.w = Sr[it*4 + 3];
            *(float4*)(op + it*4) = w;
        }
    }
    // mirror (n0,m0) from transposed smem (scalar LDS)
    if (i != j){
        const int c = tid>>1, r0 = (tid&1)*64;
        float* op = att + obase + (size_t)(n0 + c)*TN + m0 + r0;
#pragma unroll
        for (int it=0; it<16; it++){
            float4 w;
            w.x = Sm[(r0 + it*4 + 0)*129 + c];
            w.y = Sm[(r0 + it*4 + 1)*129 + c];
            w.z = Sm[(r0 + it*4 + 2)*129 + c];
            w.w = Sm[(r0 + it*4 + 3)*129 + c];
            *(float4*)(op + it*4) = w;
        }
    }
}

// ---------------- fused exp/rowsum/normalize ctx GEMM (fp32 att in) ----------
#define CTX_STAGE 40960u
__global__ void __launch_bounds__(256,1) gemm_ctx_fused(
    const float* __restrict__ att,
    const __half* __restrict__ vh,
    const u32* __restrict__ rmaxU,
    __half* __restrict__ ch)
{
    extern __shared__ char dsm[];
    const int tid = threadIdx.x, wid = tid>>5, lid = tid&31;
    const int z = blockIdx.z;
    const int n0 = blockIdx.x*64;
    const size_t abase = (size_t)z*TN*TN;
    const __half* vhb = vh + (size_t)z*256*TN;
    const u32 sb = smem_u32(dsm);
    float* srow = (float*)(dsm + 3*CTX_STAGE);

    const int wm = wid>>2, wn = wid&3;
    const int lr = tid>>3, lc = tid&7;

    const float mx0 = fdec(rmaxU[(size_t)z*TN + n0 + lr]);
    const float mx1 = fdec(rmaxU[(size_t)z*TN + n0 + lr + 32]);
    const float* pA0 = att + abase + (size_t)(n0+lr)*TN + lc*8;
    const float* pA1 = pA0 + (size_t)32*TN;

    float acc[2][8][4];
#pragma unroll
    for (int i=0;i<2;i++)
#pragma unroll
        for (int j=0;j<8;j++)
#pragma unroll
            for (int q=0;q<4;q++) acc[i][j][q] = 0.f;
    float s0 = 0.f, s1 = 0.f;

    const int S = TN/64;   // 144
    __align__(16) float raf[16];
    auto ldgA = [&](int s){
        const int k0 = s<<6;
        *(uint4*)&raf[0]  = *(const uint4*)(pA0 + k0);
        *(uint4*)&raf[4]  = *(const uint4*)(pA0 + k0 + 4);
        *(uint4*)&raf[8]  = *(const uint4*)(pA1 + k0);
        *(uint4*)&raf[12] = *(const uint4*)(pA1 + k0 + 4);
    };
    auto issueB = [&](int s){
        const int k0 = s<<6;
        const u32 so = sb + (u32)(s%3)*CTX_STAGE + 8192u;
#pragma unroll
        for (int i=0;i<8;i++){
            const int row = lr + i*32;
            cpasync16(so + (u32)(row*128) + (u32)((lc ^ (row&7)) << 4),
                      vhb + (size_t)row*TN + k0 + lc*8);
        }
        CP_COMMIT();
    };
    auto exp8h = [&](const float* f, float mxv, float& ssum)->uint4{
        uint4 r;
        float e0, e1;
        e0 = __expf(f[0] - mxv); e1 = __expf(f[1] - mxv); ssum += e0 + e1;
        { __half2 h = __floats2half2_rn(e0, e1); r.x = *(u32*)&h; }
        e0 = __expf(f[2] - mxv); e1 = __expf(f[3] - mxv); ssum += e0 + e1;
        { __half2 h = __floats2half2_rn(e0, e1); r.y = *(u32*)&h; }
        e0 = __expf(f[4] - mxv); e1 = __expf(f[5] - mxv); ssum += e0 + e1;
        { __half2 h = __floats2half2_rn(e0, e1); r.z = *(u32*)&h; }
        e0 = __expf(f[6] - mxv); e1 = __expf(f[7] - mxv); ssum += e0 + e1;
        { __half2 h = __floats2half2_rn(e0, e1); r.w = *(u32*)&h; }
        return r;
    };
    const int aoff = lr*128 + ((lc ^ (lr&7)) << 4);

    ldgA(0);
    {
        uint4 h0 = exp8h(&raf[0], mx0, s0);
        uint4 h1 = exp8h(&raf[8], mx1, s1);
        *(uint4*)(dsm + aoff)        = h0;
        *(uint4*)(dsm + aoff + 4096) = h1;
    }
    issueB(0);
    issueB(1);

    for (int s=0; s<S; s++){
        if (s+1 < S) ldgA(s+1);
        if (s+1 < S) { CP_WAIT1(); } else { CP_WAIT0(); }
        __syncthreads();
        if (s+2 < S) issueB(s+2);

        const u32 bufo = (u32)(s%3)*CTX_STAGE;
        const u32 bA = sb + bufo, bB = sb + bufo + 8192u;
#pragma unroll
        for (int st=0; st<4; st++){
            u32 Ah[2][4], Bh[8][2];
            const int xa = ((st*2 + (lid>>4))    ^ (lid&7)) << 4;
            const int xb = ((st*2 + ((lid>>3)&1)) ^ (lid&7)) << 4;
#pragma unroll
            for (int i=0;i<2;i++){
                const u32 pr = (u32)((wm*32 + i*16 + (lid&15)) * 128);
                ldsm4(Ah[i][0],Ah[i][1],Ah[i][2],Ah[i][3], bA + pr + xa);
            }
#pragma unroll
            for (int j2=0; j2<4; j2++){
                const u32 pr = (u32)((wn*64 + j2*16 + (lid&7) + ((lid>>4)<<3)) * 128);
                u32 r0,r1,r2,r3;
                ldsm4(r0,r1,r2,r3, bB + pr + xb);
                Bh[2*j2][0]=r0; Bh[2*j2][1]=r1; Bh[2*j2+1][0]=r2; Bh[2*j2+1][1]=r3;
            }
#pragma unroll
            for (int i=0;i<2;i++)
#pragma unroll
                for (int j=0;j<8;j++) mma16816(acc[i][j], Ah[i], Bh[j]);
        }

        if (s+1 < S){
            const int off2 = (int)((u32)((s+1)%3)*CTX_STAGE) + aoff;
            uint4 h0 = exp8h(&raf[0], mx0, s0);
            uint4 h1 = exp8h(&raf[8], mx1, s1);
            *(uint4*)(dsm + off2)        = h0;
            *(uint4*)(dsm + off2 + 4096) = h1;
        }
    }

#pragma unroll
    for (int o=1;o<8;o<<=1){
        s0 += __shfl_xor_sync(0xffffffffu, s0, o);
        s1 += __shfl_xor_sync(0xffffffffu, s1, o);
    }
    __syncthreads();
    if ((tid&7)==0){ srow[lr] = s0; srow[lr+32] = s1; }
    __syncthreads();

    const int tr = lid>>2, tc2 = (lid&3)*2;
#pragma unroll
    for (int i=0;i<2;i++){
#pragma unroll
        for (int hh=0; hh<2; hh++){
            const int rowl = wm*32 + i*16 + tr + hh*8;
            const float inv = 1.0f / srow[rowl];
            const int row = n0 + rowl;
            __half* oph = ch + (size_t)z*TN*256 + (size_t)row*256 + wn*64;
#pragma unroll
            for (int j=0;j<8;j++){
                const int col = j*8 + tc2;
                *(__half2*)(oph + col) =
                    __floats2half2_rn(acc[i][j][hh*2+0]*inv, acc[i][j][hh*2+1]*inv);
            }
        }
    }
}

// ---------------- merged prep (single fp16 weights) --------------------------
__global__ void prep_all(
    const float* __restrict__ wk, const float* __restrict__ bk,
    const float* __restrict__ g1, const float* __restrict__ b1,
    const float* __restrict__ m1, const float* __restrict__ v1,
    const float* __restrict__ wv,
    const float* __restrict__ wW,
    const float* __restrict__ wo, const float* __restrict__ bo,
    const float* __restrict__ g2, const float* __restrict__ b2,
    const float* __restrict__ m2, const float* __restrict__ v2,
    __half* __restrict__ wkh, float* __restrict__ bkf,
    __half* __restrict__ wvh,
    __half* __restrict__ wWh,
    __half* __restrict__ woh, float* __restrict__ bof)
{
    const int o = blockIdx.x, which = blockIdx.y;
    if (which == 0){
        float s = g1[o] * rsqrtf(v1[o] + 1e-5f);
        for (int c = threadIdx.x; c < 512; c += blockDim.x)
            wkh[o*512 + c] = __float2half_rn(wk[o*512 + c] * s);
        if (threadIdx.x == 0) bkf[o] = bk[o]*s + b1[o] - m1[o]*s;
    } else if (which == 1){
        if (o < 256)
            for (int c = threadIdx.x; c < 512; c += blockDim.x)
                wvh[o*512 + c] = __float2half_rn(wv[o*512 + c]);
    } else if (which == 2){
        for (int c = threadIdx.x; c < 256; c += blockDim.x)
            wWh[o*256 + c] = __float2half_rn(wW[o*256 + c]);
    } else {
        float s = g2[o] * rsqrtf(v2[o] + 1e-5f);
        for (int c = threadIdx.x; c < 512; c += blockDim.x)
            woh[o*512 + c] = __float2half_rn(wo[o*512 + c] * s);
        if (threadIdx.x == 0) bof[o] = bo[o]*s + b2[o] - m2[o]*s;
    }
}

__global__ void init_rmax(u32* r){
    int t = blockIdx.x*256 + threadIdx.x;
    if (t < NB*TN) r[t] = 0u;
}

__global__ void conv_x(const float* __restrict__ x, __half* __restrict__ xh)
{
    __shared__ float t[32][33];
    const int z = blockIdx.z;
    const float* xb = x + (size_t)z*512*TN;
    const int n0 = blockIdx.x*32, c0 = blockIdx.y*32;
    const int tx = threadIdx.x, ty = threadIdx.y;
#pragma unroll
    for (int i=0;i<4;i++)
        t[ty + i*8][tx] = xb[(size_t)(c0 + ty + i*8)*TN + n0 + tx];
    __syncthreads();
#pragma unroll
    for (int i=0;i<4;i++){
        int n = n0 + ty + i*8, c = c0 + tx;
        xh[((size_t)z*TN + n)*512 + c] = __float2half_rn(t[tx][ty + i*8]);
    }
}

// ---------------- launch ----------------------------------------------------
#define DSMEM_TC  98304
#define DSMEM_SYM 98304
#define DSMEM_CTX (3*40960 + 256)

extern "C" void kernel_launch(void* const* d_in, const int* in_sizes, int n_in,
                              void* d_out, int out_size)
{
    const float* x  = (const float*)d_in[0];
    const float* wk = (const float*)d_in[1];
    const float* bk = (const float*)d_in[2];
    const float* g1 = (const float*)d_in[3];
    const float* b1 = (const float*)d_in[4];
    const float* m1 = (const float*)d_in[5];
    const float* v1 = (const float*)d_in[6];
    const float* wv = (const float*)d_in[7];
    const float* bv = (const float*)d_in[8];
    const float* wW = (const float*)d_in[9];
    const float* bW = (const float*)d_in[10];
    const float* wo = (const float*)d_in[11];
    const float* bo = (const float*)d_in[12];
    const float* g2 = (const float*)d_in[13];
    const float* b2 = (const float*)d_in[14];
    const float* m2 = (const float*)d_in[15];
    const float* v2 = (const float*)d_in[16];
    float* out = (float*)d_out;

    cudaFuncSetAttribute(gemm_tc,        cudaFuncAttributeMaxDynamicSharedMemorySize, DSMEM_TC);
    cudaFuncSetAttribute(gemm_sym,       cudaFuncAttributeMaxDynamicSharedMemorySize, DSMEM_SYM);
    cudaFuncSetAttribute(gemm_ctx_fused, cudaFuncAttributeMaxDynamicSharedMemorySize, DSMEM_CTX);

    __half *xh,*kh,*vh,*ch,*c2h,*wkh,*wvh,*wWh,*woh;
    float *att,*bkf,*bof; u32 *rmx;
    cudaGetSymbolAddress((void**)&xh, g_xh);
    cudaGetSymbolAddress((void**)&kh, g_kh);
    cudaGetSymbolAddress((void**)&vh, g_vh);
    cudaGetSymbolAddress((void**)&att, g_att);
    cudaGetSymbolAddress((void**)&ch, g_ch);
    cudaGetSymbolAddress((void**)&c2h, g_c2h);
    cudaGetSymbolAddress((void**)&wkh, g_wkh);
    cudaGetSymbolAddress((void**)&wvh, g_wvh);
    cudaGetSymbolAddress((void**)&wWh, g_wWh);
    cudaGetSymbolAddress((void**)&woh, g_woh);
    cudaGetSymbolAddress((void**)&bkf, g_bkf);
    cudaGetSymbolAddress((void**)&bof, g_bof);
    cudaGetSymbolAddress((void**)&rmx, g_rmax);

    // launches 0-2
    prep_all<<<dim3(512,4), 256>>>(wk, bk, g1, b1, m1, v1, wv, wW, wo, bo, g2, b2, m2, v2,
                                   wkh, bkf, wvh, wWh, woh, bof);
    conv_x<<<dim3(TN/32, 16, NB), dim3(32,8)>>>(x, xh);
    init_rmax<<<(NB*TN + 255)/256, 256>>>(rmx);

    // 3: k_t[n][cout] = relu(Wk_f x + bk_f)
    gemm_tc<<<dim3(72,4,NB), 256, DSMEM_TC>>>(xh, (size_t)TN*512, 512,
        wkh, 0, 512, 512, F_BCOL|F_RELU, bkf,
        kh, nullptr, (size_t)TN*512, 512);
    // 4: val[v][n] = Wv x + bv
    gemm_tc<<<dim3(2,72,NB), 256, DSMEM_TC>>>(wvh, 0, 512,
        xh, (size_t)TN*512, 512, 512, F_BROW, bv,
        vh, nullptr, (size_t)256*TN, TN);
    // 5: sim (symmetric, fp16 1-pass, fp32 out) — ncu lands here
    gemm_sym<<<dim3(2628,1,NB), 256, DSMEM_SYM>>>(kh, 0.0441941738241592f, att, rmx);
    // 6: ctx with fused exp/rowsum/normalize
    gemm_ctx_fused<<<dim3(TN/64,1,NB), 256, DSMEM_CTX>>>(att, vh, rmx, ch);
    // 7: ctx2[n][co] = wW ctx + bW
    gemm_tc<<<dim3(72,4,NB), 256, DSMEM_TC>>>(ch, (size_t)TN*256, 256,
        wWh, 0, 256, 256, F_BCOL, bW,
        c2h, nullptr, (size_t)TN*512, 512);
    // 8: out[co][n] = relu(wo_f ctx2 + bo_f), fp32
    gemm_tc<<<dim3(4,72,NB), 256, DSMEM_TC>>>(woh, 0, 512,
        c2h, (size_t)TN*512, 512, 512, F_BROW|F_RELU|F_F32, bof,
        nullptr, out, (size_t)512*TN, TN);
}